// round 1
// baseline (speedup 1.0000x reference)
#include <cuda_runtime.h>
#include <math.h>

// Problem constants
constexpr int Bc  = 2;
constexpr int Sc  = 4096;
constexpr int Dc  = 512;
constexpr int Hc  = 8;
constexpr int HDc = 64;
constexpr int FFc = 2048;
constexpr int BHc = Bc * Hc;        // 16
constexpr int Mc  = Bc * Sc;        // 8192 rows

// Scratch (device globals; no allocation allowed)
__device__ float g_Q  [BHc * Sc * HDc];   // [B,H,S,64]
__device__ float g_K  [BHc * Sc * HDc];   // [B,H,S,64]  (also V)
__device__ float g_ctx[Mc * Dc];          // [B,S,D] context after head merge
__device__ float g_rs [BHc * Sc];         // softmax row sums (unnormalized)
__device__ float g_y1 [Mc * Dc];          // x + ctx@Wfc^T
__device__ float g_att[Mc * Dc];          // att_result (LN1 out)
__device__ float g_z  [Mc * FFc];         // relu(att@Wff1^T)
__device__ float g_y2 [Mc * Dc];          // att + ff

// ---------------------------------------------------------------------------
// Generic NT GEMM: C[M,N] = A[M,K] @ W[N,K]^T  (both K-contiguous)
// 64x64 C-tile, BK=16, 256 threads, 4x4 register tile.
// EPI: 0 = permuted Q/K store ([B,H,S,64]), 1 = +residual, 2 = relu
// ---------------------------------------------------------------------------
template<int EPI>
__global__ __launch_bounds__(256)
void gemm_nt(const float* __restrict__ A, const float* __restrict__ W,
             const float* __restrict__ res, float* __restrict__ C,
             int M, int N, int K)
{
    __shared__ float As[16][64];
    __shared__ float Bs[16][64];

    const int tid = threadIdx.x;
    const int tx  = tid & 15;
    const int ty  = tid >> 4;
    const int m0  = blockIdx.y * 64;
    const int n0  = blockIdx.x * 64;

    const int lr = tid >> 2;     // 0..63 row within tile
    const int sg = tid & 3;      // 0..3 float4 segment within BK=16

    float acc[4][4] = {};

    for (int k0 = 0; k0 < K; k0 += 16) {
        float4 va = *(const float4*)(A + (size_t)(m0 + lr) * K + k0 + sg * 4);
        float4 vb = *(const float4*)(W + (size_t)(n0 + lr) * K + k0 + sg * 4);
        As[sg*4+0][lr] = va.x; As[sg*4+1][lr] = va.y;
        As[sg*4+2][lr] = va.z; As[sg*4+3][lr] = va.w;
        Bs[sg*4+0][lr] = vb.x; Bs[sg*4+1][lr] = vb.y;
        Bs[sg*4+2][lr] = vb.z; Bs[sg*4+3][lr] = vb.w;
        __syncthreads();

        #pragma unroll
        for (int k = 0; k < 16; ++k) {
            float4 a = *(const float4*)(&As[k][ty * 4]);
            float4 b = *(const float4*)(&Bs[k][tx * 4]);
            acc[0][0] += a.x*b.x; acc[0][1] += a.x*b.y; acc[0][2] += a.x*b.z; acc[0][3] += a.x*b.w;
            acc[1][0] += a.y*b.x; acc[1][1] += a.y*b.y; acc[1][2] += a.y*b.z; acc[1][3] += a.y*b.w;
            acc[2][0] += a.z*b.x; acc[2][1] += a.z*b.y; acc[2][2] += a.z*b.z; acc[2][3] += a.z*b.w;
            acc[3][0] += a.w*b.x; acc[3][1] += a.w*b.y; acc[3][2] += a.w*b.z; acc[3][3] += a.w*b.w;
        }
        __syncthreads();
    }

    #pragma unroll
    for (int i = 0; i < 4; ++i) {
        int m = m0 + ty * 4 + i;
        int n = n0 + tx * 4;
        float4 v = make_float4(acc[i][0], acc[i][1], acc[i][2], acc[i][3]);
        if (EPI == 0) {
            // permute: row m = b*S+s ; col n = h*64+d  ->  [((b*H+h)*S+s)*64 + d]
            int bb = m >> 12;           // /4096
            int ss = m & (Sc - 1);
            int hh = n >> 6;
            int dd = n & 63;
            size_t o = (((size_t)(bb * Hc + hh)) * Sc + ss) * HDc + dd;
            *(float4*)(C + o) = v;
        } else if (EPI == 1) {
            size_t o = (size_t)m * N + n;
            float4 r = *(const float4*)(res + o);
            v.x += r.x; v.y += r.y; v.z += r.z; v.w += r.w;
            *(float4*)(C + o) = v;
        } else { // relu
            size_t o = (size_t)m * N + n;
            v.x = fmaxf(v.x, 0.f); v.y = fmaxf(v.y, 0.f);
            v.z = fmaxf(v.z, 0.f); v.w = fmaxf(v.w, 0.f);
            *(float4*)(C + o) = v;
        }
    }
}

// ---------------------------------------------------------------------------
// Fused attention: per (b,h, 64-query tile)
//   S = (Q * 0.125) K^T ; P = exp(S)  (no max-shift: scores are O(1))
//   write unnormalized P to attn_out, accumulate rowsum and C = P V (V == K),
//   store context / rowsum. attn normalized by a separate pass.
// ---------------------------------------------------------------------------
constexpr int PADW = 68;                 // padded row stride (floats)
constexpr int ATTN_SMEM = 4 * 64 * PADW * (int)sizeof(float);   // 69632 B

__global__ __launch_bounds__(256)
void attn_kernel(float* __restrict__ attn_out)
{
    extern __shared__ float sm[];
    float* QT = sm;                  // QT[d][i]  (scaled)
    float* KT = sm + 1 * 64 * PADW;  // KT[d][j]
    float* KN = sm + 2 * 64 * PADW;  // KN[j][d]
    float* PS = sm + 3 * 64 * PADW;  // PS[j][i]
    __shared__ float rsum_sm[64];

    const int bh  = blockIdx.y;
    const int q0  = blockIdx.x * 64;
    const int tid = threadIdx.x;
    const int tx  = tid & 15;
    const int ty  = tid >> 4;

    const float* Qg = g_Q + (size_t)bh * Sc * HDc;
    const float* Kg = g_K + (size_t)bh * Sc * HDc;

    // load Q tile (64x64), transpose + pre-scale by 1/sqrt(64)
    for (int f = tid; f < 1024; f += 256) {
        int r = f >> 4, seg = f & 15;
        float4 v = *(const float4*)(Qg + (size_t)(q0 + r) * HDc + seg * 4);
        QT[(seg*4+0)*PADW + r] = v.x * 0.125f;
        QT[(seg*4+1)*PADW + r] = v.y * 0.125f;
        QT[(seg*4+2)*PADW + r] = v.z * 0.125f;
        QT[(seg*4+3)*PADW + r] = v.w * 0.125f;
    }

    float c_acc[4][4] = {};
    float rs[4] = {0.f, 0.f, 0.f, 0.f};

    for (int kt = 0; kt < Sc / 64; ++kt) {
        __syncthreads();   // covers initial Q load & prev-iter PV reads
        // load K tile into both layouts
        for (int f = tid; f < 1024; f += 256) {
            int r = f >> 4, seg = f & 15;
            float4 v = *(const float4*)(Kg + (size_t)(kt * 64 + r) * HDc + seg * 4);
            KT[(seg*4+0)*PADW + r] = v.x;
            KT[(seg*4+1)*PADW + r] = v.y;
            KT[(seg*4+2)*PADW + r] = v.z;
            KT[(seg*4+3)*PADW + r] = v.w;
            *(float4*)(KN + r * PADW + seg * 4) = v;
        }
        __syncthreads();

        // S = Q K^T (64x64x64)
        float s_acc[4][4] = {};
        #pragma unroll
        for (int d = 0; d < 64; ++d) {
            float4 a = *(const float4*)(QT + d * PADW + ty * 4);
            float4 b = *(const float4*)(KT + d * PADW + tx * 4);
            s_acc[0][0] += a.x*b.x; s_acc[0][1] += a.x*b.y; s_acc[0][2] += a.x*b.z; s_acc[0][3] += a.x*b.w;
            s_acc[1][0] += a.y*b.x; s_acc[1][1] += a.y*b.y; s_acc[1][2] += a.y*b.z; s_acc[1][3] += a.y*b.w;
            s_acc[2][0] += a.z*b.x; s_acc[2][1] += a.z*b.y; s_acc[2][2] += a.z*b.z; s_acc[2][3] += a.z*b.w;
            s_acc[3][0] += a.w*b.x; s_acc[3][1] += a.w*b.y; s_acc[3][2] += a.w*b.z; s_acc[3][3] += a.w*b.w;
        }

        // exp, accumulate rowsum, write unnormalized attn, transpose to PS
        #pragma unroll
        for (int i = 0; i < 4; ++i) {
            float4 p;
            p.x = __expf(s_acc[i][0]);
            p.y = __expf(s_acc[i][1]);
            p.z = __expf(s_acc[i][2]);
            p.w = __expf(s_acc[i][3]);
            rs[i] += (p.x + p.y) + (p.z + p.w);
            size_t row = (size_t)bh * Sc + q0 + ty * 4 + i;
            *(float4*)(attn_out + row * Sc + kt * 64 + tx * 4) = p;
            PS[(tx*4+0)*PADW + ty*4 + i] = p.x;
            PS[(tx*4+1)*PADW + ty*4 + i] = p.y;
            PS[(tx*4+2)*PADW + ty*4 + i] = p.z;
            PS[(tx*4+3)*PADW + ty*4 + i] = p.w;
        }
        __syncthreads();

        // C += P V (V = K tile, natural layout)
        #pragma unroll
        for (int j = 0; j < 64; ++j) {
            float4 a = *(const float4*)(PS + j * PADW + ty * 4);
            float4 b = *(const float4*)(KN + j * PADW + tx * 4);
            c_acc[0][0] += a.x*b.x; c_acc[0][1] += a.x*b.y; c_acc[0][2] += a.x*b.z; c_acc[0][3] += a.x*b.w;
            c_acc[1][0] += a.y*b.x; c_acc[1][1] += a.y*b.y; c_acc[1][2] += a.y*b.z; c_acc[1][3] += a.y*b.w;
            c_acc[2][0] += a.z*b.x; c_acc[2][1] += a.z*b.y; c_acc[2][2] += a.z*b.z; c_acc[2][3] += a.z*b.w;
            c_acc[3][0] += a.w*b.x; c_acc[3][1] += a.w*b.y; c_acc[3][2] += a.w*b.z; c_acc[3][3] += a.w*b.w;
        }
    }

    // reduce rowsums across the 16 tx lanes
    #pragma unroll
    for (int i = 0; i < 4; ++i) {
        float v = rs[i];
        v += __shfl_xor_sync(0xffffffffu, v, 8);
        v += __shfl_xor_sync(0xffffffffu, v, 4);
        v += __shfl_xor_sync(0xffffffffu, v, 2);
        v += __shfl_xor_sync(0xffffffffu, v, 1);
        if (tx == 0) rsum_sm[ty * 4 + i] = v;
    }
    __syncthreads();

    if (tid < 64) g_rs[(size_t)bh * Sc + q0 + tid] = rsum_sm[tid];

    const int bb = bh / Hc, hh = bh % Hc;
    #pragma unroll
    for (int i = 0; i < 4; ++i) {
        float inv = 1.0f / rsum_sm[ty * 4 + i];
        size_t o = ((size_t)bb * Sc + q0 + ty * 4 + i) * Dc + hh * HDc + tx * 4;
        float4 v = make_float4(c_acc[i][0]*inv, c_acc[i][1]*inv,
                               c_acc[i][2]*inv, c_acc[i][3]*inv);
        *(float4*)(g_ctx + o) = v;
    }
}

// normalize attn in place: attn[row][*] /= rowsum[row]
__global__ __launch_bounds__(256)
void norm_attn(float* __restrict__ attn)
{
    size_t i = (size_t)blockIdx.x * 256 + threadIdx.x;   // float4 index
    size_t row = (i * 4) >> 12;                          // / S
    float inv = 1.0f / g_rs[row];
    float4 v = ((const float4*)attn)[i];
    v.x *= inv; v.y *= inv; v.z *= inv; v.w *= inv;
    ((float4*)attn)[i] = v;
}

// LayerNorm over D=512: one block (128 threads) per row
__global__ __launch_bounds__(128)
void ln_kernel(const float* __restrict__ X, const float* __restrict__ gw,
               const float* __restrict__ bw, float* __restrict__ Y)
{
    const int row = blockIdx.x;
    const int tid = threadIdx.x;
    float4 v = ((const float4*)(X + (size_t)row * Dc))[tid];
    float s = (v.x + v.y) + (v.z + v.w);
    float q = (v.x*v.x + v.y*v.y) + (v.z*v.z + v.w*v.w);
    #pragma unroll
    for (int o = 16; o; o >>= 1) {
        s += __shfl_xor_sync(0xffffffffu, s, o);
        q += __shfl_xor_sync(0xffffffffu, q, o);
    }
    __shared__ float ss[4], sq[4];
    if ((tid & 31) == 0) { ss[tid >> 5] = s; sq[tid >> 5] = q; }
    __syncthreads();
    s = ss[0] + ss[1] + ss[2] + ss[3];
    q = sq[0] + sq[1] + sq[2] + sq[3];
    const float mu  = s * (1.0f / Dc);
    const float var = q * (1.0f / Dc) - mu * mu;
    const float inv = rsqrtf(var + 1e-5f);
    float4 g4 = ((const float4*)gw)[tid];
    float4 b4 = ((const float4*)bw)[tid];
    float4 o4;
    o4.x = (v.x - mu) * inv * g4.x + b4.x;
    o4.y = (v.y - mu) * inv * g4.y + b4.y;
    o4.z = (v.z - mu) * inv * g4.z + b4.z;
    o4.w = (v.w - mu) * inv * g4.w + b4.w;
    ((float4*)(Y + (size_t)row * Dc))[tid] = o4;
}

// ---------------------------------------------------------------------------
extern "C" void kernel_launch(void* const* d_in, const int* in_sizes, int n_in,
                              void* d_out, int out_size)
{
    const float* x    = (const float*)d_in[0];
    // d_in[1] = attn_mask (all-false, never applied in reference)
    const float* Wq   = (const float*)d_in[2];
    const float* Wk   = (const float*)d_in[3];
    // d_in[4] = Wv (unused: reference computes V with Wk)
    const float* Wfc  = (const float*)d_in[5];
    const float* Wff1 = (const float*)d_in[6];
    const float* Wff2 = (const float*)d_in[7];
    const float* g1   = (const float*)d_in[8];
    const float* b1   = (const float*)d_in[9];
    const float* g2   = (const float*)d_in[10];
    const float* b2   = (const float*)d_in[11];

    float* out_feed = (float*)d_out;                         // [B,S,D]
    float* out_attn = (float*)d_out + (size_t)Mc * Dc;       // [B,H,S,S]

    float *pQ, *pK, *pCtx, *pY1, *pAtt, *pZ, *pY2;
    cudaGetSymbolAddress((void**)&pQ,   g_Q);
    cudaGetSymbolAddress((void**)&pK,   g_K);
    cudaGetSymbolAddress((void**)&pCtx, g_ctx);
    cudaGetSymbolAddress((void**)&pY1,  g_y1);
    cudaGetSymbolAddress((void**)&pAtt, g_att);
    cudaGetSymbolAddress((void**)&pZ,   g_z);
    cudaGetSymbolAddress((void**)&pY2,  g_y2);

    cudaFuncSetAttribute(attn_kernel,
                         cudaFuncAttributeMaxDynamicSharedMemorySize, ATTN_SMEM);

    // 1. Q and K projections (K also serves as V — source bug preserved)
    gemm_nt<0><<<dim3(Dc/64, Mc/64), 256>>>(x, Wq, nullptr, pQ, Mc, Dc, Dc);
    gemm_nt<0><<<dim3(Dc/64, Mc/64), 256>>>(x, Wk, nullptr, pK, Mc, Dc, Dc);

    // 2. Fused attention (unnormalized attn + normalized context)
    attn_kernel<<<dim3(Sc/64, BHc), 256, ATTN_SMEM>>>(out_attn);

    // 3. Normalize attn output
    {
        size_t n4 = (size_t)BHc * Sc * Sc / 4;
        norm_attn<<<(unsigned)(n4 / 256), 256>>>(out_attn);
    }

    // 4. y1 = x + ctx @ Wfc^T ; att = LN(y1)
    gemm_nt<1><<<dim3(Dc/64, Mc/64), 256>>>(pCtx, Wfc, x, pY1, Mc, Dc, Dc);
    ln_kernel<<<Mc, 128>>>(pY1, g1, b1, pAtt);

    // 5. z = relu(att @ Wff1^T) ; y2 = att + z @ Wff2^T ; out = LN(y2)
    gemm_nt<2><<<dim3(FFc/64, Mc/64), 256>>>(pAtt, Wff1, nullptr, pZ, Mc, FFc, Dc);
    gemm_nt<1><<<dim3(Dc/64, Mc/64), 256>>>(pZ, Wff2, pAtt, pY2, Mc, Dc, FFc);
    ln_kernel<<<Mc, 128>>>(pY2, g2, b2, out_feed);
}

// round 3
// speedup vs baseline: 2.1582x; 2.1582x over previous
#include <cuda_runtime.h>
#include <cuda_bf16.h>
#include <math.h>
#include <stdint.h>

// Problem constants
constexpr int Bc  = 2;
constexpr int Sc  = 4096;
constexpr int Dc  = 512;
constexpr int Hc  = 8;
constexpr int HDc = 64;
constexpr int FFc = 2048;
constexpr int BHc = Bc * Hc;        // 16
constexpr int Mc  = Bc * Sc;        // 8192

// ---------------------------------------------------------------------------
// Scratch (device globals)
// ---------------------------------------------------------------------------
__device__ float g_rs [BHc * Sc];
__device__ float g_y1 [Mc * Dc];
__device__ float g_att[Mc * Dc];
__device__ float g_y2 [Mc * Dc];

__device__ __nv_bfloat16 g_xh [Mc * Dc],        g_xl [Mc * Dc];
__device__ __nv_bfloat16 g_qh [BHc * Sc * HDc], g_ql [BHc * Sc * HDc];
__device__ __nv_bfloat16 g_kh [BHc * Sc * HDc], g_kl [BHc * Sc * HDc];
__device__ __nv_bfloat16 g_ch [Mc * Dc],        g_cl [Mc * Dc];
__device__ __nv_bfloat16 g_ah [Mc * Dc],        g_al [Mc * Dc];
__device__ __nv_bfloat16 g_zh [Mc * FFc],       g_zl [Mc * FFc];
__device__ __nv_bfloat16 g_wqh[Dc * Dc],        g_wql[Dc * Dc];
__device__ __nv_bfloat16 g_wkh[Dc * Dc],        g_wkl[Dc * Dc];
__device__ __nv_bfloat16 g_wfh[Dc * Dc],        g_wfl[Dc * Dc];
__device__ __nv_bfloat16 g_w1h[FFc * Dc],       g_w1l[FFc * Dc];
__device__ __nv_bfloat16 g_w2h[Dc * FFc],       g_w2l[Dc * FFc];

// ---------------------------------------------------------------------------
// Helpers
// ---------------------------------------------------------------------------
__device__ __forceinline__ uint32_t smem_u32(const void* p) {
    uint32_t a;
    asm("{ .reg .u64 t; cvta.to.shared.u64 t, %1; cvt.u32.u64 %0, t; }"
        : "=r"(a) : "l"(p));
    return a;
}

__device__ __forceinline__ void ldsm_x4(uint32_t& r0, uint32_t& r1,
                                        uint32_t& r2, uint32_t& r3, uint32_t a) {
    asm volatile("ldmatrix.sync.aligned.m8n8.x4.shared.b16 {%0,%1,%2,%3}, [%4];"
                 : "=r"(r0), "=r"(r1), "=r"(r2), "=r"(r3) : "r"(a));
}
__device__ __forceinline__ void ldsm_x4_t(uint32_t& r0, uint32_t& r1,
                                          uint32_t& r2, uint32_t& r3, uint32_t a) {
    asm volatile("ldmatrix.sync.aligned.m8n8.x4.trans.shared.b16 {%0,%1,%2,%3}, [%4];"
                 : "=r"(r0), "=r"(r1), "=r"(r2), "=r"(r3) : "r"(a));
}

__device__ __forceinline__ void mma16816(float c[4],
        uint32_t a0, uint32_t a1, uint32_t a2, uint32_t a3,
        uint32_t b0, uint32_t b1) {
    asm volatile("mma.sync.aligned.m16n8k16.row.col.f32.bf16.bf16.f32 "
                 "{%0,%1,%2,%3}, {%4,%5,%6,%7}, {%8,%9}, {%0,%1,%2,%3};"
                 : "+f"(c[0]), "+f"(c[1]), "+f"(c[2]), "+f"(c[3])
                 : "r"(a0), "r"(a1), "r"(a2), "r"(a3), "r"(b0), "r"(b1));
}

__device__ __forceinline__ uint32_t pack_bf(__nv_bfloat16 a, __nv_bfloat16 b) {
    return ((uint32_t)__bfloat16_as_ushort(b) << 16) | (uint32_t)__bfloat16_as_ushort(a);
}
__device__ __forceinline__ void split_pair(float x, float y, uint32_t& h, uint32_t& l) {
    __nv_bfloat16 hx = __float2bfloat16(x), hy = __float2bfloat16(y);
    h = pack_bf(hx, hy);
    l = pack_bf(__float2bfloat16(x - __bfloat162float(hx)),
                __float2bfloat16(y - __bfloat162float(hy)));
}

// ---------------------------------------------------------------------------
// fp32 -> bf16 hi/lo split conversion
// ---------------------------------------------------------------------------
__global__ __launch_bounds__(256)
void cvt_hilo(const float4* __restrict__ in, uint2* __restrict__ hi,
              uint2* __restrict__ lo)
{
    size_t i = (size_t)blockIdx.x * 256 + threadIdx.x;
    float4 v = in[i];
    uint32_t h0, l0, h1, l1;
    split_pair(v.x, v.y, h0, l0);
    split_pair(v.z, v.w, h1, l1);
    hi[i] = make_uint2(h0, h1);
    lo[i] = make_uint2(l0, l1);
}

// ---------------------------------------------------------------------------
// HMMA GEMM (bf16x3): C[M,N] = A[M,K] @ W[N,K]^T
// CTA 128x128, BK=32, 256 thr, 8 warps (2M x 4N), warp tile 64x32.
// EPI 0: permuted bf16-split store ([B,H,S,64])  -> Ch, Cl
// EPI 1: fp32 + residual                         -> Cf
// EPI 2: relu + bf16-split store                 -> Ch, Cl
// ---------------------------------------------------------------------------
constexpr int GP = 80;                       // smem row stride (bytes), 32 bf16 + pad
constexpr int SM_A_H = 0, SM_A_L = 10240, SM_B_H = 20480, SM_B_L = 30720;

template<int EPI>
__global__ __launch_bounds__(256, 2)
void gemm_mma(const __nv_bfloat16* __restrict__ Ah, const __nv_bfloat16* __restrict__ Al,
              const __nv_bfloat16* __restrict__ Bh, const __nv_bfloat16* __restrict__ Bl,
              const float* __restrict__ res, float* __restrict__ Cf,
              __nv_bfloat16* __restrict__ Ch, __nv_bfloat16* __restrict__ Cl,
              int N, int K)
{
    __shared__ __align__(16) char sm[40960];
    const uint32_t sb = smem_u32(sm);
    const int tid = threadIdx.x, lane = tid & 31, wid = tid >> 5;
    const int wm = wid >> 2, wn = wid & 3;
    const int m0 = blockIdx.y * 128, n0 = blockIdx.x * 128;

    float acc[4][4][4];
    #pragma unroll
    for (int i = 0; i < 4; ++i)
        #pragma unroll
        for (int j = 0; j < 4; ++j)
            #pragma unroll
            for (int q = 0; q < 4; ++q) acc[i][j][q] = 0.f;

    for (int k0 = 0; k0 < K; k0 += 32) {
        #pragma unroll
        for (int i = 0; i < 2; ++i) {
            int seg = tid + i * 256, row = seg >> 2, part = seg & 3;
            size_t ga = (size_t)(m0 + row) * K + k0 + part * 8;
            size_t gb = (size_t)(n0 + row) * K + k0 + part * 8;
            int so = row * GP + part * 16;
            *(uint4*)(sm + SM_A_H + so) = *(const uint4*)(Ah + ga);
            *(uint4*)(sm + SM_A_L + so) = *(const uint4*)(Al + ga);
            *(uint4*)(sm + SM_B_H + so) = *(const uint4*)(Bh + gb);
            *(uint4*)(sm + SM_B_L + so) = *(const uint4*)(Bl + gb);
        }
        __syncthreads();

        #pragma unroll
        for (int ks = 0; ks < 2; ++ks) {
            uint32_t bhf[4][2], blf[4][2];
            #pragma unroll
            for (int nfp = 0; nfp < 2; ++nfp) {
                int ro = (wn * 32 + nfp * 16 + (lane & 15)) * GP + ks * 32 + (lane >> 4) * 16;
                uint32_t r0, r1, r2, r3;
                ldsm_x4(r0, r1, r2, r3, sb + SM_B_H + ro);
                bhf[nfp*2][0] = r0; bhf[nfp*2+1][0] = r1;
                bhf[nfp*2][1] = r2; bhf[nfp*2+1][1] = r3;
                ldsm_x4(r0, r1, r2, r3, sb + SM_B_L + ro);
                blf[nfp*2][0] = r0; blf[nfp*2+1][0] = r1;
                blf[nfp*2][1] = r2; blf[nfp*2+1][1] = r3;
            }
            #pragma unroll
            for (int mf = 0; mf < 4; ++mf) {
                int ro = (wm * 64 + mf * 16 + (lane & 15)) * GP + ks * 32 + (lane >> 4) * 16;
                uint32_t a0, a1, a2, a3, l0, l1, l2, l3;
                ldsm_x4(a0, a1, a2, a3, sb + SM_A_H + ro);
                ldsm_x4(l0, l1, l2, l3, sb + SM_A_L + ro);
                #pragma unroll
                for (int nf = 0; nf < 4; ++nf) {
                    mma16816(acc[mf][nf], a0, a1, a2, a3, bhf[nf][0], bhf[nf][1]);
                    mma16816(acc[mf][nf], a0, a1, a2, a3, blf[nf][0], blf[nf][1]);
                    mma16816(acc[mf][nf], l0, l1, l2, l3, bhf[nf][0], bhf[nf][1]);
                }
            }
        }
        __syncthreads();
    }

    // epilogue
    #pragma unroll
    for (int mf = 0; mf < 4; ++mf) {
        int r0 = m0 + wm * 64 + mf * 16 + (lane >> 2);
        #pragma unroll
        for (int nf = 0; nf < 4; ++nf) {
            int c = n0 + wn * 32 + nf * 8 + (lane & 3) * 2;
            float v0 = acc[mf][nf][0], v1 = acc[mf][nf][1];
            float v2 = acc[mf][nf][2], v3 = acc[mf][nf][3];
            if (EPI == 0) {
                int hh = c >> 6, d = c & 63;
                int b0 = r0 >> 12, s0 = r0 & 4095;
                size_t o = (((size_t)(b0 * Hc + hh)) * Sc + s0) * HDc + d;
                uint32_t ph, pl;
                split_pair(v0, v1, ph, pl);
                *(uint32_t*)(Ch + o) = ph; *(uint32_t*)(Cl + o) = pl;
                int r1 = r0 + 8;
                int b1 = r1 >> 12, s1 = r1 & 4095;
                o = (((size_t)(b1 * Hc + hh)) * Sc + s1) * HDc + d;
                split_pair(v2, v3, ph, pl);
                *(uint32_t*)(Ch + o) = ph; *(uint32_t*)(Cl + o) = pl;
            } else if (EPI == 1) {
                size_t o = (size_t)r0 * N + c;
                float2 rr = *(const float2*)(res + o);
                *(float2*)(Cf + o) = make_float2(v0 + rr.x, v1 + rr.y);
                o = (size_t)(r0 + 8) * N + c;
                rr = *(const float2*)(res + o);
                *(float2*)(Cf + o) = make_float2(v2 + rr.x, v3 + rr.y);
            } else {
                v0 = fmaxf(v0, 0.f); v1 = fmaxf(v1, 0.f);
                v2 = fmaxf(v2, 0.f); v3 = fmaxf(v3, 0.f);
                size_t o = (size_t)r0 * N + c;
                uint32_t ph, pl;
                split_pair(v0, v1, ph, pl);
                *(uint32_t*)(Ch + o) = ph; *(uint32_t*)(Cl + o) = pl;
                o = (size_t)(r0 + 8) * N + c;
                split_pair(v2, v3, ph, pl);
                *(uint32_t*)(Ch + o) = ph; *(uint32_t*)(Cl + o) = pl;
            }
        }
    }
}

// ---------------------------------------------------------------------------
// HMMA attention: per (bh, 128-query block). K-tiles of 64 keys.
// S = QK^T (bf16x3), P = exp(S/8) -> gmem (unnormalized) + smem bf16 split,
// ctx += P@V (bf16x3, V = K tile via ldmatrix.trans). Rowsums in regs,
// ctx normalized at end and stored pre-split to g_ch/g_cl.
// ---------------------------------------------------------------------------
constexpr int AP   = 144;   // smem row stride bytes (64 bf16 + pad)
constexpr int A_QH = 0,      A_QL = 18432, A_KH = 36864, A_KL = 46080;
constexpr int A_PH = 55296,  A_PL = 73728, A_RS = 92160;
constexpr int ATT_SMEM = A_RS + 512 + 16;

__global__ __launch_bounds__(256, 2)
void attn_mma(float* __restrict__ attn_out)
{
    extern __shared__ __align__(16) char sm[];
    float* rsum = (float*)(sm + A_RS);
    const uint32_t sb = smem_u32(sm);
    const int tid = threadIdx.x, lane = tid & 31, wid = tid >> 5;
    const int wm = wid >> 1, wn = wid & 1;       // 4 M-warps x 2 N-warps
    const int bh = blockIdx.y, q0 = blockIdx.x * 128;

    const __nv_bfloat16* Qh = g_qh + (size_t)bh * Sc * HDc;
    const __nv_bfloat16* Ql = g_ql + (size_t)bh * Sc * HDc;
    const __nv_bfloat16* Kh = g_kh + (size_t)bh * Sc * HDc;
    const __nv_bfloat16* Kl = g_kl + (size_t)bh * Sc * HDc;

    // Q tile 128x64 (hi/lo)
    #pragma unroll
    for (int i = 0; i < 4; ++i) {
        int seg = tid + i * 256, row = seg >> 3, part = seg & 7;
        size_t g = (size_t)(q0 + row) * HDc + part * 8;
        int so = row * AP + part * 16;
        *(uint4*)(sm + A_QH + so) = *(const uint4*)(Qh + g);
        *(uint4*)(sm + A_QL + so) = *(const uint4*)(Ql + g);
    }
    if (tid < 128) rsum[tid] = 0.f;

    float ctx[2][4][4];
    #pragma unroll
    for (int i = 0; i < 2; ++i)
        #pragma unroll
        for (int j = 0; j < 4; ++j)
            #pragma unroll
            for (int q = 0; q < 4; ++q) ctx[i][j][q] = 0.f;
    float rs[2][2] = {{0.f, 0.f}, {0.f, 0.f}};

    for (int kt = 0; kt < Sc / 64; ++kt) {
        __syncthreads();   // K/V + P smem safe to overwrite; covers Q load & rsum init
        #pragma unroll
        for (int i = 0; i < 2; ++i) {
            int seg = tid + i * 256, row = seg >> 3, part = seg & 7;
            size_t g = (size_t)(kt * 64 + row) * HDc + part * 8;
            int so = row * AP + part * 16;
            *(uint4*)(sm + A_KH + so) = *(const uint4*)(Kh + g);
            *(uint4*)(sm + A_KL + so) = *(const uint4*)(Kl + g);
        }
        __syncthreads();

        // ---- S = Q K^T ----
        float s[2][4][4];
        #pragma unroll
        for (int i = 0; i < 2; ++i)
            #pragma unroll
            for (int j = 0; j < 4; ++j)
                #pragma unroll
                for (int q = 0; q < 4; ++q) s[i][j][q] = 0.f;

        #pragma unroll
        for (int ks = 0; ks < 4; ++ks) {
            uint32_t bhf[4][2], blf[4][2];
            #pragma unroll
            for (int nfp = 0; nfp < 2; ++nfp) {
                int ro = (wn * 32 + nfp * 16 + (lane & 15)) * AP + ks * 32 + (lane >> 4) * 16;
                uint32_t r0, r1, r2, r3;
                ldsm_x4(r0, r1, r2, r3, sb + A_KH + ro);
                bhf[nfp*2][0] = r0; bhf[nfp*2+1][0] = r1;
                bhf[nfp*2][1] = r2; bhf[nfp*2+1][1] = r3;
                ldsm_x4(r0, r1, r2, r3, sb + A_KL + ro);
                blf[nfp*2][0] = r0; blf[nfp*2+1][0] = r1;
                blf[nfp*2][1] = r2; blf[nfp*2+1][1] = r3;
            }
            #pragma unroll
            for (int mf = 0; mf < 2; ++mf) {
                int ro = (wm * 32 + mf * 16 + (lane & 15)) * AP + ks * 32 + (lane >> 4) * 16;
                uint32_t a0, a1, a2, a3, l0, l1, l2, l3;
                ldsm_x4(a0, a1, a2, a3, sb + A_QH + ro);
                ldsm_x4(l0, l1, l2, l3, sb + A_QL + ro);
                #pragma unroll
                for (int nf = 0; nf < 4; ++nf) {
                    mma16816(s[mf][nf], a0, a1, a2, a3, bhf[nf][0], bhf[nf][1]);
                    mma16816(s[mf][nf], a0, a1, a2, a3, blf[nf][0], blf[nf][1]);
                    mma16816(s[mf][nf], l0, l1, l2, l3, bhf[nf][0], bhf[nf][1]);
                }
            }
        }

        // ---- exp, rowsum, P stores ----
        #pragma unroll
        for (int mf = 0; mf < 2; ++mf) {
            int rl = wm * 32 + mf * 16 + (lane >> 2);
            #pragma unroll
            for (int nf = 0; nf < 4; ++nf) {
                int cl_ = wn * 32 + nf * 8 + (lane & 3) * 2;
                float p0 = __expf(s[mf][nf][0] * 0.125f);
                float p1 = __expf(s[mf][nf][1] * 0.125f);
                float p2 = __expf(s[mf][nf][2] * 0.125f);
                float p3 = __expf(s[mf][nf][3] * 0.125f);
                rs[mf][0] += p0 + p1;
                rs[mf][1] += p2 + p3;
                size_t gr = ((size_t)bh * Sc + q0 + rl) * Sc + kt * 64 + cl_;
                *(float2*)(attn_out + gr) = make_float2(p0, p1);
                *(float2*)(attn_out + gr + (size_t)8 * Sc) = make_float2(p2, p3);
                uint32_t h0, l0p, h1, l1p;
                split_pair(p0, p1, h0, l0p);
                split_pair(p2, p3, h1, l1p);
                int so = rl * AP + cl_ * 2;
                *(uint32_t*)(sm + A_PH + so) = h0;
                *(uint32_t*)(sm + A_PL + so) = l0p;
                so += 8 * AP;
                *(uint32_t*)(sm + A_PH + so) = h1;
                *(uint32_t*)(sm + A_PL + so) = l1p;
            }
        }
        __syncthreads();

        // ---- ctx += P V  (V = K tile, via trans ldmatrix) ----
        #pragma unroll
        for (int ks = 0; ks < 4; ++ks) {
            uint32_t vh[4][2], vl[4][2];
            #pragma unroll
            for (int nfp = 0; nfp < 2; ++nfp) {
                int ro = (ks * 16 + (lane & 15)) * AP + wn * 64 + nfp * 32 + (lane >> 4) * 16;
                uint32_t r0, r1, r2, r3;
                ldsm_x4_t(r0, r1, r2, r3, sb + A_KH + ro);
                vh[nfp*2][0] = r0; vh[nfp*2][1] = r1;
                vh[nfp*2+1][0] = r2; vh[nfp*2+1][1] = r3;
                ldsm_x4_t(r0, r1, r2, r3, sb + A_KL + ro);
                vl[nfp*2][0] = r0; vl[nfp*2][1] = r1;
                vl[nfp*2+1][0] = r2; vl[nfp*2+1][1] = r3;
            }
            #pragma unroll
            for (int mf = 0; mf < 2; ++mf) {
                int ro = (wm * 32 + mf * 16 + (lane & 15)) * AP + ks * 32 + (lane >> 4) * 16;
                uint32_t p0, p1, p2, p3, q0r, q1r, q2r, q3r;
                ldsm_x4(p0, p1, p2, p3, sb + A_PH + ro);
                ldsm_x4(q0r, q1r, q2r, q3r, sb + A_PL + ro);
                #pragma unroll
                for (int nf = 0; nf < 4; ++nf) {
                    mma16816(ctx[mf][nf], p0, p1, p2, p3, vh[nf][0], vh[nf][1]);
                    mma16816(ctx[mf][nf], p0, p1, p2, p3, vl[nf][0], vl[nf][1]);
                    mma16816(ctx[mf][nf], q0r, q1r, q2r, q3r, vh[nf][0], vh[nf][1]);
                }
            }
        }
    }

    // ---- rowsum reduce ----
    #pragma unroll
    for (int mf = 0; mf < 2; ++mf)
        #pragma unroll
        for (int h = 0; h < 2; ++h) {
            float v = rs[mf][h];
            v += __shfl_xor_sync(0xffffffffu, v, 1);
            v += __shfl_xor_sync(0xffffffffu, v, 2);
            if ((lane & 3) == 0)
                atomicAdd(&rsum[wm * 32 + mf * 16 + h * 8 + (lane >> 2)], v);
        }
    __syncthreads();

    if (tid < 128) g_rs[(size_t)bh * Sc + q0 + tid] = rsum[tid];

    const int bb = bh >> 3, hh = bh & 7;
    #pragma unroll
    for (int mf = 0; mf < 2; ++mf) {
        int rl = wm * 32 + mf * 16 + (lane >> 2);
        float i0 = 1.f / rsum[rl];
        float i1 = 1.f / rsum[rl + 8];
        #pragma unroll
        for (int nf = 0; nf < 4; ++nf) {
            int d = wn * 32 + nf * 8 + (lane & 3) * 2;
            size_t o = ((size_t)bb * Sc + q0 + rl) * Dc + hh * HDc + d;
            uint32_t ph, pl;
            split_pair(ctx[mf][nf][0] * i0, ctx[mf][nf][1] * i0, ph, pl);
            *(uint32_t*)(g_ch + o) = ph; *(uint32_t*)(g_cl + o) = pl;
            o += (size_t)8 * Dc;
            split_pair(ctx[mf][nf][2] * i1, ctx[mf][nf][3] * i1, ph, pl);
            *(uint32_t*)(g_ch + o) = ph; *(uint32_t*)(g_cl + o) = pl;
        }
    }
}

// ---------------------------------------------------------------------------
// attn /= rowsum
// ---------------------------------------------------------------------------
__global__ __launch_bounds__(256)
void norm_attn(float* __restrict__ attn)
{
    size_t i = (size_t)blockIdx.x * 256 + threadIdx.x;
    size_t row = (i * 4) >> 12;
    float inv = 1.0f / g_rs[row];
    float4 v = ((const float4*)attn)[i];
    v.x *= inv; v.y *= inv; v.z *= inv; v.w *= inv;
    ((float4*)attn)[i] = v;
}

// ---------------------------------------------------------------------------
// LayerNorm; optionally also emits bf16 hi/lo split
// ---------------------------------------------------------------------------
template<bool SPLIT>
__global__ __launch_bounds__(128)
void ln_kernel(const float* __restrict__ X, const float* __restrict__ gw,
               const float* __restrict__ bw, float* __restrict__ Y,
               __nv_bfloat16* __restrict__ Yh, __nv_bfloat16* __restrict__ Yl)
{
    const int row = blockIdx.x;
    const int tid = threadIdx.x;
    float4 v = ((const float4*)(X + (size_t)row * Dc))[tid];
    float s = (v.x + v.y) + (v.z + v.w);
    float q = (v.x*v.x + v.y*v.y) + (v.z*v.z + v.w*v.w);
    #pragma unroll
    for (int o = 16; o; o >>= 1) {
        s += __shfl_xor_sync(0xffffffffu, s, o);
        q += __shfl_xor_sync(0xffffffffu, q, o);
    }
    __shared__ float ss[4], sq[4];
    if ((tid & 31) == 0) { ss[tid >> 5] = s; sq[tid >> 5] = q; }
    __syncthreads();
    s = ss[0] + ss[1] + ss[2] + ss[3];
    q = sq[0] + sq[1] + sq[2] + sq[3];
    const float mu  = s * (1.0f / Dc);
    const float var = q * (1.0f / Dc) - mu * mu;
    const float inv = rsqrtf(var + 1e-5f);
    float4 g4 = ((const float4*)gw)[tid];
    float4 b4 = ((const float4*)bw)[tid];
    float4 o4;
    o4.x = (v.x - mu) * inv * g4.x + b4.x;
    o4.y = (v.y - mu) * inv * g4.y + b4.y;
    o4.z = (v.z - mu) * inv * g4.z + b4.z;
    o4.w = (v.w - mu) * inv * g4.w + b4.w;
    ((float4*)(Y + (size_t)row * Dc))[tid] = o4;
    if (SPLIT) {
        size_t o = (size_t)row * Dc + tid * 4;
        uint32_t h0, l0, h1, l1;
        split_pair(o4.x, o4.y, h0, l0);
        split_pair(o4.z, o4.w, h1, l1);
        *(uint32_t*)(Yh + o)     = h0;  *(uint32_t*)(Yl + o)     = l0;
        *(uint32_t*)(Yh + o + 2) = h1;  *(uint32_t*)(Yl + o + 2) = l1;
    }
}

// ---------------------------------------------------------------------------
extern "C" void kernel_launch(void* const* d_in, const int* in_sizes, int n_in,
                              void* d_out, int out_size)
{
    const float* x    = (const float*)d_in[0];
    const float* Wq   = (const float*)d_in[2];
    const float* Wk   = (const float*)d_in[3];
    const float* Wfc  = (const float*)d_in[5];
    const float* Wff1 = (const float*)d_in[6];
    const float* Wff2 = (const float*)d_in[7];
    const float* g1   = (const float*)d_in[8];
    const float* b1   = (const float*)d_in[9];
    const float* g2   = (const float*)d_in[10];
    const float* b2   = (const float*)d_in[11];

    float* out_feed = (float*)d_out;
    float* out_attn = (float*)d_out + (size_t)Mc * Dc;

    float *pY1, *pAtt, *pY2;
    cudaGetSymbolAddress((void**)&pY1,  g_y1);
    cudaGetSymbolAddress((void**)&pAtt, g_att);
    cudaGetSymbolAddress((void**)&pY2,  g_y2);

    __nv_bfloat16 *xh,*xl,*qh,*ql,*kh,*kl,*ch,*cl,*ah,*al,*zh,*zl;
    __nv_bfloat16 *wqh,*wql,*wkh,*wkl,*wfh,*wfl,*w1h,*w1l,*w2h,*w2l;
    cudaGetSymbolAddress((void**)&xh,  g_xh);  cudaGetSymbolAddress((void**)&xl,  g_xl);
    cudaGetSymbolAddress((void**)&qh,  g_qh);  cudaGetSymbolAddress((void**)&ql,  g_ql);
    cudaGetSymbolAddress((void**)&kh,  g_kh);  cudaGetSymbolAddress((void**)&kl,  g_kl);
    cudaGetSymbolAddress((void**)&ch,  g_ch);  cudaGetSymbolAddress((void**)&cl,  g_cl);
    cudaGetSymbolAddress((void**)&ah,  g_ah);  cudaGetSymbolAddress((void**)&al,  g_al);
    cudaGetSymbolAddress((void**)&zh,  g_zh);  cudaGetSymbolAddress((void**)&zl,  g_zl);
    cudaGetSymbolAddress((void**)&wqh, g_wqh); cudaGetSymbolAddress((void**)&wql, g_wql);
    cudaGetSymbolAddress((void**)&wkh, g_wkh); cudaGetSymbolAddress((void**)&wkl, g_wkl);
    cudaGetSymbolAddress((void**)&wfh, g_wfh); cudaGetSymbolAddress((void**)&wfl, g_wfl);
    cudaGetSymbolAddress((void**)&w1h, g_w1h); cudaGetSymbolAddress((void**)&w1l, g_w1l);
    cudaGetSymbolAddress((void**)&w2h, g_w2h); cudaGetSymbolAddress((void**)&w2l, g_w2l);

    cudaFuncSetAttribute(attn_mma,
                         cudaFuncAttributeMaxDynamicSharedMemorySize, ATT_SMEM);

    auto cvt = [](const float* in, __nv_bfloat16* hi, __nv_bfloat16* lo, size_t n) {
        cvt_hilo<<<(unsigned)(n / 1024), 256>>>((const float4*)in, (uint2*)hi, (uint2*)lo);
    };

    // 0. splits of x + weights
    cvt(x,    xh,  xl,  (size_t)Mc * Dc);
    cvt(Wq,   wqh, wql, (size_t)Dc * Dc);
    cvt(Wk,   wkh, wkl, (size_t)Dc * Dc);
    cvt(Wfc,  wfh, wfl, (size_t)Dc * Dc);
    cvt(Wff1, w1h, w1l, (size_t)FFc * Dc);
    cvt(Wff2, w2h, w2l, (size_t)Dc * FFc);

    // 1. Q, K projections -> pre-split permuted bf16 (K doubles as V)
    gemm_mma<0><<<dim3(Dc/128, Mc/128), 256>>>(xh, xl, wqh, wql, nullptr, nullptr, qh, ql, Dc, Dc);
    gemm_mma<0><<<dim3(Dc/128, Mc/128), 256>>>(xh, xl, wkh, wkl, nullptr, nullptr, kh, kl, Dc, Dc);

    // 2. Attention (unnormalized attn out + ctx split) + attn normalization
    attn_mma<<<dim3(Sc/128, BHc), 256, ATT_SMEM>>>(out_attn);
    {
        size_t n4 = (size_t)BHc * Sc * Sc / 4;
        norm_attn<<<(unsigned)(n4 / 256), 256>>>(out_attn);
    }

    // 3. y1 = x + ctx@Wfc^T ; att = LN(y1) (+ split)
    gemm_mma<1><<<dim3(Dc/128, Mc/128), 256>>>(ch, cl, wfh, wfl, x, pY1, nullptr, nullptr, Dc, Dc);
    ln_kernel<true><<<Mc, 128>>>(pY1, g1, b1, pAtt, ah, al);

    // 4. z = relu(att@Wff1^T) (split) ; y2 = att + z@Wff2^T ; out = LN(y2)
    gemm_mma<2><<<dim3(FFc/128, Mc/128), 256>>>(ah, al, w1h, w1l, nullptr, nullptr, zh, zl, FFc, Dc);
    gemm_mma<1><<<dim3(Dc/128, Mc/128), 256>>>(zh, zl, w2h, w2l, pAtt, pY2, nullptr, nullptr, Dc, FFc);
    ln_kernel<false><<<Mc, 128>>>(pY2, g2, b2, out_feed, nullptr, nullptr);
}

// round 4
// speedup vs baseline: 2.3852x; 1.1052x over previous
#include <cuda_runtime.h>
#include <cuda_bf16.h>
#include <math.h>
#include <stdint.h>

// Problem constants
constexpr int Bc  = 2;
constexpr int Sc  = 4096;
constexpr int Dc  = 512;
constexpr int Hc  = 8;
constexpr int HDc = 64;
constexpr int FFc = 2048;
constexpr int BHc = Bc * Hc;        // 16
constexpr int Mc  = Bc * Sc;        // 8192

// ---------------------------------------------------------------------------
// Scratch (device globals)
// ---------------------------------------------------------------------------
__device__ float g_rs [BHc * Sc];
__device__ float g_y1 [Mc * Dc];
__device__ float g_att[Mc * Dc];
__device__ float g_y2 [Mc * Dc];

__device__ __nv_bfloat16 g_xh [Mc * Dc],        g_xl [Mc * Dc];
__device__ __nv_bfloat16 g_qh [BHc * Sc * HDc], g_ql [BHc * Sc * HDc];
__device__ __nv_bfloat16 g_kh [BHc * Sc * HDc], g_kl [BHc * Sc * HDc];
__device__ __nv_bfloat16 g_ch [Mc * Dc],        g_cl [Mc * Dc];
__device__ __nv_bfloat16 g_ah [Mc * Dc],        g_al [Mc * Dc];
__device__ __nv_bfloat16 g_zh [Mc * FFc],       g_zl [Mc * FFc];
__device__ __nv_bfloat16 g_wqh[Dc * Dc],        g_wql[Dc * Dc];
__device__ __nv_bfloat16 g_wkh[Dc * Dc],        g_wkl[Dc * Dc];
__device__ __nv_bfloat16 g_wfh[Dc * Dc],        g_wfl[Dc * Dc];
__device__ __nv_bfloat16 g_w1h[FFc * Dc],       g_w1l[FFc * Dc];
__device__ __nv_bfloat16 g_w2h[Dc * FFc],       g_w2l[Dc * FFc];

// ---------------------------------------------------------------------------
// Helpers
// ---------------------------------------------------------------------------
__device__ __forceinline__ uint32_t smem_u32(const void* p) {
    uint32_t a;
    asm("{ .reg .u64 t; cvta.to.shared.u64 t, %1; cvt.u32.u64 %0, t; }"
        : "=r"(a) : "l"(p));
    return a;
}

__device__ __forceinline__ void ldsm_x4(uint32_t& r0, uint32_t& r1,
                                        uint32_t& r2, uint32_t& r3, uint32_t a) {
    asm volatile("ldmatrix.sync.aligned.m8n8.x4.shared.b16 {%0,%1,%2,%3}, [%4];"
                 : "=r"(r0), "=r"(r1), "=r"(r2), "=r"(r3) : "r"(a));
}
__device__ __forceinline__ void ldsm_x4_t(uint32_t& r0, uint32_t& r1,
                                          uint32_t& r2, uint32_t& r3, uint32_t a) {
    asm volatile("ldmatrix.sync.aligned.m8n8.x4.trans.shared.b16 {%0,%1,%2,%3}, [%4];"
                 : "=r"(r0), "=r"(r1), "=r"(r2), "=r"(r3) : "r"(a));
}

__device__ __forceinline__ void mma16816(float c[4],
        uint32_t a0, uint32_t a1, uint32_t a2, uint32_t a3,
        uint32_t b0, uint32_t b1) {
    asm volatile("mma.sync.aligned.m16n8k16.row.col.f32.bf16.bf16.f32 "
                 "{%0,%1,%2,%3}, {%4,%5,%6,%7}, {%8,%9}, {%0,%1,%2,%3};"
                 : "+f"(c[0]), "+f"(c[1]), "+f"(c[2]), "+f"(c[3])
                 : "r"(a0), "r"(a1), "r"(a2), "r"(a3), "r"(b0), "r"(b1));
}

__device__ __forceinline__ uint32_t pack_bf(__nv_bfloat16 a, __nv_bfloat16 b) {
    return ((uint32_t)__bfloat16_as_ushort(b) << 16) | (uint32_t)__bfloat16_as_ushort(a);
}
__device__ __forceinline__ void split_pair(float x, float y, uint32_t& h, uint32_t& l) {
    __nv_bfloat16 hx = __float2bfloat16(x), hy = __float2bfloat16(y);
    h = pack_bf(hx, hy);
    l = pack_bf(__float2bfloat16(x - __bfloat162float(hx)),
                __float2bfloat16(y - __bfloat162float(hy)));
}

// ---------------------------------------------------------------------------
// fp32 -> bf16 hi/lo split conversion
// ---------------------------------------------------------------------------
__global__ __launch_bounds__(256)
void cvt_hilo(const float4* __restrict__ in, uint2* __restrict__ hi,
              uint2* __restrict__ lo)
{
    size_t i = (size_t)blockIdx.x * 256 + threadIdx.x;
    float4 v = in[i];
    uint32_t h0, l0, h1, l1;
    split_pair(v.x, v.y, h0, l0);
    split_pair(v.z, v.w, h1, l1);
    hi[i] = make_uint2(h0, h1);
    lo[i] = make_uint2(l0, l1);
}

// ---------------------------------------------------------------------------
// HMMA GEMM (bf16x3): C[M,N] = A[M,K] @ W[N,K]^T
// CTA 128x128, BK=32, 256 thr, 8 warps (2M x 4N), warp tile 64x32.
// EPI 0: permuted bf16-split store ([B,H,S,64])  -> Ch, Cl
// EPI 1: fp32 + residual                         -> Cf
// EPI 2: relu + bf16-split store                 -> Ch, Cl
// ---------------------------------------------------------------------------
constexpr int GP = 80;                       // smem row stride (bytes)
constexpr int SM_A_H = 0, SM_A_L = 10240, SM_B_H = 20480, SM_B_L = 30720;

template<int EPI>
__global__ __launch_bounds__(256, 2)
void gemm_mma(const __nv_bfloat16* __restrict__ Ah, const __nv_bfloat16* __restrict__ Al,
              const __nv_bfloat16* __restrict__ Bh, const __nv_bfloat16* __restrict__ Bl,
              const float* __restrict__ res, float* __restrict__ Cf,
              __nv_bfloat16* __restrict__ Ch, __nv_bfloat16* __restrict__ Cl,
              int N, int K)
{
    __shared__ __align__(16) char sm[40960];
    const uint32_t sb = smem_u32(sm);
    const int tid = threadIdx.x, lane = tid & 31, wid = tid >> 5;
    const int wm = wid >> 2, wn = wid & 3;
    const int m0 = blockIdx.y * 128, n0 = blockIdx.x * 128;

    float acc[4][4][4];
    #pragma unroll
    for (int i = 0; i < 4; ++i)
        #pragma unroll
        for (int j = 0; j < 4; ++j)
            #pragma unroll
            for (int q = 0; q < 4; ++q) acc[i][j][q] = 0.f;

    for (int k0 = 0; k0 < K; k0 += 32) {
        #pragma unroll
        for (int i = 0; i < 2; ++i) {
            int seg = tid + i * 256, row = seg >> 2, part = seg & 3;
            size_t ga = (size_t)(m0 + row) * K + k0 + part * 8;
            size_t gb = (size_t)(n0 + row) * K + k0 + part * 8;
            int so = row * GP + part * 16;
            *(uint4*)(sm + SM_A_H + so) = *(const uint4*)(Ah + ga);
            *(uint4*)(sm + SM_A_L + so) = *(const uint4*)(Al + ga);
            *(uint4*)(sm + SM_B_H + so) = *(const uint4*)(Bh + gb);
            *(uint4*)(sm + SM_B_L + so) = *(const uint4*)(Bl + gb);
        }
        __syncthreads();

        #pragma unroll
        for (int ks = 0; ks < 2; ++ks) {
            uint32_t bhf[4][2], blf[4][2];
            #pragma unroll
            for (int nfp = 0; nfp < 2; ++nfp) {
                int ro = (wn * 32 + nfp * 16 + (lane & 15)) * GP + ks * 32 + (lane >> 4) * 16;
                uint32_t r0, r1, r2, r3;
                ldsm_x4(r0, r1, r2, r3, sb + SM_B_H + ro);
                bhf[nfp*2][0] = r0; bhf[nfp*2+1][0] = r1;
                bhf[nfp*2][1] = r2; bhf[nfp*2+1][1] = r3;
                ldsm_x4(r0, r1, r2, r3, sb + SM_B_L + ro);
                blf[nfp*2][0] = r0; blf[nfp*2+1][0] = r1;
                blf[nfp*2][1] = r2; blf[nfp*2+1][1] = r3;
            }
            #pragma unroll
            for (int mf = 0; mf < 4; ++mf) {
                int ro = (wm * 64 + mf * 16 + (lane & 15)) * GP + ks * 32 + (lane >> 4) * 16;
                uint32_t a0, a1, a2, a3, l0, l1, l2, l3;
                ldsm_x4(a0, a1, a2, a3, sb + SM_A_H + ro);
                ldsm_x4(l0, l1, l2, l3, sb + SM_A_L + ro);
                #pragma unroll
                for (int nf = 0; nf < 4; ++nf) {
                    mma16816(acc[mf][nf], a0, a1, a2, a3, bhf[nf][0], bhf[nf][1]);
                    mma16816(acc[mf][nf], a0, a1, a2, a3, blf[nf][0], blf[nf][1]);
                    mma16816(acc[mf][nf], l0, l1, l2, l3, bhf[nf][0], bhf[nf][1]);
                }
            }
        }
        __syncthreads();
    }

    // epilogue
    #pragma unroll
    for (int mf = 0; mf < 4; ++mf) {
        int r0 = m0 + wm * 64 + mf * 16 + (lane >> 2);
        #pragma unroll
        for (int nf = 0; nf < 4; ++nf) {
            int c = n0 + wn * 32 + nf * 8 + (lane & 3) * 2;
            float v0 = acc[mf][nf][0], v1 = acc[mf][nf][1];
            float v2 = acc[mf][nf][2], v3 = acc[mf][nf][3];
            if (EPI == 0) {
                int hh = c >> 6, d = c & 63;
                int b0 = r0 >> 12, s0 = r0 & 4095;
                size_t o = (((size_t)(b0 * Hc + hh)) * Sc + s0) * HDc + d;
                uint32_t ph, pl;
                split_pair(v0, v1, ph, pl);
                *(uint32_t*)(Ch + o) = ph; *(uint32_t*)(Cl + o) = pl;
                int r1 = r0 + 8;
                int b1 = r1 >> 12, s1 = r1 & 4095;
                o = (((size_t)(b1 * Hc + hh)) * Sc + s1) * HDc + d;
                split_pair(v2, v3, ph, pl);
                *(uint32_t*)(Ch + o) = ph; *(uint32_t*)(Cl + o) = pl;
            } else if (EPI == 1) {
                size_t o = (size_t)r0 * N + c;
                float2 rr = *(const float2*)(res + o);
                *(float2*)(Cf + o) = make_float2(v0 + rr.x, v1 + rr.y);
                o = (size_t)(r0 + 8) * N + c;
                rr = *(const float2*)(res + o);
                *(float2*)(Cf + o) = make_float2(v2 + rr.x, v3 + rr.y);
            } else {
                v0 = fmaxf(v0, 0.f); v1 = fmaxf(v1, 0.f);
                v2 = fmaxf(v2, 0.f); v3 = fmaxf(v3, 0.f);
                size_t o = (size_t)r0 * N + c;
                uint32_t ph, pl;
                split_pair(v0, v1, ph, pl);
                *(uint32_t*)(Ch + o) = ph; *(uint32_t*)(Cl + o) = pl;
                o = (size_t)(r0 + 8) * N + c;
                split_pair(v2, v3, ph, pl);
                *(uint32_t*)(Ch + o) = ph; *(uint32_t*)(Cl + o) = pl;
            }
        }
    }
}

// ---------------------------------------------------------------------------
// HMMA attention: per (bh, 128-query block). K-tiles of 64 keys.
// S = QK^T (bf16x3 — feeds element-compared attn output), P = exp(S/8)
// -> gmem fp32 (unnormalized) + smem bf16 (hi only),
// ctx += P@V  (single MMA: bf16 errors average out over 4096-key sum).
// ---------------------------------------------------------------------------
constexpr int AP   = 144;   // smem row stride bytes (64 bf16 + pad)
constexpr int A_QH = 0,      A_QL = 18432, A_KH = 36864, A_KL = 46080;
constexpr int A_PH = 55296,  A_RS = 73728;
constexpr int ATT_SMEM = A_RS + 512 + 16;

__global__ __launch_bounds__(256, 2)
void attn_mma(float* __restrict__ attn_out)
{
    extern __shared__ __align__(16) char sm[];
    float* rsum = (float*)(sm + A_RS);
    const uint32_t sb = smem_u32(sm);
    const int tid = threadIdx.x, lane = tid & 31, wid = tid >> 5;
    const int wm = wid >> 1, wn = wid & 1;       // 4 M-warps x 2 N-warps
    const int bh = blockIdx.y, q0 = blockIdx.x * 128;

    const __nv_bfloat16* Qh = g_qh + (size_t)bh * Sc * HDc;
    const __nv_bfloat16* Ql = g_ql + (size_t)bh * Sc * HDc;
    const __nv_bfloat16* Kh = g_kh + (size_t)bh * Sc * HDc;
    const __nv_bfloat16* Kl = g_kl + (size_t)bh * Sc * HDc;

    // Q tile 128x64 (hi/lo)
    #pragma unroll
    for (int i = 0; i < 4; ++i) {
        int seg = tid + i * 256, row = seg >> 3, part = seg & 7;
        size_t g = (size_t)(q0 + row) * HDc + part * 8;
        int so = row * AP + part * 16;
        *(uint4*)(sm + A_QH + so) = *(const uint4*)(Qh + g);
        *(uint4*)(sm + A_QL + so) = *(const uint4*)(Ql + g);
    }
    if (tid < 128) rsum[tid] = 0.f;

    float ctx[2][4][4];
    #pragma unroll
    for (int i = 0; i < 2; ++i)
        #pragma unroll
        for (int j = 0; j < 4; ++j)
            #pragma unroll
            for (int q = 0; q < 4; ++q) ctx[i][j][q] = 0.f;
    float rs[2][2] = {{0.f, 0.f}, {0.f, 0.f}};

    for (int kt = 0; kt < Sc / 64; ++kt) {
        __syncthreads();
        #pragma unroll
        for (int i = 0; i < 2; ++i) {
            int seg = tid + i * 256, row = seg >> 3, part = seg & 7;
            size_t g = (size_t)(kt * 64 + row) * HDc + part * 8;
            int so = row * AP + part * 16;
            *(uint4*)(sm + A_KH + so) = *(const uint4*)(Kh + g);
            *(uint4*)(sm + A_KL + so) = *(const uint4*)(Kl + g);
        }
        __syncthreads();

        // ---- S = Q K^T (bf16x3) ----
        float s[2][4][4];
        #pragma unroll
        for (int i = 0; i < 2; ++i)
            #pragma unroll
            for (int j = 0; j < 4; ++j)
                #pragma unroll
                for (int q = 0; q < 4; ++q) s[i][j][q] = 0.f;

        #pragma unroll
        for (int ks = 0; ks < 4; ++ks) {
            uint32_t bhf[4][2], blf[4][2];
            #pragma unroll
            for (int nfp = 0; nfp < 2; ++nfp) {
                int ro = (wn * 32 + nfp * 16 + (lane & 15)) * AP + ks * 32 + (lane >> 4) * 16;
                uint32_t r0, r1, r2, r3;
                ldsm_x4(r0, r1, r2, r3, sb + A_KH + ro);
                bhf[nfp*2][0] = r0; bhf[nfp*2+1][0] = r1;
                bhf[nfp*2][1] = r2; bhf[nfp*2+1][1] = r3;
                ldsm_x4(r0, r1, r2, r3, sb + A_KL + ro);
                blf[nfp*2][0] = r0; blf[nfp*2+1][0] = r1;
                blf[nfp*2][1] = r2; blf[nfp*2+1][1] = r3;
            }
            #pragma unroll
            for (int mf = 0; mf < 2; ++mf) {
                int ro = (wm * 32 + mf * 16 + (lane & 15)) * AP + ks * 32 + (lane >> 4) * 16;
                uint32_t a0, a1, a2, a3, l0, l1, l2, l3;
                ldsm_x4(a0, a1, a2, a3, sb + A_QH + ro);
                ldsm_x4(l0, l1, l2, l3, sb + A_QL + ro);
                #pragma unroll
                for (int nf = 0; nf < 4; ++nf) {
                    mma16816(s[mf][nf], a0, a1, a2, a3, bhf[nf][0], bhf[nf][1]);
                    mma16816(s[mf][nf], a0, a1, a2, a3, blf[nf][0], blf[nf][1]);
                    mma16816(s[mf][nf], l0, l1, l2, l3, bhf[nf][0], bhf[nf][1]);
                }
            }
        }

        // ---- exp, rowsum, P stores (fp32 gmem + bf16-hi smem) ----
        #pragma unroll
        for (int mf = 0; mf < 2; ++mf) {
            int rl = wm * 32 + mf * 16 + (lane >> 2);
            #pragma unroll
            for (int nf = 0; nf < 4; ++nf) {
                int cl_ = wn * 32 + nf * 8 + (lane & 3) * 2;
                float p0 = __expf(s[mf][nf][0] * 0.125f);
                float p1 = __expf(s[mf][nf][1] * 0.125f);
                float p2 = __expf(s[mf][nf][2] * 0.125f);
                float p3 = __expf(s[mf][nf][3] * 0.125f);
                rs[mf][0] += p0 + p1;
                rs[mf][1] += p2 + p3;
                size_t gr = ((size_t)bh * Sc + q0 + rl) * Sc + kt * 64 + cl_;
                *(float2*)(attn_out + gr) = make_float2(p0, p1);
                *(float2*)(attn_out + gr + (size_t)8 * Sc) = make_float2(p2, p3);
                int so = rl * AP + cl_ * 2;
                *(uint32_t*)(sm + A_PH + so) =
                    pack_bf(__float2bfloat16(p0), __float2bfloat16(p1));
                *(uint32_t*)(sm + A_PH + so + 8 * AP) =
                    pack_bf(__float2bfloat16(p2), __float2bfloat16(p3));
            }
        }
        __syncthreads();

        // ---- ctx += P V  (single MMA; V = K-hi tile via trans ldmatrix) ----
        #pragma unroll
        for (int ks = 0; ks < 4; ++ks) {
            uint32_t vh[4][2];
            #pragma unroll
            for (int nfp = 0; nfp < 2; ++nfp) {
                int ro = (ks * 16 + (lane & 15)) * AP + wn * 64 + nfp * 32 + (lane >> 4) * 16;
                uint32_t r0, r1, r2, r3;
                ldsm_x4_t(r0, r1, r2, r3, sb + A_KH + ro);
                vh[nfp*2][0] = r0; vh[nfp*2][1] = r1;
                vh[nfp*2+1][0] = r2; vh[nfp*2+1][1] = r3;
            }
            #pragma unroll
            for (int mf = 0; mf < 2; ++mf) {
                int ro = (wm * 32 + mf * 16 + (lane & 15)) * AP + ks * 32 + (lane >> 4) * 16;
                uint32_t p0, p1, p2, p3;
                ldsm_x4(p0, p1, p2, p3, sb + A_PH + ro);
                #pragma unroll
                for (int nf = 0; nf < 4; ++nf)
                    mma16816(ctx[mf][nf], p0, p1, p2, p3, vh[nf][0], vh[nf][1]);
            }
        }
    }

    // ---- rowsum reduce ----
    #pragma unroll
    for (int mf = 0; mf < 2; ++mf)
        #pragma unroll
        for (int h = 0; h < 2; ++h) {
            float v = rs[mf][h];
            v += __shfl_xor_sync(0xffffffffu, v, 1);
            v += __shfl_xor_sync(0xffffffffu, v, 2);
            if ((lane & 3) == 0)
                atomicAdd(&rsum[wm * 32 + mf * 16 + h * 8 + (lane >> 2)], v);
        }
    __syncthreads();

    if (tid < 128) g_rs[(size_t)bh * Sc + q0 + tid] = rsum[tid];

    const int bb = bh >> 3, hh = bh & 7;
    #pragma unroll
    for (int mf = 0; mf < 2; ++mf) {
        int rl = wm * 32 + mf * 16 + (lane >> 2);
        float i0 = 1.f / rsum[rl];
        float i1 = 1.f / rsum[rl + 8];
        #pragma unroll
        for (int nf = 0; nf < 4; ++nf) {
            int d = wn * 32 + nf * 8 + (lane & 3) * 2;
            size_t o = ((size_t)bb * Sc + q0 + rl) * Dc + hh * HDc + d;
            uint32_t ph, pl;
            split_pair(ctx[mf][nf][0] * i0, ctx[mf][nf][1] * i0, ph, pl);
            *(uint32_t*)(g_ch + o) = ph; *(uint32_t*)(g_cl + o) = pl;
            o += (size_t)8 * Dc;
            split_pair(ctx[mf][nf][2] * i1, ctx[mf][nf][3] * i1, ph, pl);
            *(uint32_t*)(g_ch + o) = ph; *(uint32_t*)(g_cl + o) = pl;
        }
    }
}

// ---------------------------------------------------------------------------
// attn /= rowsum
// ---------------------------------------------------------------------------
__global__ __launch_bounds__(256)
void norm_attn(float* __restrict__ attn)
{
    size_t i = (size_t)blockIdx.x * 256 + threadIdx.x;
    size_t row = (i * 4) >> 12;
    float inv = 1.0f / g_rs[row];
    float4 v = ((const float4*)attn)[i];
    v.x *= inv; v.y *= inv; v.z *= inv; v.w *= inv;
    ((float4*)attn)[i] = v;
}

// ---------------------------------------------------------------------------
// LayerNorm; optionally also emits bf16 hi/lo split
// ---------------------------------------------------------------------------
template<bool SPLIT>
__global__ __launch_bounds__(128)
void ln_kernel(const float* __restrict__ X, const float* __restrict__ gw,
               const float* __restrict__ bw, float* __restrict__ Y,
               __nv_bfloat16* __restrict__ Yh, __nv_bfloat16* __restrict__ Yl)
{
    const int row = blockIdx.x;
    const int tid = threadIdx.x;
    float4 v = ((const float4*)(X + (size_t)row * Dc))[tid];
    float s = (v.x + v.y) + (v.z + v.w);
    float q = (v.x*v.x + v.y*v.y) + (v.z*v.z + v.w*v.w);
    #pragma unroll
    for (int o = 16; o; o >>= 1) {
        s += __shfl_xor_sync(0xffffffffu, s, o);
        q += __shfl_xor_sync(0xffffffffu, q, o);
    }
    __shared__ float ss[4], sq[4];
    if ((tid & 31) == 0) { ss[tid >> 5] = s; sq[tid >> 5] = q; }
    __syncthreads();
    s = ss[0] + ss[1] + ss[2] + ss[3];
    q = sq[0] + sq[1] + sq[2] + sq[3];
    const float mu  = s * (1.0f / Dc);
    const float var = q * (1.0f / Dc) - mu * mu;
    const float inv = rsqrtf(var + 1e-5f);
    float4 g4 = ((const float4*)gw)[tid];
    float4 b4 = ((const float4*)bw)[tid];
    float4 o4;
    o4.x = (v.x - mu) * inv * g4.x + b4.x;
    o4.y = (v.y - mu) * inv * g4.y + b4.y;
    o4.z = (v.z - mu) * inv * g4.z + b4.z;
    o4.w = (v.w - mu) * inv * g4.w + b4.w;
    ((float4*)(Y + (size_t)row * Dc))[tid] = o4;
    if (SPLIT) {
        size_t o = (size_t)row * Dc + tid * 4;
        uint32_t h0, l0, h1, l1;
        split_pair(o4.x, o4.y, h0, l0);
        split_pair(o4.z, o4.w, h1, l1);
        *(uint32_t*)(Yh + o)     = h0;  *(uint32_t*)(Yl + o)     = l0;
        *(uint32_t*)(Yh + o + 2) = h1;  *(uint32_t*)(Yl + o + 2) = l1;
    }
}

// ---------------------------------------------------------------------------
extern "C" void kernel_launch(void* const* d_in, const int* in_sizes, int n_in,
                              void* d_out, int out_size)
{
    const float* x    = (const float*)d_in[0];
    const float* Wq   = (const float*)d_in[2];
    const float* Wk   = (const float*)d_in[3];
    const float* Wfc  = (const float*)d_in[5];
    const float* Wff1 = (const float*)d_in[6];
    const float* Wff2 = (const float*)d_in[7];
    const float* g1   = (const float*)d_in[8];
    const float* b1   = (const float*)d_in[9];
    const float* g2   = (const float*)d_in[10];
    const float* b2   = (const float*)d_in[11];

    float* out_feed = (float*)d_out;
    float* out_attn = (float*)d_out + (size_t)Mc * Dc;

    float *pY1, *pAtt, *pY2;
    cudaGetSymbolAddress((void**)&pY1,  g_y1);
    cudaGetSymbolAddress((void**)&pAtt, g_att);
    cudaGetSymbolAddress((void**)&pY2,  g_y2);

    __nv_bfloat16 *xh,*xl,*qh,*ql,*kh,*kl,*ch,*cl,*ah,*al,*zh,*zl;
    __nv_bfloat16 *wqh,*wql,*wkh,*wkl,*wfh,*wfl,*w1h,*w1l,*w2h,*w2l;
    cudaGetSymbolAddress((void**)&xh,  g_xh);  cudaGetSymbolAddress((void**)&xl,  g_xl);
    cudaGetSymbolAddress((void**)&qh,  g_qh);  cudaGetSymbolAddress((void**)&ql,  g_ql);
    cudaGetSymbolAddress((void**)&kh,  g_kh);  cudaGetSymbolAddress((void**)&kl,  g_kl);
    cudaGetSymbolAddress((void**)&ch,  g_ch);  cudaGetSymbolAddress((void**)&cl,  g_cl);
    cudaGetSymbolAddress((void**)&ah,  g_ah);  cudaGetSymbolAddress((void**)&al,  g_al);
    cudaGetSymbolAddress((void**)&zh,  g_zh);  cudaGetSymbolAddress((void**)&zl,  g_zl);
    cudaGetSymbolAddress((void**)&wqh, g_wqh); cudaGetSymbolAddress((void**)&wql, g_wql);
    cudaGetSymbolAddress((void**)&wkh, g_wkh); cudaGetSymbolAddress((void**)&wkl, g_wkl);
    cudaGetSymbolAddress((void**)&wfh, g_wfh); cudaGetSymbolAddress((void**)&wfl, g_wfl);
    cudaGetSymbolAddress((void**)&w1h, g_w1h); cudaGetSymbolAddress((void**)&w1l, g_w1l);
    cudaGetSymbolAddress((void**)&w2h, g_w2h); cudaGetSymbolAddress((void**)&w2l, g_w2l);

    cudaFuncSetAttribute(attn_mma,
                         cudaFuncAttributeMaxDynamicSharedMemorySize, ATT_SMEM);

    // One-time side-stream resources (created on the uncaptured correctness
    // call; captured calls only record/wait — standard fork-join capture).
    static cudaStream_t s2 = nullptr;
    static cudaEvent_t  eFork = nullptr, eJoin = nullptr;
    if (s2 == nullptr) {
        cudaStreamCreateWithFlags(&s2, cudaStreamNonBlocking);
        cudaEventCreateWithFlags(&eFork, cudaEventDisableTiming);
        cudaEventCreateWithFlags(&eJoin, cudaEventDisableTiming);
    }

    auto cvt = [](const float* in, __nv_bfloat16* hi, __nv_bfloat16* lo, size_t n) {
        cvt_hilo<<<(unsigned)(n / 1024), 256>>>((const float4*)in, (uint2*)hi, (uint2*)lo);
    };

    // 0. splits of x + weights
    cvt(x,    xh,  xl,  (size_t)Mc * Dc);
    cvt(Wq,   wqh, wql, (size_t)Dc * Dc);
    cvt(Wk,   wkh, wkl, (size_t)Dc * Dc);
    cvt(Wfc,  wfh, wfl, (size_t)Dc * Dc);
    cvt(Wff1, w1h, w1l, (size_t)FFc * Dc);
    cvt(Wff2, w2h, w2l, (size_t)Dc * FFc);

    // 1. Q, K projections -> pre-split permuted bf16 (K doubles as V)
    gemm_mma<0><<<dim3(Dc/128, Mc/128), 256>>>(xh, xl, wqh, wql, nullptr, nullptr, qh, ql, Dc, Dc);
    gemm_mma<0><<<dim3(Dc/128, Mc/128), 256>>>(xh, xl, wkh, wkl, nullptr, nullptr, kh, kl, Dc, Dc);

    // 2. Attention (unnormalized attn out + ctx split)
    attn_mma<<<dim3(Sc/128, BHc), 256, ATT_SMEM>>>(out_attn);

    // Fork: normalize attn on side stream, concurrent with the FFN chain
    // (DRAM-bound vs compute-bound — they overlap cleanly).
    cudaEventRecord(eFork, 0);
    cudaStreamWaitEvent(s2, eFork, 0);
    {
        size_t n4 = (size_t)BHc * Sc * Sc / 4;
        norm_attn<<<(unsigned)(n4 / 256), 256, 0, s2>>>(out_attn);
    }

    // 3. y1 = x + ctx@Wfc^T ; att = LN(y1) (+ split)
    gemm_mma<1><<<dim3(Dc/128, Mc/128), 256>>>(ch, cl, wfh, wfl, x, pY1, nullptr, nullptr, Dc, Dc);
    ln_kernel<true><<<Mc, 128>>>(pY1, g1, b1, pAtt, ah, al);

    // 4. z = relu(att@Wff1^T) (split) ; y2 = att + z@Wff2^T ; out = LN(y2)
    gemm_mma<2><<<dim3(FFc/128, Mc/128), 256>>>(ah, al, w1h, w1l, nullptr, nullptr, zh, zl, FFc, Dc);
    gemm_mma<1><<<dim3(Dc/128, Mc/128), 256>>>(zh, zl, w2h, w2l, pAtt, pY2, nullptr, nullptr, Dc, FFc);
    ln_kernel<false><<<Mc, 128>>>(pY2, g2, b2, out_feed, nullptr, nullptr);

    // Join: main stream waits for norm_attn before returning.
    cudaEventRecord(eJoin, s2);
    cudaStreamWaitEvent(0, eJoin, 0);
}

// round 5
// speedup vs baseline: 2.5425x; 1.0659x over previous
#include <cuda_runtime.h>
#include <cuda_bf16.h>
#include <math.h>
#include <stdint.h>

// Problem constants
constexpr int Bc  = 2;
constexpr int Sc  = 4096;
constexpr int Dc  = 512;
constexpr int Hc  = 8;
constexpr int HDc = 64;
constexpr int FFc = 2048;
constexpr int BHc = Bc * Hc;        // 16
constexpr int Mc  = Bc * Sc;        // 8192

// ---------------------------------------------------------------------------
// Scratch (device globals)
// ---------------------------------------------------------------------------
__device__ float g_rs [BHc * Sc];
__device__ float g_y1 [Mc * Dc];
__device__ float g_att[Mc * Dc];
__device__ float g_y2 [Mc * Dc];

__device__ __nv_bfloat16 g_xh [Mc * Dc],        g_xl [Mc * Dc];
__device__ __nv_bfloat16 g_qh [BHc * Sc * HDc], g_ql [BHc * Sc * HDc];
__device__ __nv_bfloat16 g_kh [BHc * Sc * HDc], g_kl [BHc * Sc * HDc];
__device__ __nv_bfloat16 g_ch [Mc * Dc],        g_cl [Mc * Dc];
__device__ __nv_bfloat16 g_ah [Mc * Dc],        g_al [Mc * Dc];
__device__ __nv_bfloat16 g_zh [Mc * FFc],       g_zl [Mc * FFc];
__device__ __nv_bfloat16 g_wqh[Dc * Dc],        g_wql[Dc * Dc];
__device__ __nv_bfloat16 g_wkh[Dc * Dc],        g_wkl[Dc * Dc];
__device__ __nv_bfloat16 g_wfh[Dc * Dc],        g_wfl[Dc * Dc];
__device__ __nv_bfloat16 g_w1h[FFc * Dc],       g_w1l[FFc * Dc];
__device__ __nv_bfloat16 g_w2h[Dc * FFc],       g_w2l[Dc * FFc];

// ---------------------------------------------------------------------------
// Helpers
// ---------------------------------------------------------------------------
__device__ __forceinline__ uint32_t smem_u32(const void* p) {
    uint32_t a;
    asm("{ .reg .u64 t; cvta.to.shared.u64 t, %1; cvt.u32.u64 %0, t; }"
        : "=r"(a) : "l"(p));
    return a;
}
__device__ __forceinline__ void cp16(uint32_t saddr, const void* g) {
    asm volatile("cp.async.cg.shared.global [%0], [%1], 16;"
                 :: "r"(saddr), "l"(g) : "memory");
}
#define CP_COMMIT()  asm volatile("cp.async.commit_group;" ::: "memory")
#define CP_WAIT(n)   asm volatile("cp.async.wait_group %0;" :: "n"(n) : "memory")

__device__ __forceinline__ void ldsm_x4(uint32_t& r0, uint32_t& r1,
                                        uint32_t& r2, uint32_t& r3, uint32_t a) {
    asm volatile("ldmatrix.sync.aligned.m8n8.x4.shared.b16 {%0,%1,%2,%3}, [%4];"
                 : "=r"(r0), "=r"(r1), "=r"(r2), "=r"(r3) : "r"(a));
}
__device__ __forceinline__ void ldsm_x4_t(uint32_t& r0, uint32_t& r1,
                                          uint32_t& r2, uint32_t& r3, uint32_t a) {
    asm volatile("ldmatrix.sync.aligned.m8n8.x4.trans.shared.b16 {%0,%1,%2,%3}, [%4];"
                 : "=r"(r0), "=r"(r1), "=r"(r2), "=r"(r3) : "r"(a));
}

__device__ __forceinline__ void mma16816(float c[4],
        uint32_t a0, uint32_t a1, uint32_t a2, uint32_t a3,
        uint32_t b0, uint32_t b1) {
    asm volatile("mma.sync.aligned.m16n8k16.row.col.f32.bf16.bf16.f32 "
                 "{%0,%1,%2,%3}, {%4,%5,%6,%7}, {%8,%9}, {%0,%1,%2,%3};"
                 : "+f"(c[0]), "+f"(c[1]), "+f"(c[2]), "+f"(c[3])
                 : "r"(a0), "r"(a1), "r"(a2), "r"(a3), "r"(b0), "r"(b1));
}

__device__ __forceinline__ uint32_t pack_bf(__nv_bfloat16 a, __nv_bfloat16 b) {
    return ((uint32_t)__bfloat16_as_ushort(b) << 16) | (uint32_t)__bfloat16_as_ushort(a);
}
__device__ __forceinline__ void split_pair(float x, float y, uint32_t& h, uint32_t& l) {
    __nv_bfloat16 hx = __float2bfloat16(x), hy = __float2bfloat16(y);
    h = pack_bf(hx, hy);
    l = pack_bf(__float2bfloat16(x - __bfloat162float(hx)),
                __float2bfloat16(y - __bfloat162float(hy)));
}

// ---------------------------------------------------------------------------
// fp32 -> bf16 hi/lo split conversion
// ---------------------------------------------------------------------------
__global__ __launch_bounds__(256)
void cvt_hilo(const float4* __restrict__ in, uint2* __restrict__ hi,
              uint2* __restrict__ lo)
{
    size_t i = (size_t)blockIdx.x * 256 + threadIdx.x;
    float4 v = in[i];
    uint32_t h0, l0, h1, l1;
    split_pair(v.x, v.y, h0, l0);
    split_pair(v.z, v.w, h1, l1);
    hi[i] = make_uint2(h0, h1);
    lo[i] = make_uint2(l0, l1);
}

// ---------------------------------------------------------------------------
// HMMA GEMM (bf16x3), cp.async 2-stage pipelined.
// C[M,N] = A[M,K] @ W[N,K]^T. CTA 128x128, BK=32, 256 thr, 8 warps.
// EPI 0: permuted bf16-split store ; 1: fp32+residual ; 2: relu+split
// ---------------------------------------------------------------------------
constexpr int GP = 80;
constexpr int SM_A_H = 0, SM_A_L = 10240, SM_B_H = 20480, SM_B_L = 30720;
constexpr int GSTG = 40960;
constexpr int GEMM_SMEM2 = 2 * GSTG;           // 81920

template<int EPI>
__global__ __launch_bounds__(256, 2)
void gemm_mma(const __nv_bfloat16* __restrict__ Ah, const __nv_bfloat16* __restrict__ Al,
              const __nv_bfloat16* __restrict__ Bh, const __nv_bfloat16* __restrict__ Bl,
              const float* __restrict__ res, float* __restrict__ Cf,
              __nv_bfloat16* __restrict__ Ch, __nv_bfloat16* __restrict__ Cl,
              int N, int K)
{
    extern __shared__ __align__(16) char smd[];
    const uint32_t sb = smem_u32(smd);
    const int tid = threadIdx.x, lane = tid & 31, wid = tid >> 5;
    const int wm = wid >> 2, wn = wid & 3;
    const int m0 = blockIdx.y * 128, n0 = blockIdx.x * 128;
    const int NK = K >> 5;

    float acc[4][4][4];
    #pragma unroll
    for (int i = 0; i < 4; ++i)
        #pragma unroll
        for (int j = 0; j < 4; ++j)
            #pragma unroll
            for (int q = 0; q < 4; ++q) acc[i][j][q] = 0.f;

    auto issue = [&](int it, int stg) {
        uint32_t base = sb + stg * GSTG;
        #pragma unroll
        for (int i = 0; i < 2; ++i) {
            int seg = tid + i * 256, row = seg >> 2, part = seg & 3;
            size_t ga = (size_t)(m0 + row) * K + it * 32 + part * 8;
            size_t gb = (size_t)(n0 + row) * K + it * 32 + part * 8;
            int so = row * GP + part * 16;
            cp16(base + SM_A_H + so, Ah + ga);
            cp16(base + SM_A_L + so, Al + ga);
            cp16(base + SM_B_H + so, Bh + gb);
            cp16(base + SM_B_L + so, Bl + gb);
        }
        CP_COMMIT();
    };

    issue(0, 0);
    issue(1, 1);                                  // NK >= 16 always

    for (int it = 0; it < NK; ++it) {
        const int stg = it & 1;
        if (it + 1 < NK) { CP_WAIT(1); } else { CP_WAIT(0); }
        __syncthreads();
        const uint32_t base = sb + stg * GSTG;

        #pragma unroll
        for (int ks = 0; ks < 2; ++ks) {
            uint32_t bhf[4][2], blf[4][2];
            #pragma unroll
            for (int nfp = 0; nfp < 2; ++nfp) {
                int ro = (wn * 32 + nfp * 16 + (lane & 15)) * GP + ks * 32 + (lane >> 4) * 16;
                uint32_t r0, r1, r2, r3;
                ldsm_x4(r0, r1, r2, r3, base + SM_B_H + ro);
                bhf[nfp*2][0] = r0; bhf[nfp*2+1][0] = r1;
                bhf[nfp*2][1] = r2; bhf[nfp*2+1][1] = r3;
                ldsm_x4(r0, r1, r2, r3, base + SM_B_L + ro);
                blf[nfp*2][0] = r0; blf[nfp*2+1][0] = r1;
                blf[nfp*2][1] = r2; blf[nfp*2+1][1] = r3;
            }
            #pragma unroll
            for (int mf = 0; mf < 4; ++mf) {
                int ro = (wm * 64 + mf * 16 + (lane & 15)) * GP + ks * 32 + (lane >> 4) * 16;
                uint32_t a0, a1, a2, a3, l0, l1, l2, l3;
                ldsm_x4(a0, a1, a2, a3, base + SM_A_H + ro);
                ldsm_x4(l0, l1, l2, l3, base + SM_A_L + ro);
                #pragma unroll
                for (int nf = 0; nf < 4; ++nf) {
                    mma16816(acc[mf][nf], a0, a1, a2, a3, bhf[nf][0], bhf[nf][1]);
                    mma16816(acc[mf][nf], a0, a1, a2, a3, blf[nf][0], blf[nf][1]);
                    mma16816(acc[mf][nf], l0, l1, l2, l3, bhf[nf][0], bhf[nf][1]);
                }
            }
        }
        __syncthreads();
        if (it + 2 < NK) issue(it + 2, stg);
    }

    // epilogue
    #pragma unroll
    for (int mf = 0; mf < 4; ++mf) {
        int r0 = m0 + wm * 64 + mf * 16 + (lane >> 2);
        #pragma unroll
        for (int nf = 0; nf < 4; ++nf) {
            int c = n0 + wn * 32 + nf * 8 + (lane & 3) * 2;
            float v0 = acc[mf][nf][0], v1 = acc[mf][nf][1];
            float v2 = acc[mf][nf][2], v3 = acc[mf][nf][3];
            if (EPI == 0) {
                int hh = c >> 6, d = c & 63;
                int b0 = r0 >> 12, s0 = r0 & 4095;
                size_t o = (((size_t)(b0 * Hc + hh)) * Sc + s0) * HDc + d;
                uint32_t ph, pl;
                split_pair(v0, v1, ph, pl);
                *(uint32_t*)(Ch + o) = ph; *(uint32_t*)(Cl + o) = pl;
                int r1 = r0 + 8;
                int b1 = r1 >> 12, s1 = r1 & 4095;
                o = (((size_t)(b1 * Hc + hh)) * Sc + s1) * HDc + d;
                split_pair(v2, v3, ph, pl);
                *(uint32_t*)(Ch + o) = ph; *(uint32_t*)(Cl + o) = pl;
            } else if (EPI == 1) {
                size_t o = (size_t)r0 * N + c;
                float2 rr = *(const float2*)(res + o);
                *(float2*)(Cf + o) = make_float2(v0 + rr.x, v1 + rr.y);
                o = (size_t)(r0 + 8) * N + c;
                rr = *(const float2*)(res + o);
                *(float2*)(Cf + o) = make_float2(v2 + rr.x, v3 + rr.y);
            } else {
                v0 = fmaxf(v0, 0.f); v1 = fmaxf(v1, 0.f);
                v2 = fmaxf(v2, 0.f); v3 = fmaxf(v3, 0.f);
                size_t o = (size_t)r0 * N + c;
                uint32_t ph, pl;
                split_pair(v0, v1, ph, pl);
                *(uint32_t*)(Ch + o) = ph; *(uint32_t*)(Cl + o) = pl;
                o = (size_t)(r0 + 8) * N + c;
                split_pair(v2, v3, ph, pl);
                *(uint32_t*)(Ch + o) = ph; *(uint32_t*)(Cl + o) = pl;
            }
        }
    }
}

// ---------------------------------------------------------------------------
// HMMA attention, cp.async double-buffered K tiles.
// S = QK^T (bf16x3), P = exp(S/8) -> gmem fp32 + smem bf16-hi,
// ctx += P@V (single MMA). Rowsums in regs; ctx normalized, split-stored.
// ---------------------------------------------------------------------------
constexpr int AP    = 144;
constexpr int A_QH  = 0,     A_QL  = 18432;
constexpr int A_K0H = 36864, A_K0L = 46080;
constexpr int A_K1H = 55296, A_K1L = 64512;
constexpr int A_PH  = 73728, A_RS  = 92160;
constexpr int ATT_SMEM = A_RS + 512 + 16;      // 92688

__global__ __launch_bounds__(256, 2)
void attn_mma(float* __restrict__ attn_out)
{
    extern __shared__ __align__(16) char sm[];
    float* rsum = (float*)(sm + A_RS);
    const uint32_t sb = smem_u32(sm);
    const int tid = threadIdx.x, lane = tid & 31, wid = tid >> 5;
    const int wm = wid >> 1, wn = wid & 1;       // 4 M-warps x 2 N-warps
    const int bh = blockIdx.y, q0 = blockIdx.x * 128;

    const __nv_bfloat16* Qh = g_qh + (size_t)bh * Sc * HDc;
    const __nv_bfloat16* Ql = g_ql + (size_t)bh * Sc * HDc;
    const __nv_bfloat16* Kh = g_kh + (size_t)bh * Sc * HDc;
    const __nv_bfloat16* Kl = g_kl + (size_t)bh * Sc * HDc;

    const uint32_t KH_OF[2] = {A_K0H, A_K1H};
    const uint32_t KL_OF[2] = {A_K0L, A_K1L};

    auto issueK = [&](int kt, int stg) {
        #pragma unroll
        for (int i = 0; i < 2; ++i) {
            int seg = tid + i * 256, row = seg >> 3, part = seg & 7;
            size_t g = (size_t)(kt * 64 + row) * HDc + part * 8;
            int so = row * AP + part * 16;
            cp16(sb + KH_OF[stg] + so, Kh + g);
            cp16(sb + KL_OF[stg] + so, Kl + g);
        }
        CP_COMMIT();
    };

    issueK(0, 0);
    issueK(1, 1);

    // Q tile 128x64 (hi/lo), regular loads
    #pragma unroll
    for (int i = 0; i < 4; ++i) {
        int seg = tid + i * 256, row = seg >> 3, part = seg & 7;
        size_t g = (size_t)(q0 + row) * HDc + part * 8;
        int so = row * AP + part * 16;
        *(uint4*)(sm + A_QH + so) = *(const uint4*)(Qh + g);
        *(uint4*)(sm + A_QL + so) = *(const uint4*)(Ql + g);
    }
    if (tid < 128) rsum[tid] = 0.f;

    float ctx[2][4][4];
    #pragma unroll
    for (int i = 0; i < 2; ++i)
        #pragma unroll
        for (int j = 0; j < 4; ++j)
            #pragma unroll
            for (int q = 0; q < 4; ++q) ctx[i][j][q] = 0.f;
    float rs[2][2] = {{0.f, 0.f}, {0.f, 0.f}};

    for (int kt = 0; kt < Sc / 64; ++kt) {
        const int stg = kt & 1;
        if (kt + 1 < Sc / 64) { CP_WAIT(1); } else { CP_WAIT(0); }
        __syncthreads();          // K[stg] ready; prev PV done (P overwrite safe)
        const uint32_t KB_H = sb + KH_OF[stg];
        const uint32_t KB_L = sb + KL_OF[stg];

        // ---- S = Q K^T (bf16x3) ----
        float s[2][4][4];
        #pragma unroll
        for (int i = 0; i < 2; ++i)
            #pragma unroll
            for (int j = 0; j < 4; ++j)
                #pragma unroll
                for (int q = 0; q < 4; ++q) s[i][j][q] = 0.f;

        #pragma unroll
        for (int ks = 0; ks < 4; ++ks) {
            uint32_t bhf[4][2], blf[4][2];
            #pragma unroll
            for (int nfp = 0; nfp < 2; ++nfp) {
                int ro = (wn * 32 + nfp * 16 + (lane & 15)) * AP + ks * 32 + (lane >> 4) * 16;
                uint32_t r0, r1, r2, r3;
                ldsm_x4(r0, r1, r2, r3, KB_H + ro);
                bhf[nfp*2][0] = r0; bhf[nfp*2+1][0] = r1;
                bhf[nfp*2][1] = r2; bhf[nfp*2+1][1] = r3;
                ldsm_x4(r0, r1, r2, r3, KB_L + ro);
                blf[nfp*2][0] = r0; blf[nfp*2+1][0] = r1;
                blf[nfp*2][1] = r2; blf[nfp*2+1][1] = r3;
            }
            #pragma unroll
            for (int mf = 0; mf < 2; ++mf) {
                int ro = (wm * 32 + mf * 16 + (lane & 15)) * AP + ks * 32 + (lane >> 4) * 16;
                uint32_t a0, a1, a2, a3, l0, l1, l2, l3;
                ldsm_x4(a0, a1, a2, a3, sb + A_QH + ro);
                ldsm_x4(l0, l1, l2, l3, sb + A_QL + ro);
                #pragma unroll
                for (int nf = 0; nf < 4; ++nf) {
                    mma16816(s[mf][nf], a0, a1, a2, a3, bhf[nf][0], bhf[nf][1]);
                    mma16816(s[mf][nf], a0, a1, a2, a3, blf[nf][0], blf[nf][1]);
                    mma16816(s[mf][nf], l0, l1, l2, l3, bhf[nf][0], bhf[nf][1]);
                }
            }
        }

        // ---- exp, rowsum, P stores (fp32 gmem + bf16-hi smem) ----
        #pragma unroll
        for (int mf = 0; mf < 2; ++mf) {
            int rl = wm * 32 + mf * 16 + (lane >> 2);
            #pragma unroll
            for (int nf = 0; nf < 4; ++nf) {
                int cl_ = wn * 32 + nf * 8 + (lane & 3) * 2;
                float p0 = __expf(s[mf][nf][0] * 0.125f);
                float p1 = __expf(s[mf][nf][1] * 0.125f);
                float p2 = __expf(s[mf][nf][2] * 0.125f);
                float p3 = __expf(s[mf][nf][3] * 0.125f);
                rs[mf][0] += p0 + p1;
                rs[mf][1] += p2 + p3;
                size_t gr = ((size_t)bh * Sc + q0 + rl) * Sc + kt * 64 + cl_;
                *(float2*)(attn_out + gr) = make_float2(p0, p1);
                *(float2*)(attn_out + gr + (size_t)8 * Sc) = make_float2(p2, p3);
                int so = rl * AP + cl_ * 2;
                *(uint32_t*)(sm + A_PH + so) =
                    pack_bf(__float2bfloat16(p0), __float2bfloat16(p1));
                *(uint32_t*)(sm + A_PH + so + 8 * AP) =
                    pack_bf(__float2bfloat16(p2), __float2bfloat16(p3));
            }
        }
        __syncthreads();          // P visible for ldmatrix

        // ---- ctx += P V  (single MMA; V = K-hi tile via trans ldmatrix) ----
        #pragma unroll
        for (int ks = 0; ks < 4; ++ks) {
            uint32_t vh[4][2];
            #pragma unroll
            for (int nfp = 0; nfp < 2; ++nfp) {
                int ro = (ks * 16 + (lane & 15)) * AP + wn * 64 + nfp * 32 + (lane >> 4) * 16;
                uint32_t r0, r1, r2, r3;
                ldsm_x4_t(r0, r1, r2, r3, KB_H + ro);
                vh[nfp*2][0] = r0; vh[nfp*2][1] = r1;
                vh[nfp*2+1][0] = r2; vh[nfp*2+1][1] = r3;
            }
            #pragma unroll
            for (int mf = 0; mf < 2; ++mf) {
                int ro = (wm * 32 + mf * 16 + (lane & 15)) * AP + ks * 32 + (lane >> 4) * 16;
                uint32_t p0, p1, p2, p3;
                ldsm_x4(p0, p1, p2, p3, sb + A_PH + ro);
                #pragma unroll
                for (int nf = 0; nf < 4; ++nf)
                    mma16816(ctx[mf][nf], p0, p1, p2, p3, vh[nf][0], vh[nf][1]);
            }
        }
        __syncthreads();          // all reads of K[stg] done -> safe to refill
        if (kt + 2 < Sc / 64) issueK(kt + 2, stg);
    }

    // ---- rowsum reduce ----
    #pragma unroll
    for (int mf = 0; mf < 2; ++mf)
        #pragma unroll
        for (int h = 0; h < 2; ++h) {
            float v = rs[mf][h];
            v += __shfl_xor_sync(0xffffffffu, v, 1);
            v += __shfl_xor_sync(0xffffffffu, v, 2);
            if ((lane & 3) == 0)
                atomicAdd(&rsum[wm * 32 + mf * 16 + h * 8 + (lane >> 2)], v);
        }
    __syncthreads();

    if (tid < 128) g_rs[(size_t)bh * Sc + q0 + tid] = rsum[tid];

    const int bb = bh >> 3, hh = bh & 7;
    #pragma unroll
    for (int mf = 0; mf < 2; ++mf) {
        int rl = wm * 32 + mf * 16 + (lane >> 2);
        float i0 = 1.f / rsum[rl];
        float i1 = 1.f / rsum[rl + 8];
        #pragma unroll
        for (int nf = 0; nf < 4; ++nf) {
            int d = wn * 32 + nf * 8 + (lane & 3) * 2;
            size_t o = ((size_t)bb * Sc + q0 + rl) * Dc + hh * HDc + d;
            uint32_t ph, pl;
            split_pair(ctx[mf][nf][0] * i0, ctx[mf][nf][1] * i0, ph, pl);
            *(uint32_t*)(g_ch + o) = ph; *(uint32_t*)(g_cl + o) = pl;
            o += (size_t)8 * Dc;
            split_pair(ctx[mf][nf][2] * i1, ctx[mf][nf][3] * i1, ph, pl);
            *(uint32_t*)(g_ch + o) = ph; *(uint32_t*)(g_cl + o) = pl;
        }
    }
}

// ---------------------------------------------------------------------------
// attn /= rowsum
// ---------------------------------------------------------------------------
__global__ __launch_bounds__(256)
void norm_attn(float* __restrict__ attn)
{
    size_t i = (size_t)blockIdx.x * 256 + threadIdx.x;
    size_t row = (i * 4) >> 12;
    float inv = 1.0f / g_rs[row];
    float4 v = ((const float4*)attn)[i];
    v.x *= inv; v.y *= inv; v.z *= inv; v.w *= inv;
    ((float4*)attn)[i] = v;
}

// ---------------------------------------------------------------------------
// LayerNorm; optionally also emits bf16 hi/lo split
// ---------------------------------------------------------------------------
template<bool SPLIT>
__global__ __launch_bounds__(128)
void ln_kernel(const float* __restrict__ X, const float* __restrict__ gw,
               const float* __restrict__ bw, float* __restrict__ Y,
               __nv_bfloat16* __restrict__ Yh, __nv_bfloat16* __restrict__ Yl)
{
    const int row = blockIdx.x;
    const int tid = threadIdx.x;
    float4 v = ((const float4*)(X + (size_t)row * Dc))[tid];
    float s = (v.x + v.y) + (v.z + v.w);
    float q = (v.x*v.x + v.y*v.y) + (v.z*v.z + v.w*v.w);
    #pragma unroll
    for (int o = 16; o; o >>= 1) {
        s += __shfl_xor_sync(0xffffffffu, s, o);
        q += __shfl_xor_sync(0xffffffffu, q, o);
    }
    __shared__ float ss[4], sq[4];
    if ((tid & 31) == 0) { ss[tid >> 5] = s; sq[tid >> 5] = q; }
    __syncthreads();
    s = ss[0] + ss[1] + ss[2] + ss[3];
    q = sq[0] + sq[1] + sq[2] + sq[3];
    const float mu  = s * (1.0f / Dc);
    const float var = q * (1.0f / Dc) - mu * mu;
    const float inv = rsqrtf(var + 1e-5f);
    float4 g4 = ((const float4*)gw)[tid];
    float4 b4 = ((const float4*)bw)[tid];
    float4 o4;
    o4.x = (v.x - mu) * inv * g4.x + b4.x;
    o4.y = (v.y - mu) * inv * g4.y + b4.y;
    o4.z = (v.z - mu) * inv * g4.z + b4.z;
    o4.w = (v.w - mu) * inv * g4.w + b4.w;
    ((float4*)(Y + (size_t)row * Dc))[tid] = o4;
    if (SPLIT) {
        size_t o = (size_t)row * Dc + tid * 4;
        uint32_t h0, l0, h1, l1;
        split_pair(o4.x, o4.y, h0, l0);
        split_pair(o4.z, o4.w, h1, l1);
        *(uint32_t*)(Yh + o)     = h0;  *(uint32_t*)(Yl + o)     = l0;
        *(uint32_t*)(Yh + o + 2) = h1;  *(uint32_t*)(Yl + o + 2) = l1;
    }
}

// ---------------------------------------------------------------------------
extern "C" void kernel_launch(void* const* d_in, const int* in_sizes, int n_in,
                              void* d_out, int out_size)
{
    const float* x    = (const float*)d_in[0];
    const float* Wq   = (const float*)d_in[2];
    const float* Wk   = (const float*)d_in[3];
    const float* Wfc  = (const float*)d_in[5];
    const float* Wff1 = (const float*)d_in[6];
    const float* Wff2 = (const float*)d_in[7];
    const float* g1   = (const float*)d_in[8];
    const float* b1   = (const float*)d_in[9];
    const float* g2   = (const float*)d_in[10];
    const float* b2   = (const float*)d_in[11];

    float* out_feed = (float*)d_out;
    float* out_attn = (float*)d_out + (size_t)Mc * Dc;

    float *pY1, *pAtt, *pY2;
    cudaGetSymbolAddress((void**)&pY1,  g_y1);
    cudaGetSymbolAddress((void**)&pAtt, g_att);
    cudaGetSymbolAddress((void**)&pY2,  g_y2);

    __nv_bfloat16 *xh,*xl,*qh,*ql,*kh,*kl,*ch,*cl,*ah,*al,*zh,*zl;
    __nv_bfloat16 *wqh,*wql,*wkh,*wkl,*wfh,*wfl,*w1h,*w1l,*w2h,*w2l;
    cudaGetSymbolAddress((void**)&xh,  g_xh);  cudaGetSymbolAddress((void**)&xl,  g_xl);
    cudaGetSymbolAddress((void**)&qh,  g_qh);  cudaGetSymbolAddress((void**)&ql,  g_ql);
    cudaGetSymbolAddress((void**)&kh,  g_kh);  cudaGetSymbolAddress((void**)&kl,  g_kl);
    cudaGetSymbolAddress((void**)&ch,  g_ch);  cudaGetSymbolAddress((void**)&cl,  g_cl);
    cudaGetSymbolAddress((void**)&ah,  g_ah);  cudaGetSymbolAddress((void**)&al,  g_al);
    cudaGetSymbolAddress((void**)&zh,  g_zh);  cudaGetSymbolAddress((void**)&zl,  g_zl);
    cudaGetSymbolAddress((void**)&wqh, g_wqh); cudaGetSymbolAddress((void**)&wql, g_wql);
    cudaGetSymbolAddress((void**)&wkh, g_wkh); cudaGetSymbolAddress((void**)&wkl, g_wkl);
    cudaGetSymbolAddress((void**)&wfh, g_wfh); cudaGetSymbolAddress((void**)&wfl, g_wfl);
    cudaGetSymbolAddress((void**)&w1h, g_w1h); cudaGetSymbolAddress((void**)&w1l, g_w1l);
    cudaGetSymbolAddress((void**)&w2h, g_w2h); cudaGetSymbolAddress((void**)&w2l, g_w2l);

    cudaFuncSetAttribute(attn_mma,
                         cudaFuncAttributeMaxDynamicSharedMemorySize, ATT_SMEM);
    cudaFuncSetAttribute(gemm_mma<0>,
                         cudaFuncAttributeMaxDynamicSharedMemorySize, GEMM_SMEM2);
    cudaFuncSetAttribute(gemm_mma<1>,
                         cudaFuncAttributeMaxDynamicSharedMemorySize, GEMM_SMEM2);
    cudaFuncSetAttribute(gemm_mma<2>,
                         cudaFuncAttributeMaxDynamicSharedMemorySize, GEMM_SMEM2);

    // One-time side-stream resources
    static cudaStream_t s2 = nullptr;
    static cudaEvent_t  eFork = nullptr, eJoin = nullptr, eW = nullptr;
    if (s2 == nullptr) {
        cudaStreamCreateWithFlags(&s2, cudaStreamNonBlocking);
        cudaEventCreateWithFlags(&eFork, cudaEventDisableTiming);
        cudaEventCreateWithFlags(&eJoin, cudaEventDisableTiming);
        cudaEventCreateWithFlags(&eW,    cudaEventDisableTiming);
    }

    auto cvtOn = [](cudaStream_t st, const float* in, __nv_bfloat16* hi,
                    __nv_bfloat16* lo, size_t n) {
        cvt_hilo<<<(unsigned)(n / 1024), 256, 0, st>>>((const float4*)in,
                                                       (uint2*)hi, (uint2*)lo);
    };

    // 0. x split on main; weight splits on side stream (overlapped)
    cudaEventRecord(eFork, 0);
    cudaStreamWaitEvent(s2, eFork, 0);
    cvtOn(0,  x,    xh,  xl,  (size_t)Mc * Dc);
    cvtOn(s2, Wq,   wqh, wql, (size_t)Dc * Dc);
    cvtOn(s2, Wk,   wkh, wkl, (size_t)Dc * Dc);
    cvtOn(s2, Wfc,  wfh, wfl, (size_t)Dc * Dc);
    cvtOn(s2, Wff1, w1h, w1l, (size_t)FFc * Dc);
    cvtOn(s2, Wff2, w2h, w2l, (size_t)Dc * FFc);
    cudaEventRecord(eW, s2);
    cudaStreamWaitEvent(0, eW, 0);

    // 1. Q, K projections -> pre-split permuted bf16 (K doubles as V)
    gemm_mma<0><<<dim3(Dc/128, Mc/128), 256, GEMM_SMEM2>>>(xh, xl, wqh, wql, nullptr, nullptr, qh, ql, Dc, Dc);
    gemm_mma<0><<<dim3(Dc/128, Mc/128), 256, GEMM_SMEM2>>>(xh, xl, wkh, wkl, nullptr, nullptr, kh, kl, Dc, Dc);

    // 2. Attention (unnormalized attn out + ctx split)
    attn_mma<<<dim3(Sc/128, BHc), 256, ATT_SMEM>>>(out_attn);

    // Fork: normalize attn on side stream, concurrent with FFN chain
    cudaEventRecord(eFork, 0);
    cudaStreamWaitEvent(s2, eFork, 0);
    {
        size_t n4 = (size_t)BHc * Sc * Sc / 4;
        norm_attn<<<(unsigned)(n4 / 256), 256, 0, s2>>>(out_attn);
    }

    // 3. y1 = x + ctx@Wfc^T ; att = LN(y1) (+ split)
    gemm_mma<1><<<dim3(Dc/128, Mc/128), 256, GEMM_SMEM2>>>(ch, cl, wfh, wfl, x, pY1, nullptr, nullptr, Dc, Dc);
    ln_kernel<true><<<Mc, 128>>>(pY1, g1, b1, pAtt, ah, al);

    // 4. z = relu(att@Wff1^T) ; y2 = att + z@Wff2^T ; out = LN(y2)
    gemm_mma<2><<<dim3(FFc/128, Mc/128), 256, GEMM_SMEM2>>>(ah, al, w1h, w1l, nullptr, nullptr, zh, zl, FFc, Dc);
    gemm_mma<1><<<dim3(Dc/128, Mc/128), 256, GEMM_SMEM2>>>(zh, zl, w2h, w2l, pAtt, pY2, nullptr, nullptr, Dc, FFc);
    ln_kernel<false><<<Mc, 128>>>(pY2, g2, b2, out_feed, nullptr, nullptr);

    // Join: main stream waits for norm_attn
    cudaEventRecord(eJoin, s2);
    cudaStreamWaitEvent(0, eJoin, 0);
}

// round 6
// speedup vs baseline: 3.0715x; 1.2080x over previous
#include <cuda_runtime.h>
#include <cuda_fp16.h>
#include <math.h>
#include <stdint.h>

// Problem constants
constexpr int Bc  = 2;
constexpr int Sc  = 4096;
constexpr int Dc  = 512;
constexpr int Hc  = 8;
constexpr int HDc = 64;
constexpr int FFc = 2048;
constexpr int BHc = Bc * Hc;        // 16
constexpr int Mc  = Bc * Sc;        // 8192

// ---------------------------------------------------------------------------
// Scratch (device globals)
// ---------------------------------------------------------------------------
__device__ float g_rs [BHc * Sc];
__device__ float g_y1 [Mc * Dc];
__device__ float g_att[Mc * Dc];
__device__ float g_y2 [Mc * Dc];

__device__ __half g_xh [Mc * Dc];
__device__ __half g_qh [BHc * Sc * HDc], g_ql [BHc * Sc * HDc];
__device__ __half g_kh [BHc * Sc * HDc];
__device__ __half g_ch [Mc * Dc];
__device__ __half g_ah [Mc * Dc];
__device__ __half g_zh [Mc * FFc];
__device__ __half g_wqh[Dc * Dc],  g_wql[Dc * Dc];
__device__ __half g_wkh[Dc * Dc],  g_wkl[Dc * Dc];
__device__ __half g_wfh[Dc * Dc],  g_wfl[Dc * Dc];
__device__ __half g_w1h[FFc * Dc], g_w1l[FFc * Dc];
__device__ __half g_w2h[Dc * FFc], g_w2l[Dc * FFc];

// ---------------------------------------------------------------------------
// Helpers
// ---------------------------------------------------------------------------
__device__ __forceinline__ uint32_t smem_u32(const void* p) {
    uint32_t a;
    asm("{ .reg .u64 t; cvta.to.shared.u64 t, %1; cvt.u32.u64 %0, t; }"
        : "=r"(a) : "l"(p));
    return a;
}
__device__ __forceinline__ void cp16(uint32_t saddr, const void* g) {
    asm volatile("cp.async.cg.shared.global [%0], [%1], 16;"
                 :: "r"(saddr), "l"(g) : "memory");
}
#define CP_COMMIT()  asm volatile("cp.async.commit_group;" ::: "memory")
#define CP_WAIT(n)   asm volatile("cp.async.wait_group %0;" :: "n"(n) : "memory")

__device__ __forceinline__ void ldsm_x4(uint32_t& r0, uint32_t& r1,
                                        uint32_t& r2, uint32_t& r3, uint32_t a) {
    asm volatile("ldmatrix.sync.aligned.m8n8.x4.shared.b16 {%0,%1,%2,%3}, [%4];"
                 : "=r"(r0), "=r"(r1), "=r"(r2), "=r"(r3) : "r"(a));
}
__device__ __forceinline__ void ldsm_x4_t(uint32_t& r0, uint32_t& r1,
                                          uint32_t& r2, uint32_t& r3, uint32_t a) {
    asm volatile("ldmatrix.sync.aligned.m8n8.x4.trans.shared.b16 {%0,%1,%2,%3}, [%4];"
                 : "=r"(r0), "=r"(r1), "=r"(r2), "=r"(r3) : "r"(a));
}

__device__ __forceinline__ void mma16816(float c[4],
        uint32_t a0, uint32_t a1, uint32_t a2, uint32_t a3,
        uint32_t b0, uint32_t b1) {
    asm volatile("mma.sync.aligned.m16n8k16.row.col.f32.f16.f16.f32 "
                 "{%0,%1,%2,%3}, {%4,%5,%6,%7}, {%8,%9}, {%0,%1,%2,%3};"
                 : "+f"(c[0]), "+f"(c[1]), "+f"(c[2]), "+f"(c[3])
                 : "r"(a0), "r"(a1), "r"(a2), "r"(a3), "r"(b0), "r"(b1));
}

__device__ __forceinline__ uint32_t pack_h(__half a, __half b) {
    return ((uint32_t)__half_as_ushort(b) << 16) | (uint32_t)__half_as_ushort(a);
}
__device__ __forceinline__ uint32_t pack_hf(float x, float y) {
    return pack_h(__float2half_rn(x), __float2half_rn(y));
}
__device__ __forceinline__ void split_pair_h(float x, float y,
                                             uint32_t& h, uint32_t& l) {
    __half hx = __float2half_rn(x), hy = __float2half_rn(y);
    h = pack_h(hx, hy);
    l = pack_h(__float2half_rn(x - __half2float(hx)),
               __float2half_rn(y - __half2float(hy)));
}

// ---------------------------------------------------------------------------
// fp32 -> fp16 conversions
// ---------------------------------------------------------------------------
__global__ __launch_bounds__(256)
void cvt_hilo(const float4* __restrict__ in, uint2* __restrict__ hi,
              uint2* __restrict__ lo)
{
    size_t i = (size_t)blockIdx.x * 256 + threadIdx.x;
    float4 v = in[i];
    uint32_t h0, l0, h1, l1;
    split_pair_h(v.x, v.y, h0, l0);
    split_pair_h(v.z, v.w, h1, l1);
    hi[i] = make_uint2(h0, h1);
    lo[i] = make_uint2(l0, l1);
}
__global__ __launch_bounds__(256)
void cvt_hi(const float4* __restrict__ in, uint2* __restrict__ hi)
{
    size_t i = (size_t)blockIdx.x * 256 + threadIdx.x;
    float4 v = in[i];
    hi[i] = make_uint2(pack_hf(v.x, v.y), pack_hf(v.z, v.w));
}

// ---------------------------------------------------------------------------
// HMMA GEMM (fp16 x2: A-hi * (W-hi + W-lo)), 3-stage cp.async.
// C[M,N] = A[M,K] @ W[N,K]^T. CTA 128x128, BK=32, 256 thr, 8 warps (2Mx4N).
// EPI 0: permuted fp16 hi+lo store (Q) ; 3: permuted fp16 hi (K)
// EPI 1: fp32 + residual ; 2: relu + fp16 hi
// ---------------------------------------------------------------------------
constexpr int GP = 80;                         // smem row stride bytes (64B + pad)
constexpr int SM_A = 0, SM_WH = 10240, SM_WL = 20480;
constexpr int GSTG = 30720;
constexpr int GEMM_SMEM3 = 3 * GSTG;           // 92160

template<int EPI>
__global__ __launch_bounds__(256, 2)
void gemm_mma(const __half* __restrict__ Ah,
              const __half* __restrict__ Wh, const __half* __restrict__ Wl,
              const float* __restrict__ res, float* __restrict__ Cf,
              __half* __restrict__ Ch, __half* __restrict__ Cl,
              int N, int K)
{
    extern __shared__ __align__(16) char smd[];
    const uint32_t sb = smem_u32(smd);
    const int tid = threadIdx.x, lane = tid & 31, wid = tid >> 5;
    const int wm = wid >> 2, wn = wid & 3;
    const int m0 = blockIdx.y * 128, n0 = blockIdx.x * 128;
    const int NK = K >> 5;

    float acc[4][4][4];
    #pragma unroll
    for (int i = 0; i < 4; ++i)
        #pragma unroll
        for (int j = 0; j < 4; ++j)
            #pragma unroll
            for (int q = 0; q < 4; ++q) acc[i][j][q] = 0.f;

    auto issue = [&](int it, int stg) {
        uint32_t base = sb + stg * GSTG;
        #pragma unroll
        for (int i = 0; i < 2; ++i) {
            int c = tid + i * 256, row = c >> 2, part = c & 3;
            int so = row * GP + part * 16;
            size_t ga = (size_t)(m0 + row) * K + it * 32 + part * 8;
            size_t gw = (size_t)(n0 + row) * K + it * 32 + part * 8;
            cp16(base + SM_A  + so, Ah + ga);
            cp16(base + SM_WH + so, Wh + gw);
            cp16(base + SM_WL + so, Wl + gw);
        }
        CP_COMMIT();
    };

    issue(0, 0);
    issue(1, 1);

    for (int it = 0; it < NK; ++it) {
        const int stg = it % 3;
        if (it + 2 < NK) { CP_WAIT(1); } else { CP_WAIT(0); }
        __syncthreads();
        if (it + 2 < NK) issue(it + 2, (it + 2) % 3);
        const uint32_t base = sb + stg * GSTG;

        #pragma unroll
        for (int ks = 0; ks < 2; ++ks) {
            uint32_t wh[4][2], wl[4][2];
            #pragma unroll
            for (int nfp = 0; nfp < 2; ++nfp) {
                int ro = (wn * 32 + nfp * 16 + (lane & 15)) * GP + ks * 32 + (lane >> 4) * 16;
                uint32_t r0, r1, r2, r3;
                ldsm_x4(r0, r1, r2, r3, base + SM_WH + ro);
                wh[nfp*2][0] = r0; wh[nfp*2+1][0] = r1;
                wh[nfp*2][1] = r2; wh[nfp*2+1][1] = r3;
                ldsm_x4(r0, r1, r2, r3, base + SM_WL + ro);
                wl[nfp*2][0] = r0; wl[nfp*2+1][0] = r1;
                wl[nfp*2][1] = r2; wl[nfp*2+1][1] = r3;
            }
            #pragma unroll
            for (int mf = 0; mf < 4; ++mf) {
                int ro = (wm * 64 + mf * 16 + (lane & 15)) * GP + ks * 32 + (lane >> 4) * 16;
                uint32_t a0, a1, a2, a3;
                ldsm_x4(a0, a1, a2, a3, base + SM_A + ro);
                #pragma unroll
                for (int nf = 0; nf < 4; ++nf) {
                    mma16816(acc[mf][nf], a0, a1, a2, a3, wh[nf][0], wh[nf][1]);
                    mma16816(acc[mf][nf], a0, a1, a2, a3, wl[nf][0], wl[nf][1]);
                }
            }
        }
    }

    // epilogue
    #pragma unroll
    for (int mf = 0; mf < 4; ++mf) {
        int r0 = m0 + wm * 64 + mf * 16 + (lane >> 2);
        #pragma unroll
        for (int nf = 0; nf < 4; ++nf) {
            int c = n0 + wn * 32 + nf * 8 + (lane & 3) * 2;
            float v0 = acc[mf][nf][0], v1 = acc[mf][nf][1];
            float v2 = acc[mf][nf][2], v3 = acc[mf][nf][3];
            if (EPI == 0 || EPI == 3) {
                int hh = c >> 6, d = c & 63;
                int b0 = r0 >> 12, s0 = r0 & 4095;
                size_t o = (((size_t)(b0 * Hc + hh)) * Sc + s0) * HDc + d;
                int r1 = r0 + 8;
                int b1 = r1 >> 12, s1 = r1 & 4095;
                size_t o2 = (((size_t)(b1 * Hc + hh)) * Sc + s1) * HDc + d;
                if (EPI == 0) {
                    uint32_t ph, pl;
                    split_pair_h(v0, v1, ph, pl);
                    *(uint32_t*)(Ch + o) = ph;  *(uint32_t*)(Cl + o) = pl;
                    split_pair_h(v2, v3, ph, pl);
                    *(uint32_t*)(Ch + o2) = ph; *(uint32_t*)(Cl + o2) = pl;
                } else {
                    *(uint32_t*)(Ch + o)  = pack_hf(v0, v1);
                    *(uint32_t*)(Ch + o2) = pack_hf(v2, v3);
                }
            } else if (EPI == 1) {
                size_t o = (size_t)r0 * N + c;
                float2 rr = *(const float2*)(res + o);
                *(float2*)(Cf + o) = make_float2(v0 + rr.x, v1 + rr.y);
                o = (size_t)(r0 + 8) * N + c;
                rr = *(const float2*)(res + o);
                *(float2*)(Cf + o) = make_float2(v2 + rr.x, v3 + rr.y);
            } else {
                size_t o = (size_t)r0 * N + c;
                *(uint32_t*)(Ch + o) = pack_hf(fmaxf(v0, 0.f), fmaxf(v1, 0.f));
                o = (size_t)(r0 + 8) * N + c;
                *(uint32_t*)(Ch + o) = pack_hf(fmaxf(v2, 0.f), fmaxf(v3, 0.f));
            }
        }
    }
}

// ---------------------------------------------------------------------------
// HMMA attention (fp16): per (bh, 128-query block), 64-key tiles, 3-stage K.
// S = qh*kh + ql*kh (2 MMAs). P = exp(S/8) -> gmem fp32 + smem fp16-hi.
// ctx += P*V (1 MMA; V = K-hi via trans ldmatrix).
// ---------------------------------------------------------------------------
constexpr int AP    = 144;
constexpr int A_QH  = 0,     A_QL = 18432;
constexpr int A_K0  = 36864;                    // 3 stages x 9216
constexpr int A_PH  = 64512, A_RS = 82944;
constexpr int ATT_SMEM = A_RS + 512 + 16;       // 83472

__global__ __launch_bounds__(256, 2)
void attn_mma(float* __restrict__ attn_out)
{
    extern __shared__ __align__(16) char sm[];
    float* rsum = (float*)(sm + A_RS);
    const uint32_t sb = smem_u32(sm);
    const int tid = threadIdx.x, lane = tid & 31, wid = tid >> 5;
    const int wm = wid >> 1, wn = wid & 1;       // 4 M-warps x 2 N-warps
    const int bh = blockIdx.y, q0 = blockIdx.x * 128;
    constexpr int NKT = Sc / 64;

    const __half* Qh = g_qh + (size_t)bh * Sc * HDc;
    const __half* Ql = g_ql + (size_t)bh * Sc * HDc;
    const __half* Kh = g_kh + (size_t)bh * Sc * HDc;

    auto issueK = [&](int kt, int stg) {
        uint32_t base = sb + A_K0 + stg * 9216;
        #pragma unroll
        for (int i = 0; i < 2; ++i) {
            int c = tid + i * 256, row = c >> 3, part = c & 7;
            cp16(base + row * AP + part * 16,
                 Kh + (size_t)(kt * 64 + row) * HDc + part * 8);
        }
        CP_COMMIT();
    };

    issueK(0, 0);
    issueK(1, 1);

    // Q tile 128x64 (hi/lo), regular loads
    #pragma unroll
    for (int i = 0; i < 4; ++i) {
        int c = tid + i * 256, row = c >> 3, part = c & 7;
        size_t g = (size_t)(q0 + row) * HDc + part * 8;
        int so = row * AP + part * 16;
        *(uint4*)(sm + A_QH + so) = *(const uint4*)(Qh + g);
        *(uint4*)(sm + A_QL + so) = *(const uint4*)(Ql + g);
    }
    if (tid < 128) rsum[tid] = 0.f;

    float ctx[2][4][4];
    #pragma unroll
    for (int i = 0; i < 2; ++i)
        #pragma unroll
        for (int j = 0; j < 4; ++j)
            #pragma unroll
            for (int q = 0; q < 4; ++q) ctx[i][j][q] = 0.f;
    float rs[2][2] = {{0.f, 0.f}, {0.f, 0.f}};

    for (int kt = 0; kt < NKT; ++kt) {
        const int stg = kt % 3;
        if (kt + 2 < NKT) { CP_WAIT(1); } else { CP_WAIT(0); }
        __syncthreads();   // K[stg] ready; prev iter fully done (stage reuse, P overwrite)
        if (kt + 2 < NKT) issueK(kt + 2, (kt + 2) % 3);
        const uint32_t KB = sb + A_K0 + stg * 9216;

        // ---- S = qh*kh + ql*kh ----
        float s[2][4][4];
        #pragma unroll
        for (int i = 0; i < 2; ++i)
            #pragma unroll
            for (int j = 0; j < 4; ++j)
                #pragma unroll
                for (int q = 0; q < 4; ++q) s[i][j][q] = 0.f;

        #pragma unroll
        for (int ks = 0; ks < 4; ++ks) {
            uint32_t bhf[4][2];
            #pragma unroll
            for (int nfp = 0; nfp < 2; ++nfp) {
                int ro = (wn * 32 + nfp * 16 + (lane & 15)) * AP + ks * 32 + (lane >> 4) * 16;
                uint32_t r0, r1, r2, r3;
                ldsm_x4(r0, r1, r2, r3, KB + ro);
                bhf[nfp*2][0] = r0; bhf[nfp*2+1][0] = r1;
                bhf[nfp*2][1] = r2; bhf[nfp*2+1][1] = r3;
            }
            #pragma unroll
            for (int mf = 0; mf < 2; ++mf) {
                int ro = (wm * 32 + mf * 16 + (lane & 15)) * AP + ks * 32 + (lane >> 4) * 16;
                uint32_t a0, a1, a2, a3, l0, l1, l2, l3;
                ldsm_x4(a0, a1, a2, a3, sb + A_QH + ro);
                ldsm_x4(l0, l1, l2, l3, sb + A_QL + ro);
                #pragma unroll
                for (int nf = 0; nf < 4; ++nf) {
                    mma16816(s[mf][nf], a0, a1, a2, a3, bhf[nf][0], bhf[nf][1]);
                    mma16816(s[mf][nf], l0, l1, l2, l3, bhf[nf][0], bhf[nf][1]);
                }
            }
        }

        // ---- exp, rowsum, P stores (fp32 gmem + fp16-hi smem) ----
        #pragma unroll
        for (int mf = 0; mf < 2; ++mf) {
            int rl = wm * 32 + mf * 16 + (lane >> 2);
            #pragma unroll
            for (int nf = 0; nf < 4; ++nf) {
                int cl_ = wn * 32 + nf * 8 + (lane & 3) * 2;
                float p0 = __expf(s[mf][nf][0] * 0.125f);
                float p1 = __expf(s[mf][nf][1] * 0.125f);
                float p2 = __expf(s[mf][nf][2] * 0.125f);
                float p3 = __expf(s[mf][nf][3] * 0.125f);
                rs[mf][0] += p0 + p1;
                rs[mf][1] += p2 + p3;
                size_t gr = ((size_t)bh * Sc + q0 + rl) * Sc + kt * 64 + cl_;
                *(float2*)(attn_out + gr) = make_float2(p0, p1);
                *(float2*)(attn_out + gr + (size_t)8 * Sc) = make_float2(p2, p3);
                int so = rl * AP + cl_ * 2;
                *(uint32_t*)(sm + A_PH + so)          = pack_hf(p0, p1);
                *(uint32_t*)(sm + A_PH + so + 8 * AP) = pack_hf(p2, p3);
            }
        }
        __syncthreads();   // P visible for ldmatrix

        // ---- ctx += P V (V = K-hi via trans ldmatrix) ----
        #pragma unroll
        for (int ks = 0; ks < 4; ++ks) {
            uint32_t vh[4][2];
            #pragma unroll
            for (int nfp = 0; nfp < 2; ++nfp) {
                int ro = (ks * 16 + (lane & 15)) * AP + wn * 64 + nfp * 32 + (lane >> 4) * 16;
                uint32_t r0, r1, r2, r3;
                ldsm_x4_t(r0, r1, r2, r3, KB + ro);
                vh[nfp*2][0] = r0; vh[nfp*2][1] = r1;
                vh[nfp*2+1][0] = r2; vh[nfp*2+1][1] = r3;
            }
            #pragma unroll
            for (int mf = 0; mf < 2; ++mf) {
                int ro = (wm * 32 + mf * 16 + (lane & 15)) * AP + ks * 32 + (lane >> 4) * 16;
                uint32_t p0, p1, p2, p3;
                ldsm_x4(p0, p1, p2, p3, sb + A_PH + ro);
                #pragma unroll
                for (int nf = 0; nf < 4; ++nf)
                    mma16816(ctx[mf][nf], p0, p1, p2, p3, vh[nf][0], vh[nf][1]);
            }
        }
    }

    // ---- rowsum reduce ----
    #pragma unroll
    for (int mf = 0; mf < 2; ++mf)
        #pragma unroll
        for (int h = 0; h < 2; ++h) {
            float v = rs[mf][h];
            v += __shfl_xor_sync(0xffffffffu, v, 1);
            v += __shfl_xor_sync(0xffffffffu, v, 2);
            if ((lane & 3) == 0)
                atomicAdd(&rsum[wm * 32 + mf * 16 + h * 8 + (lane >> 2)], v);
        }
    __syncthreads();

    if (tid < 128) g_rs[(size_t)bh * Sc + q0 + tid] = rsum[tid];

    const int bb = bh >> 3, hh = bh & 7;
    #pragma unroll
    for (int mf = 0; mf < 2; ++mf) {
        int rl = wm * 32 + mf * 16 + (lane >> 2);
        float i0 = 1.f / rsum[rl];
        float i1 = 1.f / rsum[rl + 8];
        #pragma unroll
        for (int nf = 0; nf < 4; ++nf) {
            int d = wn * 32 + nf * 8 + (lane & 3) * 2;
            size_t o = ((size_t)bb * Sc + q0 + rl) * Dc + hh * HDc + d;
            *(uint32_t*)(g_ch + o) = pack_hf(ctx[mf][nf][0] * i0, ctx[mf][nf][1] * i0);
            o += (size_t)8 * Dc;
            *(uint32_t*)(g_ch + o) = pack_hf(ctx[mf][nf][2] * i1, ctx[mf][nf][3] * i1);
        }
    }
}

// ---------------------------------------------------------------------------
// attn /= rowsum
// ---------------------------------------------------------------------------
__global__ __launch_bounds__(256)
void norm_attn(float* __restrict__ attn)
{
    size_t i = (size_t)blockIdx.x * 256 + threadIdx.x;
    size_t row = (i * 4) >> 12;
    float inv = 1.0f / g_rs[row];
    float4 v = ((const float4*)attn)[i];
    v.x *= inv; v.y *= inv; v.z *= inv; v.w *= inv;
    ((float4*)attn)[i] = v;
}

// ---------------------------------------------------------------------------
// LayerNorm; optionally emits fp16-hi split
// ---------------------------------------------------------------------------
template<bool SPLIT>
__global__ __launch_bounds__(128)
void ln_kernel(const float* __restrict__ X, const float* __restrict__ gw,
               const float* __restrict__ bw, float* __restrict__ Y,
               __half* __restrict__ Yh)
{
    const int row = blockIdx.x;
    const int tid = threadIdx.x;
    float4 v = ((const float4*)(X + (size_t)row * Dc))[tid];
    float s = (v.x + v.y) + (v.z + v.w);
    float q = (v.x*v.x + v.y*v.y) + (v.z*v.z + v.w*v.w);
    #pragma unroll
    for (int o = 16; o; o >>= 1) {
        s += __shfl_xor_sync(0xffffffffu, s, o);
        q += __shfl_xor_sync(0xffffffffu, q, o);
    }
    __shared__ float ss[4], sq[4];
    if ((tid & 31) == 0) { ss[tid >> 5] = s; sq[tid >> 5] = q; }
    __syncthreads();
    s = ss[0] + ss[1] + ss[2] + ss[3];
    q = sq[0] + sq[1] + sq[2] + sq[3];
    const float mu  = s * (1.0f / Dc);
    const float var = q * (1.0f / Dc) - mu * mu;
    const float inv = rsqrtf(var + 1e-5f);
    float4 g4 = ((const float4*)gw)[tid];
    float4 b4 = ((const float4*)bw)[tid];
    float4 o4;
    o4.x = (v.x - mu) * inv * g4.x + b4.x;
    o4.y = (v.y - mu) * inv * g4.y + b4.y;
    o4.z = (v.z - mu) * inv * g4.z + b4.z;
    o4.w = (v.w - mu) * inv * g4.w + b4.w;
    ((float4*)(Y + (size_t)row * Dc))[tid] = o4;
    if (SPLIT) {
        size_t o = (size_t)row * Dc + tid * 4;
        *(uint32_t*)(Yh + o)     = pack_hf(o4.x, o4.y);
        *(uint32_t*)(Yh + o + 2) = pack_hf(o4.z, o4.w);
    }
}

// ---------------------------------------------------------------------------
extern "C" void kernel_launch(void* const* d_in, const int* in_sizes, int n_in,
                              void* d_out, int out_size)
{
    const float* x    = (const float*)d_in[0];
    const float* Wq   = (const float*)d_in[2];
    const float* Wk   = (const float*)d_in[3];
    const float* Wfc  = (const float*)d_in[5];
    const float* Wff1 = (const float*)d_in[6];
    const float* Wff2 = (const float*)d_in[7];
    const float* g1   = (const float*)d_in[8];
    const float* b1   = (const float*)d_in[9];
    const float* g2   = (const float*)d_in[10];
    const float* b2   = (const float*)d_in[11];

    float* out_feed = (float*)d_out;
    float* out_attn = (float*)d_out + (size_t)Mc * Dc;

    float *pY1, *pAtt, *pY2;
    cudaGetSymbolAddress((void**)&pY1,  g_y1);
    cudaGetSymbolAddress((void**)&pAtt, g_att);
    cudaGetSymbolAddress((void**)&pY2,  g_y2);

    __half *xh,*qh,*ql,*kh,*ch,*ah,*zh;
    __half *wqh,*wql,*wkh,*wkl,*wfh,*wfl,*w1h,*w1l,*w2h,*w2l;
    cudaGetSymbolAddress((void**)&xh,  g_xh);
    cudaGetSymbolAddress((void**)&qh,  g_qh);  cudaGetSymbolAddress((void**)&ql,  g_ql);
    cudaGetSymbolAddress((void**)&kh,  g_kh);
    cudaGetSymbolAddress((void**)&ch,  g_ch);
    cudaGetSymbolAddress((void**)&ah,  g_ah);
    cudaGetSymbolAddress((void**)&zh,  g_zh);
    cudaGetSymbolAddress((void**)&wqh, g_wqh); cudaGetSymbolAddress((void**)&wql, g_wql);
    cudaGetSymbolAddress((void**)&wkh, g_wkh); cudaGetSymbolAddress((void**)&wkl, g_wkl);
    cudaGetSymbolAddress((void**)&wfh, g_wfh); cudaGetSymbolAddress((void**)&wfl, g_wfl);
    cudaGetSymbolAddress((void**)&w1h, g_w1h); cudaGetSymbolAddress((void**)&w1l, g_w1l);
    cudaGetSymbolAddress((void**)&w2h, g_w2h); cudaGetSymbolAddress((void**)&w2l, g_w2l);

    cudaFuncSetAttribute(attn_mma,
                         cudaFuncAttributeMaxDynamicSharedMemorySize, ATT_SMEM);
    cudaFuncSetAttribute(gemm_mma<0>,
                         cudaFuncAttributeMaxDynamicSharedMemorySize, GEMM_SMEM3);
    cudaFuncSetAttribute(gemm_mma<1>,
                         cudaFuncAttributeMaxDynamicSharedMemorySize, GEMM_SMEM3);
    cudaFuncSetAttribute(gemm_mma<2>,
                         cudaFuncAttributeMaxDynamicSharedMemorySize, GEMM_SMEM3);
    cudaFuncSetAttribute(gemm_mma<3>,
                         cudaFuncAttributeMaxDynamicSharedMemorySize, GEMM_SMEM3);

    // One-time side-stream resources
    static cudaStream_t s2 = nullptr;
    static cudaEvent_t  eFork = nullptr, eJoin = nullptr, eW = nullptr;
    if (s2 == nullptr) {
        cudaStreamCreateWithFlags(&s2, cudaStreamNonBlocking);
        cudaEventCreateWithFlags(&eFork, cudaEventDisableTiming);
        cudaEventCreateWithFlags(&eJoin, cudaEventDisableTiming);
        cudaEventCreateWithFlags(&eW,    cudaEventDisableTiming);
    }

    // 0. x -> fp16 hi on main; weights -> fp16 hi/lo on side stream
    cudaEventRecord(eFork, 0);
    cudaStreamWaitEvent(s2, eFork, 0);
    cvt_hi<<<(unsigned)((size_t)Mc * Dc / 1024), 256>>>((const float4*)x, (uint2*)xh);
    auto cvtW = [&](const float* w, __half* hi, __half* lo, size_t n) {
        cvt_hilo<<<(unsigned)(n / 1024), 256, 0, s2>>>((const float4*)w,
                                                       (uint2*)hi, (uint2*)lo);
    };
    cvtW(Wq,   wqh, wql, (size_t)Dc * Dc);
    cvtW(Wk,   wkh, wkl, (size_t)Dc * Dc);
    cvtW(Wfc,  wfh, wfl, (size_t)Dc * Dc);
    cvtW(Wff1, w1h, w1l, (size_t)FFc * Dc);
    cvtW(Wff2, w2h, w2l, (size_t)Dc * FFc);
    cudaEventRecord(eW, s2);
    cudaStreamWaitEvent(0, eW, 0);

    // 1. Q (hi+lo) and K (hi) projections, permuted
    gemm_mma<0><<<dim3(Dc/128, Mc/128), 256, GEMM_SMEM3>>>(xh, wqh, wql, nullptr, nullptr, qh, ql, Dc, Dc);
    gemm_mma<3><<<dim3(Dc/128, Mc/128), 256, GEMM_SMEM3>>>(xh, wkh, wkl, nullptr, nullptr, kh, nullptr, Dc, Dc);

    // 2. Attention (unnormalized attn out + ctx fp16)
    attn_mma<<<dim3(Sc/128, BHc), 256, ATT_SMEM>>>(out_attn);

    // Fork: normalize attn on side stream, concurrent with FFN chain
    cudaEventRecord(eFork, 0);
    cudaStreamWaitEvent(s2, eFork, 0);
    {
        size_t n4 = (size_t)BHc * Sc * Sc / 4;
        norm_attn<<<(unsigned)(n4 / 256), 256, 0, s2>>>(out_attn);
    }

    // 3. y1 = x + ctx@Wfc^T ; att = LN(y1) (+ fp16)
    gemm_mma<1><<<dim3(Dc/128, Mc/128), 256, GEMM_SMEM3>>>(ch, wfh, wfl, x, pY1, nullptr, nullptr, Dc, Dc);
    ln_kernel<true><<<Mc, 128>>>(pY1, g1, b1, pAtt, ah);

    // 4. z = relu(att@Wff1^T) ; y2 = att + z@Wff2^T ; out = LN(y2)
    gemm_mma<2><<<dim3(FFc/128, Mc/128), 256, GEMM_SMEM3>>>(ah, w1h, w1l, nullptr, nullptr, zh, nullptr, FFc, Dc);
    gemm_mma<1><<<dim3(Dc/128, Mc/128), 256, GEMM_SMEM3>>>(zh, w2h, w2l, pAtt, pY2, nullptr, nullptr, Dc, FFc);
    ln_kernel<false><<<Mc, 128>>>(pY2, g2, b2, out_feed, nullptr);

    // Join: main stream waits for norm_attn
    cudaEventRecord(eJoin, s2);
    cudaStreamWaitEvent(0, eJoin, 0);
}

// round 8
// speedup vs baseline: 3.3650x; 1.0956x over previous
#include <cuda_runtime.h>
#include <cuda_fp16.h>
#include <math.h>
#include <stdint.h>

// Problem constants
constexpr int Bc  = 2;
constexpr int Sc  = 4096;
constexpr int Dc  = 512;
constexpr int Hc  = 8;
constexpr int HDc = 64;
constexpr int FFc = 2048;
constexpr int BHc = Bc * Hc;        // 16
constexpr int Mc  = Bc * Sc;        // 8192

// ---------------------------------------------------------------------------
// Scratch (device globals)
// ---------------------------------------------------------------------------
__device__ float g_rs [BHc * Sc];
__device__ float g_y1 [Mc * Dc];
__device__ float g_att[Mc * Dc];
__device__ float g_y2 [Mc * Dc];

__device__ __half g_xh [Mc * Dc];
__device__ __half g_qh [BHc * Sc * HDc];
__device__ __half g_kh [BHc * Sc * HDc];
__device__ __half g_ch [Mc * Dc];
__device__ __half g_ah [Mc * Dc];
__device__ __half g_zh [Mc * FFc];
__device__ __half g_wqh[Dc * Dc],  g_wql[Dc * Dc];
__device__ __half g_wkh[Dc * Dc],  g_wkl[Dc * Dc];
__device__ __half g_wfh[Dc * Dc],  g_wfl[Dc * Dc];
__device__ __half g_w1h[FFc * Dc], g_w1l[FFc * Dc];
__device__ __half g_w2h[Dc * FFc], g_w2l[Dc * FFc];

// ---------------------------------------------------------------------------
// Helpers
// ---------------------------------------------------------------------------
__device__ __forceinline__ uint32_t smem_u32(const void* p) {
    uint32_t a;
    asm("{ .reg .u64 t; cvta.to.shared.u64 t, %1; cvt.u32.u64 %0, t; }"
        : "=r"(a) : "l"(p));
    return a;
}
__device__ __forceinline__ void cp16(uint32_t saddr, const void* g) {
    asm volatile("cp.async.cg.shared.global [%0], [%1], 16;"
                 :: "r"(saddr), "l"(g) : "memory");
}
#define CP_COMMIT()  asm volatile("cp.async.commit_group;" ::: "memory")
#define CP_WAIT(n)   asm volatile("cp.async.wait_group %0;" :: "n"(n) : "memory")

__device__ __forceinline__ void ldsm_x4(uint32_t& r0, uint32_t& r1,
                                        uint32_t& r2, uint32_t& r3, uint32_t a) {
    asm volatile("ldmatrix.sync.aligned.m8n8.x4.shared.b16 {%0,%1,%2,%3}, [%4];"
                 : "=r"(r0), "=r"(r1), "=r"(r2), "=r"(r3) : "r"(a));
}
__device__ __forceinline__ void ldsm_x4_t(uint32_t& r0, uint32_t& r1,
                                          uint32_t& r2, uint32_t& r3, uint32_t a) {
    asm volatile("ldmatrix.sync.aligned.m8n8.x4.trans.shared.b16 {%0,%1,%2,%3}, [%4];"
                 : "=r"(r0), "=r"(r1), "=r"(r2), "=r"(r3) : "r"(a));
}

__device__ __forceinline__ void mma16816(float c[4],
        uint32_t a0, uint32_t a1, uint32_t a2, uint32_t a3,
        uint32_t b0, uint32_t b1) {
    asm volatile("mma.sync.aligned.m16n8k16.row.col.f32.f16.f16.f32 "
                 "{%0,%1,%2,%3}, {%4,%5,%6,%7}, {%8,%9}, {%0,%1,%2,%3};"
                 : "+f"(c[0]), "+f"(c[1]), "+f"(c[2]), "+f"(c[3])
                 : "r"(a0), "r"(a1), "r"(a2), "r"(a3), "r"(b0), "r"(b1));
}

__device__ __forceinline__ uint32_t pack_h(__half a, __half b) {
    return ((uint32_t)__half_as_ushort(b) << 16) | (uint32_t)__half_as_ushort(a);
}
__device__ __forceinline__ uint32_t pack_hf(float x, float y) {
    return pack_h(__float2half_rn(x), __float2half_rn(y));
}
__device__ __forceinline__ void split_pair_h(float x, float y,
                                             uint32_t& h, uint32_t& l) {
    __half hx = __float2half_rn(x), hy = __float2half_rn(y);
    h = pack_h(hx, hy);
    l = pack_h(__float2half_rn(x - __half2float(hx)),
               __float2half_rn(y - __half2float(hy)));
}

// ---------------------------------------------------------------------------
// fp32 -> fp16 conversions
// ---------------------------------------------------------------------------
__global__ __launch_bounds__(256)
void cvt_hilo(const float4* __restrict__ in, uint2* __restrict__ hi,
              uint2* __restrict__ lo)
{
    size_t i = (size_t)blockIdx.x * 256 + threadIdx.x;
    float4 v = in[i];
    uint32_t h0, l0, h1, l1;
    split_pair_h(v.x, v.y, h0, l0);
    split_pair_h(v.z, v.w, h1, l1);
    hi[i] = make_uint2(h0, h1);
    lo[i] = make_uint2(l0, l1);
}
__global__ __launch_bounds__(256)
void cvt_hi(const float4* __restrict__ in, uint2* __restrict__ hi)
{
    size_t i = (size_t)blockIdx.x * 256 + threadIdx.x;
    float4 v = in[i];
    hi[i] = make_uint2(pack_hf(v.x, v.y), pack_hf(v.z, v.w));
}

// ---------------------------------------------------------------------------
// HMMA GEMM (fp16 x2: A-hi * (W-hi + W-lo)), 3-stage cp.async.
// C[M,N] = A[M,K] @ W[N,K]^T. CTA 128x128, BK=32, 256 thr, 8 warps (2Mx4N).
// EPI 3: permuted fp16-hi store (Q/K) ; 1: fp32+residual ; 2: relu+fp16-hi
// ---------------------------------------------------------------------------
constexpr int GP = 80;
constexpr int SM_A = 0, SM_WH = 10240, SM_WL = 20480;
constexpr int GSTG = 30720;
constexpr int GEMM_SMEM3 = 3 * GSTG;           // 92160

template<int EPI>
__global__ __launch_bounds__(256, 2)
void gemm_mma(const __half* __restrict__ Ah,
              const __half* __restrict__ Wh, const __half* __restrict__ Wl,
              const float* __restrict__ res, float* __restrict__ Cf,
              __half* __restrict__ Ch,
              int N, int K)
{
    extern __shared__ __align__(16) char smd[];
    const uint32_t sb = smem_u32(smd);
    const int tid = threadIdx.x, lane = tid & 31, wid = tid >> 5;
    const int wm = wid >> 2, wn = wid & 3;
    const int m0 = blockIdx.y * 128, n0 = blockIdx.x * 128;
    const int NK = K >> 5;

    float acc[4][4][4];
    #pragma unroll
    for (int i = 0; i < 4; ++i)
        #pragma unroll
        for (int j = 0; j < 4; ++j)
            #pragma unroll
            for (int q = 0; q < 4; ++q) acc[i][j][q] = 0.f;

    auto issue = [&](int it, int stg) {
        uint32_t base = sb + stg * GSTG;
        #pragma unroll
        for (int i = 0; i < 2; ++i) {
            int c = tid + i * 256, row = c >> 2, part = c & 3;
            int so = row * GP + part * 16;
            size_t ga = (size_t)(m0 + row) * K + it * 32 + part * 8;
            size_t gw = (size_t)(n0 + row) * K + it * 32 + part * 8;
            cp16(base + SM_A  + so, Ah + ga);
            cp16(base + SM_WH + so, Wh + gw);
            cp16(base + SM_WL + so, Wl + gw);
        }
        CP_COMMIT();
    };

    issue(0, 0);
    issue(1, 1);

    for (int it = 0; it < NK; ++it) {
        const int stg = it % 3;
        if (it + 2 < NK) { CP_WAIT(1); } else { CP_WAIT(0); }
        __syncthreads();
        if (it + 2 < NK) issue(it + 2, (it + 2) % 3);
        const uint32_t base = sb + stg * GSTG;

        #pragma unroll
        for (int ks = 0; ks < 2; ++ks) {
            uint32_t wh[4][2], wl[4][2];
            #pragma unroll
            for (int nfp = 0; nfp < 2; ++nfp) {
                int ro = (wn * 32 + nfp * 16 + (lane & 15)) * GP + ks * 32 + (lane >> 4) * 16;
                uint32_t r0, r1, r2, r3;
                ldsm_x4(r0, r1, r2, r3, base + SM_WH + ro);
                wh[nfp*2][0] = r0; wh[nfp*2+1][0] = r1;
                wh[nfp*2][1] = r2; wh[nfp*2+1][1] = r3;
                ldsm_x4(r0, r1, r2, r3, base + SM_WL + ro);
                wl[nfp*2][0] = r0; wl[nfp*2+1][0] = r1;
                wl[nfp*2][1] = r2; wl[nfp*2+1][1] = r3;
            }
            #pragma unroll
            for (int mf = 0; mf < 4; ++mf) {
                int ro = (wm * 64 + mf * 16 + (lane & 15)) * GP + ks * 32 + (lane >> 4) * 16;
                uint32_t a0, a1, a2, a3;
                ldsm_x4(a0, a1, a2, a3, base + SM_A + ro);
                #pragma unroll
                for (int nf = 0; nf < 4; ++nf) {
                    mma16816(acc[mf][nf], a0, a1, a2, a3, wh[nf][0], wh[nf][1]);
                    mma16816(acc[mf][nf], a0, a1, a2, a3, wl[nf][0], wl[nf][1]);
                }
            }
        }
    }

    // epilogue
    #pragma unroll
    for (int mf = 0; mf < 4; ++mf) {
        int r0 = m0 + wm * 64 + mf * 16 + (lane >> 2);
        #pragma unroll
        for (int nf = 0; nf < 4; ++nf) {
            int c = n0 + wn * 32 + nf * 8 + (lane & 3) * 2;
            float v0 = acc[mf][nf][0], v1 = acc[mf][nf][1];
            float v2 = acc[mf][nf][2], v3 = acc[mf][nf][3];
            if (EPI == 3) {
                int hh = c >> 6, d = c & 63;
                int b0 = r0 >> 12, s0 = r0 & 4095;
                size_t o = (((size_t)(b0 * Hc + hh)) * Sc + s0) * HDc + d;
                int r1 = r0 + 8;
                int b1 = r1 >> 12, s1 = r1 & 4095;
                size_t o2 = (((size_t)(b1 * Hc + hh)) * Sc + s1) * HDc + d;
                *(uint32_t*)(Ch + o)  = pack_hf(v0, v1);
                *(uint32_t*)(Ch + o2) = pack_hf(v2, v3);
            } else if (EPI == 1) {
                size_t o = (size_t)r0 * N + c;
                float2 rr = *(const float2*)(res + o);
                *(float2*)(Cf + o) = make_float2(v0 + rr.x, v1 + rr.y);
                o = (size_t)(r0 + 8) * N + c;
                rr = *(const float2*)(res + o);
                *(float2*)(Cf + o) = make_float2(v2 + rr.x, v3 + rr.y);
            } else {
                size_t o = (size_t)r0 * N + c;
                *(uint32_t*)(Ch + o) = pack_hf(fmaxf(v0, 0.f), fmaxf(v1, 0.f));
                o = (size_t)(r0 + 8) * N + c;
                *(uint32_t*)(Ch + o) = pack_hf(fmaxf(v2, 0.f), fmaxf(v3, 0.f));
            }
        }
    }
}

// ---------------------------------------------------------------------------
// HMMA attention (fp16 x1): per (bh, 128-query block), 64-key tiles, 3-stage K.
// S = qh*kh (1 MMA). P = exp(S/8) -> gmem fp32 + smem fp16.
// ctx += P*V (1 MMA; V = K via trans ldmatrix).
// ---------------------------------------------------------------------------
constexpr int AP    = 144;
constexpr int A_QH  = 0;
constexpr int A_K0  = 18432;                    // 3 stages x 9216
constexpr int A_PH  = 46080, A_RS = 64512;
constexpr int ATT_SMEM = A_RS + 512 + 16;       // 65040

__global__ __launch_bounds__(256, 2)
void attn_mma(float* __restrict__ attn_out)
{
    extern __shared__ __align__(16) char sm[];
    float* rsum = (float*)(sm + A_RS);
    const uint32_t sb = smem_u32(sm);
    const int tid = threadIdx.x, lane = tid & 31, wid = tid >> 5;
    const int wm = wid >> 1, wn = wid & 1;       // 4 M-warps x 2 N-warps
    const int bh = blockIdx.y, q0 = blockIdx.x * 128;
    constexpr int NKT = Sc / 64;

    const __half* Qh = g_qh + (size_t)bh * Sc * HDc;
    const __half* Kh = g_kh + (size_t)bh * Sc * HDc;

    auto issueK = [&](int kt, int stg) {
        uint32_t base = sb + A_K0 + stg * 9216;
        #pragma unroll
        for (int i = 0; i < 2; ++i) {
            int c = tid + i * 256, row = c >> 3, part = c & 7;
            cp16(base + row * AP + part * 16,
                 Kh + (size_t)(kt * 64 + row) * HDc + part * 8);
        }
        CP_COMMIT();
    };

    issueK(0, 0);
    issueK(1, 1);

    // Q tile 128x64 fp16 = 1024 16B-chunks (4 iterations x 256 threads)
    #pragma unroll
    for (int i = 0; i < 4; ++i) {
        int c = tid + i * 256, row = c >> 3, part = c & 7;
        size_t g = (size_t)(q0 + row) * HDc + part * 8;
        *(uint4*)(sm + A_QH + row * AP + part * 16) = *(const uint4*)(Qh + g);
    }
    if (tid < 128) rsum[tid] = 0.f;

    float ctx[2][4][4];
    #pragma unroll
    for (int i = 0; i < 2; ++i)
        #pragma unroll
        for (int j = 0; j < 4; ++j)
            #pragma unroll
            for (int q = 0; q < 4; ++q) ctx[i][j][q] = 0.f;
    float rs[2][2] = {{0.f, 0.f}, {0.f, 0.f}};

    for (int kt = 0; kt < NKT; ++kt) {
        const int stg = kt % 3;
        if (kt + 2 < NKT) { CP_WAIT(1); } else { CP_WAIT(0); }
        __syncthreads();   // K[stg] ready; prev iter fully done
        if (kt + 2 < NKT) issueK(kt + 2, (kt + 2) % 3);
        const uint32_t KB = sb + A_K0 + stg * 9216;

        // ---- S = qh*kh ----
        float s[2][4][4];
        #pragma unroll
        for (int i = 0; i < 2; ++i)
            #pragma unroll
            for (int j = 0; j < 4; ++j)
                #pragma unroll
                for (int q = 0; q < 4; ++q) s[i][j][q] = 0.f;

        #pragma unroll
        for (int ks = 0; ks < 4; ++ks) {
            uint32_t bhf[4][2];
            #pragma unroll
            for (int nfp = 0; nfp < 2; ++nfp) {
                int ro = (wn * 32 + nfp * 16 + (lane & 15)) * AP + ks * 32 + (lane >> 4) * 16;
                uint32_t r0, r1, r2, r3;
                ldsm_x4(r0, r1, r2, r3, KB + ro);
                bhf[nfp*2][0] = r0; bhf[nfp*2+1][0] = r1;
                bhf[nfp*2][1] = r2; bhf[nfp*2+1][1] = r3;
            }
            #pragma unroll
            for (int mf = 0; mf < 2; ++mf) {
                int ro = (wm * 32 + mf * 16 + (lane & 15)) * AP + ks * 32 + (lane >> 4) * 16;
                uint32_t a0, a1, a2, a3;
                ldsm_x4(a0, a1, a2, a3, sb + A_QH + ro);
                #pragma unroll
                for (int nf = 0; nf < 4; ++nf)
                    mma16816(s[mf][nf], a0, a1, a2, a3, bhf[nf][0], bhf[nf][1]);
            }
        }

        // ---- exp, rowsum, P stores (fp32 gmem + fp16 smem) ----
        #pragma unroll
        for (int mf = 0; mf < 2; ++mf) {
            int rl = wm * 32 + mf * 16 + (lane >> 2);
            #pragma unroll
            for (int nf = 0; nf < 4; ++nf) {
                int cl_ = wn * 32 + nf * 8 + (lane & 3) * 2;
                float p0 = __expf(s[mf][nf][0] * 0.125f);
                float p1 = __expf(s[mf][nf][1] * 0.125f);
                float p2 = __expf(s[mf][nf][2] * 0.125f);
                float p3 = __expf(s[mf][nf][3] * 0.125f);
                rs[mf][0] += p0 + p1;
                rs[mf][1] += p2 + p3;
                size_t gr = ((size_t)bh * Sc + q0 + rl) * Sc + kt * 64 + cl_;
                *(float2*)(attn_out + gr) = make_float2(p0, p1);
                *(float2*)(attn_out + gr + (size_t)8 * Sc) = make_float2(p2, p3);
                int so = rl * AP + cl_ * 2;
                *(uint32_t*)(sm + A_PH + so)          = pack_hf(p0, p1);
                *(uint32_t*)(sm + A_PH + so + 8 * AP) = pack_hf(p2, p3);
            }
        }
        __syncthreads();   // P visible for ldmatrix

        // ---- ctx += P V (V = K via trans ldmatrix) ----
        #pragma unroll
        for (int ks = 0; ks < 4; ++ks) {
            uint32_t vh[4][2];
            #pragma unroll
            for (int nfp = 0; nfp < 2; ++nfp) {
                int ro = (ks * 16 + (lane & 15)) * AP + wn * 64 + nfp * 32 + (lane >> 4) * 16;
                uint32_t r0, r1, r2, r3;
                ldsm_x4_t(r0, r1, r2, r3, KB + ro);
                vh[nfp*2][0] = r0; vh[nfp*2][1] = r1;
                vh[nfp*2+1][0] = r2; vh[nfp*2+1][1] = r3;
            }
            #pragma unroll
            for (int mf = 0; mf < 2; ++mf) {
                int ro = (wm * 32 + mf * 16 + (lane & 15)) * AP + ks * 32 + (lane >> 4) * 16;
                uint32_t p0, p1, p2, p3;
                ldsm_x4(p0, p1, p2, p3, sb + A_PH + ro);
                #pragma unroll
                for (int nf = 0; nf < 4; ++nf)
                    mma16816(ctx[mf][nf], p0, p1, p2, p3, vh[nf][0], vh[nf][1]);
            }
        }
    }

    // ---- rowsum reduce ----
    #pragma unroll
    for (int mf = 0; mf < 2; ++mf)
        #pragma unroll
        for (int h = 0; h < 2; ++h) {
            float v = rs[mf][h];
            v += __shfl_xor_sync(0xffffffffu, v, 1);
            v += __shfl_xor_sync(0xffffffffu, v, 2);
            if ((lane & 3) == 0)
                atomicAdd(&rsum[wm * 32 + mf * 16 + h * 8 + (lane >> 2)], v);
        }
    __syncthreads();

    if (tid < 128) g_rs[(size_t)bh * Sc + q0 + tid] = rsum[tid];

    const int bb = bh >> 3, hh = bh & 7;
    #pragma unroll
    for (int mf = 0; mf < 2; ++mf) {
        int rl = wm * 32 + mf * 16 + (lane >> 2);
        float i0 = 1.f / rsum[rl];
        float i1 = 1.f / rsum[rl + 8];
        #pragma unroll
        for (int nf = 0; nf < 4; ++nf) {
            int d = wn * 32 + nf * 8 + (lane & 3) * 2;
            size_t o = ((size_t)bb * Sc + q0 + rl) * Dc + hh * HDc + d;
            *(uint32_t*)(g_ch + o) = pack_hf(ctx[mf][nf][0] * i0, ctx[mf][nf][1] * i0);
            o += (size_t)8 * Dc;
            *(uint32_t*)(g_ch + o) = pack_hf(ctx[mf][nf][2] * i1, ctx[mf][nf][3] * i1);
        }
    }
}

// ---------------------------------------------------------------------------
// attn /= rowsum
// ---------------------------------------------------------------------------
__global__ __launch_bounds__(256)
void norm_attn(float* __restrict__ attn)
{
    size_t i = (size_t)blockIdx.x * 256 + threadIdx.x;
    size_t row = (i * 4) >> 12;
    float inv = 1.0f / g_rs[row];
    float4 v = ((const float4*)attn)[i];
    v.x *= inv; v.y *= inv; v.z *= inv; v.w *= inv;
    ((float4*)attn)[i] = v;
}

// ---------------------------------------------------------------------------
// LayerNorm; optionally emits fp16 copy
// ---------------------------------------------------------------------------
template<bool SPLIT>
__global__ __launch_bounds__(128)
void ln_kernel(const float* __restrict__ X, const float* __restrict__ gw,
               const float* __restrict__ bw, float* __restrict__ Y,
               __half* __restrict__ Yh)
{
    const int row = blockIdx.x;
    const int tid = threadIdx.x;
    float4 v = ((const float4*)(X + (size_t)row * Dc))[tid];
    float s = (v.x + v.y) + (v.z + v.w);
    float q = (v.x*v.x + v.y*v.y) + (v.z*v.z + v.w*v.w);
    #pragma unroll
    for (int o = 16; o; o >>= 1) {
        s += __shfl_xor_sync(0xffffffffu, s, o);
        q += __shfl_xor_sync(0xffffffffu, q, o);
    }
    __shared__ float ss[4], sq[4];
    if ((tid & 31) == 0) { ss[tid >> 5] = s; sq[tid >> 5] = q; }
    __syncthreads();
    s = ss[0] + ss[1] + ss[2] + ss[3];
    q = sq[0] + sq[1] + sq[2] + sq[3];
    const float mu  = s * (1.0f / Dc);
    const float var = q * (1.0f / Dc) - mu * mu;
    const float inv = rsqrtf(var + 1e-5f);
    float4 g4 = ((const float4*)gw)[tid];
    float4 b4 = ((const float4*)bw)[tid];
    float4 o4;
    o4.x = (v.x - mu) * inv * g4.x + b4.x;
    o4.y = (v.y - mu) * inv * g4.y + b4.y;
    o4.z = (v.z - mu) * inv * g4.z + b4.z;
    o4.w = (v.w - mu) * inv * g4.w + b4.w;
    ((float4*)(Y + (size_t)row * Dc))[tid] = o4;
    if (SPLIT) {
        size_t o = (size_t)row * Dc + tid * 4;
        *(uint32_t*)(Yh + o)     = pack_hf(o4.x, o4.y);
        *(uint32_t*)(Yh + o + 2) = pack_hf(o4.z, o4.w);
    }
}

// ---------------------------------------------------------------------------
extern "C" void kernel_launch(void* const* d_in, const int* in_sizes, int n_in,
                              void* d_out, int out_size)
{
    const float* x    = (const float*)d_in[0];
    const float* Wq   = (const float*)d_in[2];
    const float* Wk   = (const float*)d_in[3];
    const float* Wfc  = (const float*)d_in[5];
    const float* Wff1 = (const float*)d_in[6];
    const float* Wff2 = (const float*)d_in[7];
    const float* g1   = (const float*)d_in[8];
    const float* b1   = (const float*)d_in[9];
    const float* g2   = (const float*)d_in[10];
    const float* b2   = (const float*)d_in[11];

    float* out_feed = (float*)d_out;
    float* out_attn = (float*)d_out + (size_t)Mc * Dc;

    float *pY1, *pAtt, *pY2;
    cudaGetSymbolAddress((void**)&pY1,  g_y1);
    cudaGetSymbolAddress((void**)&pAtt, g_att);
    cudaGetSymbolAddress((void**)&pY2,  g_y2);

    __half *xh,*qh,*kh,*ch,*ah,*zh;
    __half *wqh,*wql,*wkh,*wkl,*wfh,*wfl,*w1h,*w1l,*w2h,*w2l;
    cudaGetSymbolAddress((void**)&xh,  g_xh);
    cudaGetSymbolAddress((void**)&qh,  g_qh);
    cudaGetSymbolAddress((void**)&kh,  g_kh);
    cudaGetSymbolAddress((void**)&ch,  g_ch);
    cudaGetSymbolAddress((void**)&ah,  g_ah);
    cudaGetSymbolAddress((void**)&zh,  g_zh);
    cudaGetSymbolAddress((void**)&wqh, g_wqh); cudaGetSymbolAddress((void**)&wql, g_wql);
    cudaGetSymbolAddress((void**)&wkh, g_wkh); cudaGetSymbolAddress((void**)&wkl, g_wkl);
    cudaGetSymbolAddress((void**)&wfh, g_wfh); cudaGetSymbolAddress((void**)&wfl, g_wfl);
    cudaGetSymbolAddress((void**)&w1h, g_w1h); cudaGetSymbolAddress((void**)&w1l, g_w1l);
    cudaGetSymbolAddress((void**)&w2h, g_w2h); cudaGetSymbolAddress((void**)&w2l, g_w2l);

    cudaFuncSetAttribute(attn_mma,
                         cudaFuncAttributeMaxDynamicSharedMemorySize, ATT_SMEM);
    cudaFuncSetAttribute(gemm_mma<1>,
                         cudaFuncAttributeMaxDynamicSharedMemorySize, GEMM_SMEM3);
    cudaFuncSetAttribute(gemm_mma<2>,
                         cudaFuncAttributeMaxDynamicSharedMemorySize, GEMM_SMEM3);
    cudaFuncSetAttribute(gemm_mma<3>,
                         cudaFuncAttributeMaxDynamicSharedMemorySize, GEMM_SMEM3);

    // One-time side-stream resources
    static cudaStream_t s2 = nullptr;
    static cudaEvent_t  eFork = nullptr, eJoin = nullptr, eW = nullptr;
    static cudaEvent_t  eX = nullptr, eK = nullptr;
    if (s2 == nullptr) {
        cudaStreamCreateWithFlags(&s2, cudaStreamNonBlocking);
        cudaEventCreateWithFlags(&eFork, cudaEventDisableTiming);
        cudaEventCreateWithFlags(&eJoin, cudaEventDisableTiming);
        cudaEventCreateWithFlags(&eW,    cudaEventDisableTiming);
        cudaEventCreateWithFlags(&eX,    cudaEventDisableTiming);
        cudaEventCreateWithFlags(&eK,    cudaEventDisableTiming);
    }

    // 0. x -> fp16 on main; weights -> fp16 hi/lo on side stream
    cudaEventRecord(eFork, 0);
    cudaStreamWaitEvent(s2, eFork, 0);
    cvt_hi<<<(unsigned)((size_t)Mc * Dc / 1024), 256>>>((const float4*)x, (uint2*)xh);
    cudaEventRecord(eX, 0);
    auto cvtW = [&](const float* w, __half* hi, __half* lo, size_t n) {
        cvt_hilo<<<(unsigned)(n / 1024), 256, 0, s2>>>((const float4*)w,
                                                       (uint2*)hi, (uint2*)lo);
    };
    cvtW(Wq,   wqh, wql, (size_t)Dc * Dc);
    cvtW(Wk,   wkh, wkl, (size_t)Dc * Dc);
    cvtW(Wfc,  wfh, wfl, (size_t)Dc * Dc);
    cvtW(Wff1, w1h, w1l, (size_t)FFc * Dc);
    cvtW(Wff2, w2h, w2l, (size_t)Dc * FFc);
    cudaEventRecord(eW, s2);
    cudaStreamWaitEvent(0, eW, 0);      // main needs weights for Q proj
    cudaStreamWaitEvent(s2, eX, 0);     // s2 needs xh for K proj

    // 1. Q proj on main || K proj on s2 (both permuted fp16)
    gemm_mma<3><<<dim3(Dc/128, Mc/128), 256, GEMM_SMEM3>>>(xh, wqh, wql, nullptr, nullptr, qh, Dc, Dc);
    gemm_mma<3><<<dim3(Dc/128, Mc/128), 256, GEMM_SMEM3, s2>>>(xh, wkh, wkl, nullptr, nullptr, kh, Dc, Dc);
    cudaEventRecord(eK, s2);
    cudaStreamWaitEvent(0, eK, 0);

    // 2. Attention (unnormalized attn out + ctx fp16)
    attn_mma<<<dim3(Sc/128, BHc), 256, ATT_SMEM>>>(out_attn);

    // Fork: normalize attn on side stream, concurrent with FFN chain
    cudaEventRecord(eFork, 0);
    cudaStreamWaitEvent(s2, eFork, 0);
    {
        size_t n4 = (size_t)BHc * Sc * Sc / 4;
        norm_attn<<<(unsigned)(n4 / 256), 256, 0, s2>>>(out_attn);
    }

    // 3. y1 = x + ctx@Wfc^T ; att = LN(y1) (+ fp16)
    gemm_mma<1><<<dim3(Dc/128, Mc/128), 256, GEMM_SMEM3>>>(ch, wfh, wfl, x, pY1, nullptr, Dc, Dc);
    ln_kernel<true><<<Mc, 128>>>(pY1, g1, b1, pAtt, ah);

    // 4. z = relu(att@Wff1^T) ; y2 = att + z@Wff2^T ; out = LN(y2)
    gemm_mma<2><<<dim3(FFc/128, Mc/128), 256, GEMM_SMEM3>>>(ah, w1h, w1l, nullptr, nullptr, zh, FFc, Dc);
    gemm_mma<1><<<dim3(Dc/128, Mc/128), 256, GEMM_SMEM3>>>(zh, w2h, w2l, pAtt, pY2, nullptr, Dc, FFc);
    ln_kernel<false><<<Mc, 128>>>(pY2, g2, b2, out_feed, nullptr);

    // Join: main stream waits for norm_attn
    cudaEventRecord(eJoin, s2);
    cudaStreamWaitEvent(0, eJoin, 0);
}

// round 9
// speedup vs baseline: 3.5183x; 1.0456x over previous
#include <cuda_runtime.h>
#include <cuda_fp16.h>
#include <math.h>
#include <stdint.h>

// Problem constants
constexpr int Bc  = 2;
constexpr int Sc  = 4096;
constexpr int Dc  = 512;
constexpr int Hc  = 8;
constexpr int HDc = 64;
constexpr int FFc = 2048;
constexpr int BHc = Bc * Hc;        // 16
constexpr int Mc  = Bc * Sc;        // 8192

// ---------------------------------------------------------------------------
// Scratch (device globals)
// ---------------------------------------------------------------------------
__device__ float g_rs [BHc * Sc];
__device__ float g_y1 [Mc * Dc];
__device__ float g_att[Mc * Dc];
__device__ float g_y2 [Mc * Dc];

__device__ __half g_p  [(size_t)BHc * Sc * Sc];   // unnormalized P, fp16 (536MB)

__device__ __half g_xh [Mc * Dc];
__device__ __half g_qh [BHc * Sc * HDc];
__device__ __half g_kh [BHc * Sc * HDc];
__device__ __half g_ch [Mc * Dc];
__device__ __half g_ah [Mc * Dc];
__device__ __half g_zh [Mc * FFc];
__device__ __half g_wqh[Dc * Dc],  g_wql[Dc * Dc];
__device__ __half g_wkh[Dc * Dc],  g_wkl[Dc * Dc];
__device__ __half g_wfh[Dc * Dc],  g_wfl[Dc * Dc];
__device__ __half g_w1h[FFc * Dc], g_w1l[FFc * Dc];
__device__ __half g_w2h[Dc * FFc], g_w2l[Dc * FFc];

// ---------------------------------------------------------------------------
// Helpers
// ---------------------------------------------------------------------------
__device__ __forceinline__ uint32_t smem_u32(const void* p) {
    uint32_t a;
    asm("{ .reg .u64 t; cvta.to.shared.u64 t, %1; cvt.u32.u64 %0, t; }"
        : "=r"(a) : "l"(p));
    return a;
}
__device__ __forceinline__ void cp16(uint32_t saddr, const void* g) {
    asm volatile("cp.async.cg.shared.global [%0], [%1], 16;"
                 :: "r"(saddr), "l"(g) : "memory");
}
#define CP_COMMIT()  asm volatile("cp.async.commit_group;" ::: "memory")
#define CP_WAIT(n)   asm volatile("cp.async.wait_group %0;" :: "n"(n) : "memory")

__device__ __forceinline__ void ldsm_x4(uint32_t& r0, uint32_t& r1,
                                        uint32_t& r2, uint32_t& r3, uint32_t a) {
    asm volatile("ldmatrix.sync.aligned.m8n8.x4.shared.b16 {%0,%1,%2,%3}, [%4];"
                 : "=r"(r0), "=r"(r1), "=r"(r2), "=r"(r3) : "r"(a));
}
__device__ __forceinline__ void ldsm_x4_t(uint32_t& r0, uint32_t& r1,
                                          uint32_t& r2, uint32_t& r3, uint32_t a) {
    asm volatile("ldmatrix.sync.aligned.m8n8.x4.trans.shared.b16 {%0,%1,%2,%3}, [%4];"
                 : "=r"(r0), "=r"(r1), "=r"(r2), "=r"(r3) : "r"(a));
}

__device__ __forceinline__ void mma16816(float c[4],
        uint32_t a0, uint32_t a1, uint32_t a2, uint32_t a3,
        uint32_t b0, uint32_t b1) {
    asm volatile("mma.sync.aligned.m16n8k16.row.col.f32.f16.f16.f32 "
                 "{%0,%1,%2,%3}, {%4,%5,%6,%7}, {%8,%9}, {%0,%1,%2,%3};"
                 : "+f"(c[0]), "+f"(c[1]), "+f"(c[2]), "+f"(c[3])
                 : "r"(a0), "r"(a1), "r"(a2), "r"(a3), "r"(b0), "r"(b1));
}

__device__ __forceinline__ uint32_t pack_h(__half a, __half b) {
    return ((uint32_t)__half_as_ushort(b) << 16) | (uint32_t)__half_as_ushort(a);
}
__device__ __forceinline__ uint32_t pack_hf(float x, float y) {
    return pack_h(__float2half_rn(x), __float2half_rn(y));
}
__device__ __forceinline__ void split_pair_h(float x, float y,
                                             uint32_t& h, uint32_t& l) {
    __half hx = __float2half_rn(x), hy = __float2half_rn(y);
    h = pack_h(hx, hy);
    l = pack_h(__float2half_rn(x - __half2float(hx)),
               __float2half_rn(y - __half2float(hy)));
}

// ---------------------------------------------------------------------------
// fp32 -> fp16 conversions
// ---------------------------------------------------------------------------
__global__ __launch_bounds__(256)
void cvt_hilo(const float4* __restrict__ in, uint2* __restrict__ hi,
              uint2* __restrict__ lo)
{
    size_t i = (size_t)blockIdx.x * 256 + threadIdx.x;
    float4 v = in[i];
    uint32_t h0, l0, h1, l1;
    split_pair_h(v.x, v.y, h0, l0);
    split_pair_h(v.z, v.w, h1, l1);
    hi[i] = make_uint2(h0, h1);
    lo[i] = make_uint2(l0, l1);
}
__global__ __launch_bounds__(256)
void cvt_hi(const float4* __restrict__ in, uint2* __restrict__ hi)
{
    size_t i = (size_t)blockIdx.x * 256 + threadIdx.x;
    float4 v = in[i];
    hi[i] = make_uint2(pack_hf(v.x, v.y), pack_hf(v.z, v.w));
}

// ---------------------------------------------------------------------------
// HMMA GEMM (fp16 x2: A-hi * (W-hi + W-lo)), 3-stage cp.async.
// C[M,N] = A[M,K] @ W[N,K]^T. CTA 128x128, BK=32, 256 thr, 8 warps (2Mx4N).
// EPI 3: permuted fp16 store (Q/K) ; 1: fp32+residual ; 2: relu+fp16
// ---------------------------------------------------------------------------
constexpr int GP = 80;
constexpr int SM_A = 0, SM_WH = 10240, SM_WL = 20480;
constexpr int GSTG = 30720;
constexpr int GEMM_SMEM3 = 3 * GSTG;           // 92160

template<int EPI>
__global__ __launch_bounds__(256, 2)
void gemm_mma(const __half* __restrict__ Ah,
              const __half* __restrict__ Wh, const __half* __restrict__ Wl,
              const float* __restrict__ res, float* __restrict__ Cf,
              __half* __restrict__ Ch,
              int N, int K)
{
    extern __shared__ __align__(16) char smd[];
    const uint32_t sb = smem_u32(smd);
    const int tid = threadIdx.x, lane = tid & 31, wid = tid >> 5;
    const int wm = wid >> 2, wn = wid & 3;
    const int m0 = blockIdx.y * 128, n0 = blockIdx.x * 128;
    const int NK = K >> 5;

    float acc[4][4][4];
    #pragma unroll
    for (int i = 0; i < 4; ++i)
        #pragma unroll
        for (int j = 0; j < 4; ++j)
            #pragma unroll
            for (int q = 0; q < 4; ++q) acc[i][j][q] = 0.f;

    auto issue = [&](int it, int stg) {
        uint32_t base = sb + stg * GSTG;
        #pragma unroll
        for (int i = 0; i < 2; ++i) {
            int c = tid + i * 256, row = c >> 2, part = c & 3;
            int so = row * GP + part * 16;
            size_t ga = (size_t)(m0 + row) * K + it * 32 + part * 8;
            size_t gw = (size_t)(n0 + row) * K + it * 32 + part * 8;
            cp16(base + SM_A  + so, Ah + ga);
            cp16(base + SM_WH + so, Wh + gw);
            cp16(base + SM_WL + so, Wl + gw);
        }
        CP_COMMIT();
    };

    issue(0, 0);
    issue(1, 1);

    for (int it = 0; it < NK; ++it) {
        const int stg = it % 3;
        if (it + 2 < NK) { CP_WAIT(1); } else { CP_WAIT(0); }
        __syncthreads();
        if (it + 2 < NK) issue(it + 2, (it + 2) % 3);
        const uint32_t base = sb + stg * GSTG;

        #pragma unroll
        for (int ks = 0; ks < 2; ++ks) {
            uint32_t wh[4][2], wl[4][2];
            #pragma unroll
            for (int nfp = 0; nfp < 2; ++nfp) {
                int ro = (wn * 32 + nfp * 16 + (lane & 15)) * GP + ks * 32 + (lane >> 4) * 16;
                uint32_t r0, r1, r2, r3;
                ldsm_x4(r0, r1, r2, r3, base + SM_WH + ro);
                wh[nfp*2][0] = r0; wh[nfp*2+1][0] = r1;
                wh[nfp*2][1] = r2; wh[nfp*2+1][1] = r3;
                ldsm_x4(r0, r1, r2, r3, base + SM_WL + ro);
                wl[nfp*2][0] = r0; wl[nfp*2+1][0] = r1;
                wl[nfp*2][1] = r2; wl[nfp*2+1][1] = r3;
            }
            #pragma unroll
            for (int mf = 0; mf < 4; ++mf) {
                int ro = (wm * 64 + mf * 16 + (lane & 15)) * GP + ks * 32 + (lane >> 4) * 16;
                uint32_t a0, a1, a2, a3;
                ldsm_x4(a0, a1, a2, a3, base + SM_A + ro);
                #pragma unroll
                for (int nf = 0; nf < 4; ++nf) {
                    mma16816(acc[mf][nf], a0, a1, a2, a3, wh[nf][0], wh[nf][1]);
                    mma16816(acc[mf][nf], a0, a1, a2, a3, wl[nf][0], wl[nf][1]);
                }
            }
        }
    }

    // epilogue
    #pragma unroll
    for (int mf = 0; mf < 4; ++mf) {
        int r0 = m0 + wm * 64 + mf * 16 + (lane >> 2);
        #pragma unroll
        for (int nf = 0; nf < 4; ++nf) {
            int c = n0 + wn * 32 + nf * 8 + (lane & 3) * 2;
            float v0 = acc[mf][nf][0], v1 = acc[mf][nf][1];
            float v2 = acc[mf][nf][2], v3 = acc[mf][nf][3];
            if (EPI == 3) {
                int hh = c >> 6, d = c & 63;
                int b0 = r0 >> 12, s0 = r0 & 4095;
                size_t o = (((size_t)(b0 * Hc + hh)) * Sc + s0) * HDc + d;
                int r1 = r0 + 8;
                int b1 = r1 >> 12, s1 = r1 & 4095;
                size_t o2 = (((size_t)(b1 * Hc + hh)) * Sc + s1) * HDc + d;
                *(uint32_t*)(Ch + o)  = pack_hf(v0, v1);
                *(uint32_t*)(Ch + o2) = pack_hf(v2, v3);
            } else if (EPI == 1) {
                size_t o = (size_t)r0 * N + c;
                float2 rr = *(const float2*)(res + o);
                *(float2*)(Cf + o) = make_float2(v0 + rr.x, v1 + rr.y);
                o = (size_t)(r0 + 8) * N + c;
                rr = *(const float2*)(res + o);
                *(float2*)(Cf + o) = make_float2(v2 + rr.x, v3 + rr.y);
            } else {
                size_t o = (size_t)r0 * N + c;
                *(uint32_t*)(Ch + o) = pack_hf(fmaxf(v0, 0.f), fmaxf(v1, 0.f));
                o = (size_t)(r0 + 8) * N + c;
                *(uint32_t*)(Ch + o) = pack_hf(fmaxf(v2, 0.f), fmaxf(v3, 0.f));
            }
        }
    }
}

// ---------------------------------------------------------------------------
// HMMA attention (fp16 x1): per (bh, 128-query block), 64-key tiles, 3-stage K.
// S = qh*kh (1 MMA). P = exp(S/8) -> g_p (fp16, unnormalized) + smem fp16.
// ctx += P*V (1 MMA; V = K via trans ldmatrix).
// ---------------------------------------------------------------------------
constexpr int AP    = 144;
constexpr int A_QH  = 0;
constexpr int A_K0  = 18432;                    // 3 stages x 9216
constexpr int A_PH  = 46080, A_RS = 64512;
constexpr int ATT_SMEM = A_RS + 512 + 16;       // 65040

__global__ __launch_bounds__(256, 2)
void attn_mma()
{
    extern __shared__ __align__(16) char sm[];
    float* rsum = (float*)(sm + A_RS);
    const uint32_t sb = smem_u32(sm);
    const int tid = threadIdx.x, lane = tid & 31, wid = tid >> 5;
    const int wm = wid >> 1, wn = wid & 1;       // 4 M-warps x 2 N-warps
    const int bh = blockIdx.y, q0 = blockIdx.x * 128;
    constexpr int NKT = Sc / 64;

    const __half* Qh = g_qh + (size_t)bh * Sc * HDc;
    const __half* Kh = g_kh + (size_t)bh * Sc * HDc;

    auto issueK = [&](int kt, int stg) {
        uint32_t base = sb + A_K0 + stg * 9216;
        #pragma unroll
        for (int i = 0; i < 2; ++i) {
            int c = tid + i * 256, row = c >> 3, part = c & 7;
            cp16(base + row * AP + part * 16,
                 Kh + (size_t)(kt * 64 + row) * HDc + part * 8);
        }
        CP_COMMIT();
    };

    issueK(0, 0);
    issueK(1, 1);

    // Q tile 128x64 fp16 = 1024 16B-chunks (4 iterations x 256 threads)
    #pragma unroll
    for (int i = 0; i < 4; ++i) {
        int c = tid + i * 256, row = c >> 3, part = c & 7;
        size_t g = (size_t)(q0 + row) * HDc + part * 8;
        *(uint4*)(sm + A_QH + row * AP + part * 16) = *(const uint4*)(Qh + g);
    }
    if (tid < 128) rsum[tid] = 0.f;

    float ctx[2][4][4];
    #pragma unroll
    for (int i = 0; i < 2; ++i)
        #pragma unroll
        for (int j = 0; j < 4; ++j)
            #pragma unroll
            for (int q = 0; q < 4; ++q) ctx[i][j][q] = 0.f;
    float rs[2][2] = {{0.f, 0.f}, {0.f, 0.f}};

    for (int kt = 0; kt < NKT; ++kt) {
        const int stg = kt % 3;
        if (kt + 2 < NKT) { CP_WAIT(1); } else { CP_WAIT(0); }
        __syncthreads();   // K[stg] ready; prev iter fully done
        if (kt + 2 < NKT) issueK(kt + 2, (kt + 2) % 3);
        const uint32_t KB = sb + A_K0 + stg * 9216;

        // ---- S = qh*kh ----
        float s[2][4][4];
        #pragma unroll
        for (int i = 0; i < 2; ++i)
            #pragma unroll
            for (int j = 0; j < 4; ++j)
                #pragma unroll
                for (int q = 0; q < 4; ++q) s[i][j][q] = 0.f;

        #pragma unroll
        for (int ks = 0; ks < 4; ++ks) {
            uint32_t bhf[4][2];
            #pragma unroll
            for (int nfp = 0; nfp < 2; ++nfp) {
                int ro = (wn * 32 + nfp * 16 + (lane & 15)) * AP + ks * 32 + (lane >> 4) * 16;
                uint32_t r0, r1, r2, r3;
                ldsm_x4(r0, r1, r2, r3, KB + ro);
                bhf[nfp*2][0] = r0; bhf[nfp*2+1][0] = r1;
                bhf[nfp*2][1] = r2; bhf[nfp*2+1][1] = r3;
            }
            #pragma unroll
            for (int mf = 0; mf < 2; ++mf) {
                int ro = (wm * 32 + mf * 16 + (lane & 15)) * AP + ks * 32 + (lane >> 4) * 16;
                uint32_t a0, a1, a2, a3;
                ldsm_x4(a0, a1, a2, a3, sb + A_QH + ro);
                #pragma unroll
                for (int nf = 0; nf < 4; ++nf)
                    mma16816(s[mf][nf], a0, a1, a2, a3, bhf[nf][0], bhf[nf][1]);
            }
        }

        // ---- exp, rowsum, P stores (fp16 gmem + fp16 smem, same packed) ----
        #pragma unroll
        for (int mf = 0; mf < 2; ++mf) {
            int rl = wm * 32 + mf * 16 + (lane >> 2);
            #pragma unroll
            for (int nf = 0; nf < 4; ++nf) {
                int cl_ = wn * 32 + nf * 8 + (lane & 3) * 2;
                float p0 = __expf(s[mf][nf][0] * 0.125f);
                float p1 = __expf(s[mf][nf][1] * 0.125f);
                float p2 = __expf(s[mf][nf][2] * 0.125f);
                float p3 = __expf(s[mf][nf][3] * 0.125f);
                rs[mf][0] += p0 + p1;
                rs[mf][1] += p2 + p3;
                uint32_t q01 = pack_hf(p0, p1);
                uint32_t q23 = pack_hf(p2, p3);
                size_t gr = ((size_t)bh * Sc + q0 + rl) * Sc + kt * 64 + cl_;
                *(uint32_t*)(g_p + gr) = q01;
                *(uint32_t*)(g_p + gr + (size_t)8 * Sc) = q23;
                int so = rl * AP + cl_ * 2;
                *(uint32_t*)(sm + A_PH + so)          = q01;
                *(uint32_t*)(sm + A_PH + so + 8 * AP) = q23;
            }
        }
        __syncthreads();   // P visible for ldmatrix

        // ---- ctx += P V (V = K via trans ldmatrix) ----
        #pragma unroll
        for (int ks = 0; ks < 4; ++ks) {
            uint32_t vh[4][2];
            #pragma unroll
            for (int nfp = 0; nfp < 2; ++nfp) {
                int ro = (ks * 16 + (lane & 15)) * AP + wn * 64 + nfp * 32 + (lane >> 4) * 16;
                uint32_t r0, r1, r2, r3;
                ldsm_x4_t(r0, r1, r2, r3, KB + ro);
                vh[nfp*2][0] = r0; vh[nfp*2][1] = r1;
                vh[nfp*2+1][0] = r2; vh[nfp*2+1][1] = r3;
            }
            #pragma unroll
            for (int mf = 0; mf < 2; ++mf) {
                int ro = (wm * 32 + mf * 16 + (lane & 15)) * AP + ks * 32 + (lane >> 4) * 16;
                uint32_t p0, p1, p2, p3;
                ldsm_x4(p0, p1, p2, p3, sb + A_PH + ro);
                #pragma unroll
                for (int nf = 0; nf < 4; ++nf)
                    mma16816(ctx[mf][nf], p0, p1, p2, p3, vh[nf][0], vh[nf][1]);
            }
        }
    }

    // ---- rowsum reduce ----
    #pragma unroll
    for (int mf = 0; mf < 2; ++mf)
        #pragma unroll
        for (int h = 0; h < 2; ++h) {
            float v = rs[mf][h];
            v += __shfl_xor_sync(0xffffffffu, v, 1);
            v += __shfl_xor_sync(0xffffffffu, v, 2);
            if ((lane & 3) == 0)
                atomicAdd(&rsum[wm * 32 + mf * 16 + h * 8 + (lane >> 2)], v);
        }
    __syncthreads();

    if (tid < 128) g_rs[(size_t)bh * Sc + q0 + tid] = rsum[tid];

    const int bb = bh >> 3, hh = bh & 7;
    #pragma unroll
    for (int mf = 0; mf < 2; ++mf) {
        int rl = wm * 32 + mf * 16 + (lane >> 2);
        float i0 = 1.f / rsum[rl];
        float i1 = 1.f / rsum[rl + 8];
        #pragma unroll
        for (int nf = 0; nf < 4; ++nf) {
            int d = wn * 32 + nf * 8 + (lane & 3) * 2;
            size_t o = ((size_t)bb * Sc + q0 + rl) * Dc + hh * HDc + d;
            *(uint32_t*)(g_ch + o) = pack_hf(ctx[mf][nf][0] * i0, ctx[mf][nf][1] * i0);
            o += (size_t)8 * Dc;
            *(uint32_t*)(g_ch + o) = pack_hf(ctx[mf][nf][2] * i1, ctx[mf][nf][3] * i1);
        }
    }
}

// ---------------------------------------------------------------------------
// attn = fp16 P / rowsum  (reads 0.54GB fp16, writes 1.07GB fp32)
// ---------------------------------------------------------------------------
__global__ __launch_bounds__(256)
void norm_attn(float* __restrict__ attn)
{
    size_t i = (size_t)blockIdx.x * 256 + threadIdx.x;   // uint2 index (4 halves)
    size_t row = (i * 4) >> 12;
    float inv = 1.0f / g_rs[row];
    uint2 pv = ((const uint2*)g_p)[i];
    __half2 a = *(__half2*)&pv.x;
    __half2 b = *(__half2*)&pv.y;
    float2 fa = __half22float2(a);
    float2 fb = __half22float2(b);
    float4 o;
    o.x = fa.x * inv; o.y = fa.y * inv;
    o.z = fb.x * inv; o.w = fb.y * inv;
    ((float4*)attn)[i] = o;
}

// ---------------------------------------------------------------------------
// LayerNorm; optionally emits fp16 copy
// ---------------------------------------------------------------------------
template<bool SPLIT>
__global__ __launch_bounds__(128)
void ln_kernel(const float* __restrict__ X, const float* __restrict__ gw,
               const float* __restrict__ bw, float* __restrict__ Y,
               __half* __restrict__ Yh)
{
    const int row = blockIdx.x;
    const int tid = threadIdx.x;
    float4 v = ((const float4*)(X + (size_t)row * Dc))[tid];
    float s = (v.x + v.y) + (v.z + v.w);
    float q = (v.x*v.x + v.y*v.y) + (v.z*v.z + v.w*v.w);
    #pragma unroll
    for (int o = 16; o; o >>= 1) {
        s += __shfl_xor_sync(0xffffffffu, s, o);
        q += __shfl_xor_sync(0xffffffffu, q, o);
    }
    __shared__ float ss[4], sq[4];
    if ((tid & 31) == 0) { ss[tid >> 5] = s; sq[tid >> 5] = q; }
    __syncthreads();
    s = ss[0] + ss[1] + ss[2] + ss[3];
    q = sq[0] + sq[1] + sq[2] + sq[3];
    const float mu  = s * (1.0f / Dc);
    const float var = q * (1.0f / Dc) - mu * mu;
    const float inv = rsqrtf(var + 1e-5f);
    float4 g4 = ((const float4*)gw)[tid];
    float4 b4 = ((const float4*)bw)[tid];
    float4 o4;
    o4.x = (v.x - mu) * inv * g4.x + b4.x;
    o4.y = (v.y - mu) * inv * g4.y + b4.y;
    o4.z = (v.z - mu) * inv * g4.z + b4.z;
    o4.w = (v.w - mu) * inv * g4.w + b4.w;
    ((float4*)(Y + (size_t)row * Dc))[tid] = o4;
    if (SPLIT) {
        size_t o = (size_t)row * Dc + tid * 4;
        *(uint32_t*)(Yh + o)     = pack_hf(o4.x, o4.y);
        *(uint32_t*)(Yh + o + 2) = pack_hf(o4.z, o4.w);
    }
}

// ---------------------------------------------------------------------------
extern "C" void kernel_launch(void* const* d_in, const int* in_sizes, int n_in,
                              void* d_out, int out_size)
{
    const float* x    = (const float*)d_in[0];
    const float* Wq   = (const float*)d_in[2];
    const float* Wk   = (const float*)d_in[3];
    const float* Wfc  = (const float*)d_in[5];
    const float* Wff1 = (const float*)d_in[6];
    const float* Wff2 = (const float*)d_in[7];
    const float* g1   = (const float*)d_in[8];
    const float* b1   = (const float*)d_in[9];
    const float* g2   = (const float*)d_in[10];
    const float* b2   = (const float*)d_in[11];

    float* out_feed = (float*)d_out;
    float* out_attn = (float*)d_out + (size_t)Mc * Dc;

    float *pY1, *pAtt, *pY2;
    cudaGetSymbolAddress((void**)&pY1,  g_y1);
    cudaGetSymbolAddress((void**)&pAtt, g_att);
    cudaGetSymbolAddress((void**)&pY2,  g_y2);

    __half *xh,*qh,*kh,*ch,*ah,*zh;
    __half *wqh,*wql,*wkh,*wkl,*wfh,*wfl,*w1h,*w1l,*w2h,*w2l;
    cudaGetSymbolAddress((void**)&xh,  g_xh);
    cudaGetSymbolAddress((void**)&qh,  g_qh);
    cudaGetSymbolAddress((void**)&kh,  g_kh);
    cudaGetSymbolAddress((void**)&ch,  g_ch);
    cudaGetSymbolAddress((void**)&ah,  g_ah);
    cudaGetSymbolAddress((void**)&zh,  g_zh);
    cudaGetSymbolAddress((void**)&wqh, g_wqh); cudaGetSymbolAddress((void**)&wql, g_wql);
    cudaGetSymbolAddress((void**)&wkh, g_wkh); cudaGetSymbolAddress((void**)&wkl, g_wkl);
    cudaGetSymbolAddress((void**)&wfh, g_wfh); cudaGetSymbolAddress((void**)&wfl, g_wfl);
    cudaGetSymbolAddress((void**)&w1h, g_w1h); cudaGetSymbolAddress((void**)&w1l, g_w1l);
    cudaGetSymbolAddress((void**)&w2h, g_w2h); cudaGetSymbolAddress((void**)&w2l, g_w2l);

    cudaFuncSetAttribute(attn_mma,
                         cudaFuncAttributeMaxDynamicSharedMemorySize, ATT_SMEM);
    cudaFuncSetAttribute(gemm_mma<1>,
                         cudaFuncAttributeMaxDynamicSharedMemorySize, GEMM_SMEM3);
    cudaFuncSetAttribute(gemm_mma<2>,
                         cudaFuncAttributeMaxDynamicSharedMemorySize, GEMM_SMEM3);
    cudaFuncSetAttribute(gemm_mma<3>,
                         cudaFuncAttributeMaxDynamicSharedMemorySize, GEMM_SMEM3);

    // One-time side-stream resources
    static cudaStream_t s2 = nullptr;
    static cudaEvent_t  eFork = nullptr, eJoin = nullptr, eW = nullptr;
    static cudaEvent_t  eX = nullptr, eK = nullptr;
    if (s2 == nullptr) {
        cudaStreamCreateWithFlags(&s2, cudaStreamNonBlocking);
        cudaEventCreateWithFlags(&eFork, cudaEventDisableTiming);
        cudaEventCreateWithFlags(&eJoin, cudaEventDisableTiming);
        cudaEventCreateWithFlags(&eW,    cudaEventDisableTiming);
        cudaEventCreateWithFlags(&eX,    cudaEventDisableTiming);
        cudaEventCreateWithFlags(&eK,    cudaEventDisableTiming);
    }

    // 0. x -> fp16 on main; weights -> fp16 hi/lo on side stream
    cudaEventRecord(eFork, 0);
    cudaStreamWaitEvent(s2, eFork, 0);
    cvt_hi<<<(unsigned)((size_t)Mc * Dc / 1024), 256>>>((const float4*)x, (uint2*)xh);
    cudaEventRecord(eX, 0);
    auto cvtW = [&](const float* w, __half* hi, __half* lo, size_t n) {
        cvt_hilo<<<(unsigned)(n / 1024), 256, 0, s2>>>((const float4*)w,
                                                       (uint2*)hi, (uint2*)lo);
    };
    cvtW(Wq,   wqh, wql, (size_t)Dc * Dc);
    cvtW(Wk,   wkh, wkl, (size_t)Dc * Dc);
    cvtW(Wfc,  wfh, wfl, (size_t)Dc * Dc);
    cvtW(Wff1, w1h, w1l, (size_t)FFc * Dc);
    cvtW(Wff2, w2h, w2l, (size_t)Dc * FFc);
    cudaEventRecord(eW, s2);
    cudaStreamWaitEvent(0, eW, 0);      // main needs weights for Q proj
    cudaStreamWaitEvent(s2, eX, 0);     // s2 needs xh for K proj

    // 1. Q proj on main || K proj on s2 (both permuted fp16)
    gemm_mma<3><<<dim3(Dc/128, Mc/128), 256, GEMM_SMEM3>>>(xh, wqh, wql, nullptr, nullptr, qh, Dc, Dc);
    gemm_mma<3><<<dim3(Dc/128, Mc/128), 256, GEMM_SMEM3, s2>>>(xh, wkh, wkl, nullptr, nullptr, kh, Dc, Dc);
    cudaEventRecord(eK, s2);
    cudaStreamWaitEvent(0, eK, 0);

    // 2. Attention (fp16 unnormalized P to scratch + ctx fp16)
    attn_mma<<<dim3(Sc/128, BHc), 256, ATT_SMEM>>>();

    // Fork: normalize attn (fp16 -> fp32) on side stream, concurrent with FFN
    cudaEventRecord(eFork, 0);
    cudaStreamWaitEvent(s2, eFork, 0);
    {
        size_t n4 = (size_t)BHc * Sc * Sc / 4;
        norm_attn<<<(unsigned)(n4 / 256), 256, 0, s2>>>(out_attn);
    }

    // 3. y1 = x + ctx@Wfc^T ; att = LN(y1) (+ fp16)
    gemm_mma<1><<<dim3(Dc/128, Mc/128), 256, GEMM_SMEM3>>>(ch, wfh, wfl, x, pY1, nullptr, Dc, Dc);
    ln_kernel<true><<<Mc, 128>>>(pY1, g1, b1, pAtt, ah);

    // 4. z = relu(att@Wff1^T) ; y2 = att + z@Wff2^T ; out = LN(y2)
    gemm_mma<2><<<dim3(FFc/128, Mc/128), 256, GEMM_SMEM3>>>(ah, w1h, w1l, nullptr, nullptr, zh, FFc, Dc);
    gemm_mma<1><<<dim3(Dc/128, Mc/128), 256, GEMM_SMEM3>>>(zh, w2h, w2l, pAtt, pY2, nullptr, Dc, FFc);
    ln_kernel<false><<<Mc, 128>>>(pY2, g2, b2, out_feed, nullptr);

    // Join: main stream waits for norm_attn
    cudaEventRecord(eJoin, s2);
    cudaStreamWaitEvent(0, eJoin, 0);
}

// round 10
// speedup vs baseline: 4.0519x; 1.1517x over previous
#include <cuda_runtime.h>
#include <cuda_fp16.h>
#include <math.h>
#include <stdint.h>

// Problem constants
constexpr int Bc  = 2;
constexpr int Sc  = 4096;
constexpr int Dc  = 512;
constexpr int Hc  = 8;
constexpr int HDc = 64;
constexpr int FFc = 2048;
constexpr int BHc = Bc * Hc;        // 16
constexpr int Mc  = Bc * Sc;        // 8192

// ---------------------------------------------------------------------------
// Scratch (device globals)
// ---------------------------------------------------------------------------
__device__ float g_rs [BHc * Sc];
__device__ float g_y1 [Mc * Dc];
__device__ float g_att[Mc * Dc];
__device__ float g_y2 [Mc * Dc];

__device__ __half g_p  [(size_t)BHc * Sc * Sc];   // unnormalized P, fp16

__device__ __half g_xh [Mc * Dc];
__device__ __half g_qh [BHc * Sc * HDc];
__device__ __half g_kh [BHc * Sc * HDc];
__device__ __half g_ch [Mc * Dc];
__device__ __half g_ah [Mc * Dc];
__device__ __half g_zh [Mc * FFc];
__device__ __half g_wqh[Dc * Dc];
__device__ __half g_wkh[Dc * Dc];
__device__ __half g_wfh[Dc * Dc];
__device__ __half g_w1h[FFc * Dc];
__device__ __half g_w2h[Dc * FFc];

// ---------------------------------------------------------------------------
// Helpers
// ---------------------------------------------------------------------------
__device__ __forceinline__ uint32_t smem_u32(const void* p) {
    uint32_t a;
    asm("{ .reg .u64 t; cvta.to.shared.u64 t, %1; cvt.u32.u64 %0, t; }"
        : "=r"(a) : "l"(p));
    return a;
}
__device__ __forceinline__ void cp16(uint32_t saddr, const void* g) {
    asm volatile("cp.async.cg.shared.global [%0], [%1], 16;"
                 :: "r"(saddr), "l"(g) : "memory");
}
#define CP_COMMIT()  asm volatile("cp.async.commit_group;" ::: "memory")
#define CP_WAIT(n)   asm volatile("cp.async.wait_group %0;" :: "n"(n) : "memory")

__device__ __forceinline__ void ldsm_x4(uint32_t& r0, uint32_t& r1,
                                        uint32_t& r2, uint32_t& r3, uint32_t a) {
    asm volatile("ldmatrix.sync.aligned.m8n8.x4.shared.b16 {%0,%1,%2,%3}, [%4];"
                 : "=r"(r0), "=r"(r1), "=r"(r2), "=r"(r3) : "r"(a));
}
__device__ __forceinline__ void ldsm_x4_t(uint32_t& r0, uint32_t& r1,
                                          uint32_t& r2, uint32_t& r3, uint32_t a) {
    asm volatile("ldmatrix.sync.aligned.m8n8.x4.trans.shared.b16 {%0,%1,%2,%3}, [%4];"
                 : "=r"(r0), "=r"(r1), "=r"(r2), "=r"(r3) : "r"(a));
}

__device__ __forceinline__ void mma16816(float c[4],
        uint32_t a0, uint32_t a1, uint32_t a2, uint32_t a3,
        uint32_t b0, uint32_t b1) {
    asm volatile("mma.sync.aligned.m16n8k16.row.col.f32.f16.f16.f32 "
                 "{%0,%1,%2,%3}, {%4,%5,%6,%7}, {%8,%9}, {%0,%1,%2,%3};"
                 : "+f"(c[0]), "+f"(c[1]), "+f"(c[2]), "+f"(c[3])
                 : "r"(a0), "r"(a1), "r"(a2), "r"(a3), "r"(b0), "r"(b1));
}

__device__ __forceinline__ uint32_t pack_h(__half a, __half b) {
    return ((uint32_t)__half_as_ushort(b) << 16) | (uint32_t)__half_as_ushort(a);
}
__device__ __forceinline__ uint32_t pack_hf(float x, float y) {
    return pack_h(__float2half_rn(x), __float2half_rn(y));
}

// ---------------------------------------------------------------------------
// fp32 -> fp16 conversion
// ---------------------------------------------------------------------------
__global__ __launch_bounds__(256)
void cvt_hi(const float4* __restrict__ in, uint2* __restrict__ hi)
{
    size_t i = (size_t)blockIdx.x * 256 + threadIdx.x;
    float4 v = in[i];
    hi[i] = make_uint2(pack_hf(v.x, v.y), pack_hf(v.z, v.w));
}

// ---------------------------------------------------------------------------
// HMMA GEMM (fp16 x1), 3-stage cp.async.
// C[M,N] = A[M,K] @ W[N,K]^T. CTA 128x128, BK=32, 256 thr, 8 warps (2Mx4N).
// EPI 3: permuted fp16 store (Q/K) ; 1: fp32+residual ; 2: relu+fp16
// ---------------------------------------------------------------------------
constexpr int GP = 80;
constexpr int SM_A = 0, SM_W = 10240;
constexpr int GSTG = 20480;
constexpr int GEMM_SMEM3 = 3 * GSTG;           // 61440

template<int EPI>
__global__ __launch_bounds__(256, 2)
void gemm_mma(const __half* __restrict__ Ah,
              const __half* __restrict__ Wh,
              const float* __restrict__ res, float* __restrict__ Cf,
              __half* __restrict__ Ch,
              int N, int K)
{
    extern __shared__ __align__(16) char smd[];
    const uint32_t sb = smem_u32(smd);
    const int tid = threadIdx.x, lane = tid & 31, wid = tid >> 5;
    const int wm = wid >> 2, wn = wid & 3;
    const int m0 = blockIdx.y * 128, n0 = blockIdx.x * 128;
    const int NK = K >> 5;

    float acc[4][4][4];
    #pragma unroll
    for (int i = 0; i < 4; ++i)
        #pragma unroll
        for (int j = 0; j < 4; ++j)
            #pragma unroll
            for (int q = 0; q < 4; ++q) acc[i][j][q] = 0.f;

    auto issue = [&](int it, int stg) {
        uint32_t base = sb + stg * GSTG;
        #pragma unroll
        for (int i = 0; i < 2; ++i) {
            int c = tid + i * 256, row = c >> 2, part = c & 3;
            int so = row * GP + part * 16;
            size_t ga = (size_t)(m0 + row) * K + it * 32 + part * 8;
            size_t gw = (size_t)(n0 + row) * K + it * 32 + part * 8;
            cp16(base + SM_A + so, Ah + ga);
            cp16(base + SM_W + so, Wh + gw);
        }
        CP_COMMIT();
    };

    issue(0, 0);
    issue(1, 1);

    for (int it = 0; it < NK; ++it) {
        const int stg = it % 3;
        if (it + 2 < NK) { CP_WAIT(1); } else { CP_WAIT(0); }
        __syncthreads();
        if (it + 2 < NK) issue(it + 2, (it + 2) % 3);
        const uint32_t base = sb + stg * GSTG;

        #pragma unroll
        for (int ks = 0; ks < 2; ++ks) {
            uint32_t wh[4][2];
            #pragma unroll
            for (int nfp = 0; nfp < 2; ++nfp) {
                int ro = (wn * 32 + nfp * 16 + (lane & 15)) * GP + ks * 32 + (lane >> 4) * 16;
                uint32_t r0, r1, r2, r3;
                ldsm_x4(r0, r1, r2, r3, base + SM_W + ro);
                wh[nfp*2][0] = r0; wh[nfp*2+1][0] = r1;
                wh[nfp*2][1] = r2; wh[nfp*2+1][1] = r3;
            }
            #pragma unroll
            for (int mf = 0; mf < 4; ++mf) {
                int ro = (wm * 64 + mf * 16 + (lane & 15)) * GP + ks * 32 + (lane >> 4) * 16;
                uint32_t a0, a1, a2, a3;
                ldsm_x4(a0, a1, a2, a3, base + SM_A + ro);
                #pragma unroll
                for (int nf = 0; nf < 4; ++nf)
                    mma16816(acc[mf][nf], a0, a1, a2, a3, wh[nf][0], wh[nf][1]);
            }
        }
    }

    // epilogue
    #pragma unroll
    for (int mf = 0; mf < 4; ++mf) {
        int r0 = m0 + wm * 64 + mf * 16 + (lane >> 2);
        #pragma unroll
        for (int nf = 0; nf < 4; ++nf) {
            int c = n0 + wn * 32 + nf * 8 + (lane & 3) * 2;
            float v0 = acc[mf][nf][0], v1 = acc[mf][nf][1];
            float v2 = acc[mf][nf][2], v3 = acc[mf][nf][3];
            if (EPI == 3) {
                int hh = c >> 6, d = c & 63;
                int b0 = r0 >> 12, s0 = r0 & 4095;
                size_t o = (((size_t)(b0 * Hc + hh)) * Sc + s0) * HDc + d;
                int r1 = r0 + 8;
                int b1 = r1 >> 12, s1 = r1 & 4095;
                size_t o2 = (((size_t)(b1 * Hc + hh)) * Sc + s1) * HDc + d;
                *(uint32_t*)(Ch + o)  = pack_hf(v0, v1);
                *(uint32_t*)(Ch + o2) = pack_hf(v2, v3);
            } else if (EPI == 1) {
                size_t o = (size_t)r0 * N + c;
                float2 rr = *(const float2*)(res + o);
                *(float2*)(Cf + o) = make_float2(v0 + rr.x, v1 + rr.y);
                o = (size_t)(r0 + 8) * N + c;
                rr = *(const float2*)(res + o);
                *(float2*)(Cf + o) = make_float2(v2 + rr.x, v3 + rr.y);
            } else {
                size_t o = (size_t)r0 * N + c;
                *(uint32_t*)(Ch + o) = pack_hf(fmaxf(v0, 0.f), fmaxf(v1, 0.f));
                o = (size_t)(r0 + 8) * N + c;
                *(uint32_t*)(Ch + o) = pack_hf(fmaxf(v2, 0.f), fmaxf(v3, 0.f));
            }
        }
    }
}

// ---------------------------------------------------------------------------
// HMMA attention (fp16 x1): per (bh, 128-query block), 64-key tiles, 3-stage K.
// S = qh*kh (1 MMA). P = exp(S/8) -> g_p (fp16, unnormalized) + smem fp16.
// ctx += P*V (1 MMA; V = K via trans ldmatrix).
// ---------------------------------------------------------------------------
constexpr int AP    = 144;
constexpr int A_QH  = 0;
constexpr int A_K0  = 18432;                    // 3 stages x 9216
constexpr int A_PH  = 46080, A_RS = 64512;
constexpr int ATT_SMEM = A_RS + 512 + 16;       // 65040

__global__ __launch_bounds__(256, 2)
void attn_mma()
{
    extern __shared__ __align__(16) char sm[];
    float* rsum = (float*)(sm + A_RS);
    const uint32_t sb = smem_u32(sm);
    const int tid = threadIdx.x, lane = tid & 31, wid = tid >> 5;
    const int wm = wid >> 1, wn = wid & 1;       // 4 M-warps x 2 N-warps
    const int bh = blockIdx.y, q0 = blockIdx.x * 128;
    constexpr int NKT = Sc / 64;

    const __half* Qh = g_qh + (size_t)bh * Sc * HDc;
    const __half* Kh = g_kh + (size_t)bh * Sc * HDc;

    auto issueK = [&](int kt, int stg) {
        uint32_t base = sb + A_K0 + stg * 9216;
        #pragma unroll
        for (int i = 0; i < 2; ++i) {
            int c = tid + i * 256, row = c >> 3, part = c & 7;
            cp16(base + row * AP + part * 16,
                 Kh + (size_t)(kt * 64 + row) * HDc + part * 8);
        }
        CP_COMMIT();
    };

    issueK(0, 0);
    issueK(1, 1);

    // Q tile 128x64 fp16 = 1024 16B-chunks (4 iterations x 256 threads)
    #pragma unroll
    for (int i = 0; i < 4; ++i) {
        int c = tid + i * 256, row = c >> 3, part = c & 7;
        size_t g = (size_t)(q0 + row) * HDc + part * 8;
        *(uint4*)(sm + A_QH + row * AP + part * 16) = *(const uint4*)(Qh + g);
    }
    if (tid < 128) rsum[tid] = 0.f;

    float ctx[2][4][4];
    #pragma unroll
    for (int i = 0; i < 2; ++i)
        #pragma unroll
        for (int j = 0; j < 4; ++j)
            #pragma unroll
            for (int q = 0; q < 4; ++q) ctx[i][j][q] = 0.f;
    float rs[2][2] = {{0.f, 0.f}, {0.f, 0.f}};

    for (int kt = 0; kt < NKT; ++kt) {
        const int stg = kt % 3;
        if (kt + 2 < NKT) { CP_WAIT(1); } else { CP_WAIT(0); }
        __syncthreads();   // K[stg] ready; prev iter fully done
        if (kt + 2 < NKT) issueK(kt + 2, (kt + 2) % 3);
        const uint32_t KB = sb + A_K0 + stg * 9216;

        // ---- S = qh*kh ----
        float s[2][4][4];
        #pragma unroll
        for (int i = 0; i < 2; ++i)
            #pragma unroll
            for (int j = 0; j < 4; ++j)
                #pragma unroll
                for (int q = 0; q < 4; ++q) s[i][j][q] = 0.f;

        #pragma unroll
        for (int ks = 0; ks < 4; ++ks) {
            uint32_t bhf[4][2];
            #pragma unroll
            for (int nfp = 0; nfp < 2; ++nfp) {
                int ro = (wn * 32 + nfp * 16 + (lane & 15)) * AP + ks * 32 + (lane >> 4) * 16;
                uint32_t r0, r1, r2, r3;
                ldsm_x4(r0, r1, r2, r3, KB + ro);
                bhf[nfp*2][0] = r0; bhf[nfp*2+1][0] = r1;
                bhf[nfp*2][1] = r2; bhf[nfp*2+1][1] = r3;
            }
            #pragma unroll
            for (int mf = 0; mf < 2; ++mf) {
                int ro = (wm * 32 + mf * 16 + (lane & 15)) * AP + ks * 32 + (lane >> 4) * 16;
                uint32_t a0, a1, a2, a3;
                ldsm_x4(a0, a1, a2, a3, sb + A_QH + ro);
                #pragma unroll
                for (int nf = 0; nf < 4; ++nf)
                    mma16816(s[mf][nf], a0, a1, a2, a3, bhf[nf][0], bhf[nf][1]);
            }
        }

        // ---- exp, rowsum, P stores (fp16 gmem + fp16 smem, same packed) ----
        #pragma unroll
        for (int mf = 0; mf < 2; ++mf) {
            int rl = wm * 32 + mf * 16 + (lane >> 2);
            #pragma unroll
            for (int nf = 0; nf < 4; ++nf) {
                int cl_ = wn * 32 + nf * 8 + (lane & 3) * 2;
                float p0 = __expf(s[mf][nf][0] * 0.125f);
                float p1 = __expf(s[mf][nf][1] * 0.125f);
                float p2 = __expf(s[mf][nf][2] * 0.125f);
                float p3 = __expf(s[mf][nf][3] * 0.125f);
                rs[mf][0] += p0 + p1;
                rs[mf][1] += p2 + p3;
                uint32_t q01 = pack_hf(p0, p1);
                uint32_t q23 = pack_hf(p2, p3);
                size_t gr = ((size_t)bh * Sc + q0 + rl) * Sc + kt * 64 + cl_;
                *(uint32_t*)(g_p + gr) = q01;
                *(uint32_t*)(g_p + gr + (size_t)8 * Sc) = q23;
                int so = rl * AP + cl_ * 2;
                *(uint32_t*)(sm + A_PH + so)          = q01;
                *(uint32_t*)(sm + A_PH + so + 8 * AP) = q23;
            }
        }
        __syncthreads();   // P visible for ldmatrix

        // ---- ctx += P V (V = K via trans ldmatrix) ----
        #pragma unroll
        for (int ks = 0; ks < 4; ++ks) {
            uint32_t vh[4][2];
            #pragma unroll
            for (int nfp = 0; nfp < 2; ++nfp) {
                int ro = (ks * 16 + (lane & 15)) * AP + wn * 64 + nfp * 32 + (lane >> 4) * 16;
                uint32_t r0, r1, r2, r3;
                ldsm_x4_t(r0, r1, r2, r3, KB + ro);
                vh[nfp*2][0] = r0; vh[nfp*2][1] = r1;
                vh[nfp*2+1][0] = r2; vh[nfp*2+1][1] = r3;
            }
            #pragma unroll
            for (int mf = 0; mf < 2; ++mf) {
                int ro = (wm * 32 + mf * 16 + (lane & 15)) * AP + ks * 32 + (lane >> 4) * 16;
                uint32_t p0, p1, p2, p3;
                ldsm_x4(p0, p1, p2, p3, sb + A_PH + ro);
                #pragma unroll
                for (int nf = 0; nf < 4; ++nf)
                    mma16816(ctx[mf][nf], p0, p1, p2, p3, vh[nf][0], vh[nf][1]);
            }
        }
    }

    // ---- rowsum reduce ----
    #pragma unroll
    for (int mf = 0; mf < 2; ++mf)
        #pragma unroll
        for (int h = 0; h < 2; ++h) {
            float v = rs[mf][h];
            v += __shfl_xor_sync(0xffffffffu, v, 1);
            v += __shfl_xor_sync(0xffffffffu, v, 2);
            if ((lane & 3) == 0)
                atomicAdd(&rsum[wm * 32 + mf * 16 + h * 8 + (lane >> 2)], v);
        }
    __syncthreads();

    if (tid < 128) g_rs[(size_t)bh * Sc + q0 + tid] = rsum[tid];

    const int bb = bh >> 3, hh = bh & 7;
    #pragma unroll
    for (int mf = 0; mf < 2; ++mf) {
        int rl = wm * 32 + mf * 16 + (lane >> 2);
        float i0 = 1.f / rsum[rl];
        float i1 = 1.f / rsum[rl + 8];
        #pragma unroll
        for (int nf = 0; nf < 4; ++nf) {
            int d = wn * 32 + nf * 8 + (lane & 3) * 2;
            size_t o = ((size_t)bb * Sc + q0 + rl) * Dc + hh * HDc + d;
            *(uint32_t*)(g_ch + o) = pack_hf(ctx[mf][nf][0] * i0, ctx[mf][nf][1] * i0);
            o += (size_t)8 * Dc;
            *(uint32_t*)(g_ch + o) = pack_hf(ctx[mf][nf][2] * i1, ctx[mf][nf][3] * i1);
        }
    }
}

// ---------------------------------------------------------------------------
// attn = fp16 P / rowsum
// ---------------------------------------------------------------------------
__global__ __launch_bounds__(256)
void norm_attn(float* __restrict__ attn)
{
    size_t i = (size_t)blockIdx.x * 256 + threadIdx.x;   // uint2 index (4 halves)
    size_t row = (i * 4) >> 12;
    float inv = 1.0f / g_rs[row];
    uint2 pv = ((const uint2*)g_p)[i];
    __half2 a = *(__half2*)&pv.x;
    __half2 b = *(__half2*)&pv.y;
    float2 fa = __half22float2(a);
    float2 fb = __half22float2(b);
    float4 o;
    o.x = fa.x * inv; o.y = fa.y * inv;
    o.z = fb.x * inv; o.w = fb.y * inv;
    ((float4*)attn)[i] = o;
}

// ---------------------------------------------------------------------------
// LayerNorm; optionally emits fp16 copy
// ---------------------------------------------------------------------------
template<bool SPLIT>
__global__ __launch_bounds__(128)
void ln_kernel(const float* __restrict__ X, const float* __restrict__ gw,
               const float* __restrict__ bw, float* __restrict__ Y,
               __half* __restrict__ Yh)
{
    const int row = blockIdx.x;
    const int tid = threadIdx.x;
    float4 v = ((const float4*)(X + (size_t)row * Dc))[tid];
    float s = (v.x + v.y) + (v.z + v.w);
    float q = (v.x*v.x + v.y*v.y) + (v.z*v.z + v.w*v.w);
    #pragma unroll
    for (int o = 16; o; o >>= 1) {
        s += __shfl_xor_sync(0xffffffffu, s, o);
        q += __shfl_xor_sync(0xffffffffu, q, o);
    }
    __shared__ float ss[4], sq[4];
    if ((tid & 31) == 0) { ss[tid >> 5] = s; sq[tid >> 5] = q; }
    __syncthreads();
    s = ss[0] + ss[1] + ss[2] + ss[3];
    q = sq[0] + sq[1] + sq[2] + sq[3];
    const float mu  = s * (1.0f / Dc);
    const float var = q * (1.0f / Dc) - mu * mu;
    const float inv = rsqrtf(var + 1e-5f);
    float4 g4 = ((const float4*)gw)[tid];
    float4 b4 = ((const float4*)bw)[tid];
    float4 o4;
    o4.x = (v.x - mu) * inv * g4.x + b4.x;
    o4.y = (v.y - mu) * inv * g4.y + b4.y;
    o4.z = (v.z - mu) * inv * g4.z + b4.z;
    o4.w = (v.w - mu) * inv * g4.w + b4.w;
    ((float4*)(Y + (size_t)row * Dc))[tid] = o4;
    if (SPLIT) {
        size_t o = (size_t)row * Dc + tid * 4;
        *(uint32_t*)(Yh + o)     = pack_hf(o4.x, o4.y);
        *(uint32_t*)(Yh + o + 2) = pack_hf(o4.z, o4.w);
    }
}

// ---------------------------------------------------------------------------
extern "C" void kernel_launch(void* const* d_in, const int* in_sizes, int n_in,
                              void* d_out, int out_size)
{
    const float* x    = (const float*)d_in[0];
    const float* Wq   = (const float*)d_in[2];
    const float* Wk   = (const float*)d_in[3];
    const float* Wfc  = (const float*)d_in[5];
    const float* Wff1 = (const float*)d_in[6];
    const float* Wff2 = (const float*)d_in[7];
    const float* g1   = (const float*)d_in[8];
    const float* b1   = (const float*)d_in[9];
    const float* g2   = (const float*)d_in[10];
    const float* b2   = (const float*)d_in[11];

    float* out_feed = (float*)d_out;
    float* out_attn = (float*)d_out + (size_t)Mc * Dc;

    float *pY1, *pAtt, *pY2;
    cudaGetSymbolAddress((void**)&pY1,  g_y1);
    cudaGetSymbolAddress((void**)&pAtt, g_att);
    cudaGetSymbolAddress((void**)&pY2,  g_y2);

    __half *xh,*qh,*kh,*ch,*ah,*zh;
    __half *wqh,*wkh,*wfh,*w1h,*w2h;
    cudaGetSymbolAddress((void**)&xh,  g_xh);
    cudaGetSymbolAddress((void**)&qh,  g_qh);
    cudaGetSymbolAddress((void**)&kh,  g_kh);
    cudaGetSymbolAddress((void**)&ch,  g_ch);
    cudaGetSymbolAddress((void**)&ah,  g_ah);
    cudaGetSymbolAddress((void**)&zh,  g_zh);
    cudaGetSymbolAddress((void**)&wqh, g_wqh);
    cudaGetSymbolAddress((void**)&wkh, g_wkh);
    cudaGetSymbolAddress((void**)&wfh, g_wfh);
    cudaGetSymbolAddress((void**)&w1h, g_w1h);
    cudaGetSymbolAddress((void**)&w2h, g_w2h);

    cudaFuncSetAttribute(attn_mma,
                         cudaFuncAttributeMaxDynamicSharedMemorySize, ATT_SMEM);
    cudaFuncSetAttribute(gemm_mma<1>,
                         cudaFuncAttributeMaxDynamicSharedMemorySize, GEMM_SMEM3);
    cudaFuncSetAttribute(gemm_mma<2>,
                         cudaFuncAttributeMaxDynamicSharedMemorySize, GEMM_SMEM3);
    cudaFuncSetAttribute(gemm_mma<3>,
                         cudaFuncAttributeMaxDynamicSharedMemorySize, GEMM_SMEM3);

    // One-time side-stream resources
    static cudaStream_t s2 = nullptr;
    static cudaEvent_t  eFork = nullptr, eJoin = nullptr, eW = nullptr;
    static cudaEvent_t  eX = nullptr, eK = nullptr;
    if (s2 == nullptr) {
        cudaStreamCreateWithFlags(&s2, cudaStreamNonBlocking);
        cudaEventCreateWithFlags(&eFork, cudaEventDisableTiming);
        cudaEventCreateWithFlags(&eJoin, cudaEventDisableTiming);
        cudaEventCreateWithFlags(&eW,    cudaEventDisableTiming);
        cudaEventCreateWithFlags(&eX,    cudaEventDisableTiming);
        cudaEventCreateWithFlags(&eK,    cudaEventDisableTiming);
    }

    // 0. x -> fp16 on main; weights -> fp16 on side stream
    cudaEventRecord(eFork, 0);
    cudaStreamWaitEvent(s2, eFork, 0);
    cvt_hi<<<(unsigned)((size_t)Mc * Dc / 1024), 256>>>((const float4*)x, (uint2*)xh);
    cudaEventRecord(eX, 0);
    auto cvtW = [&](const float* w, __half* hi, size_t n) {
        cvt_hi<<<(unsigned)(n / 1024), 256, 0, s2>>>((const float4*)w, (uint2*)hi);
    };
    cvtW(Wq,   wqh, (size_t)Dc * Dc);
    cvtW(Wk,   wkh, (size_t)Dc * Dc);
    cvtW(Wfc,  wfh, (size_t)Dc * Dc);
    cvtW(Wff1, w1h, (size_t)FFc * Dc);
    cvtW(Wff2, w2h, (size_t)Dc * FFc);
    cudaEventRecord(eW, s2);
    cudaStreamWaitEvent(0, eW, 0);      // main needs weights for Q proj
    cudaStreamWaitEvent(s2, eX, 0);     // s2 needs xh for K proj

    // 1. Q proj on main || K proj on s2 (both permuted fp16)
    gemm_mma<3><<<dim3(Dc/128, Mc/128), 256, GEMM_SMEM3>>>(xh, wqh, nullptr, nullptr, qh, Dc, Dc);
    gemm_mma<3><<<dim3(Dc/128, Mc/128), 256, GEMM_SMEM3, s2>>>(xh, wkh, nullptr, nullptr, kh, Dc, Dc);
    cudaEventRecord(eK, s2);
    cudaStreamWaitEvent(0, eK, 0);

    // 2. Attention (fp16 unnormalized P to scratch + ctx fp16)
    attn_mma<<<dim3(Sc/128, BHc), 256, ATT_SMEM>>>();

    // Fork: normalize attn (fp16 -> fp32) on side stream, concurrent with FFN
    cudaEventRecord(eFork, 0);
    cudaStreamWaitEvent(s2, eFork, 0);
    {
        size_t n4 = (size_t)BHc * Sc * Sc / 4;
        norm_attn<<<(unsigned)(n4 / 256), 256, 0, s2>>>(out_attn);
    }

    // 3. y1 = x + ctx@Wfc^T ; att = LN(y1) (+ fp16)
    gemm_mma<1><<<dim3(Dc/128, Mc/128), 256, GEMM_SMEM3>>>(ch, wfh, x, pY1, nullptr, Dc, Dc);
    ln_kernel<true><<<Mc, 128>>>(pY1, g1, b1, pAtt, ah);

    // 4. z = relu(att@Wff1^T) ; y2 = att + z@Wff2^T ; out = LN(y2)
    gemm_mma<2><<<dim3(FFc/128, Mc/128), 256, GEMM_SMEM3>>>(ah, w1h, nullptr, nullptr, zh, FFc, Dc);
    gemm_mma<1><<<dim3(Dc/128, Mc/128), 256, GEMM_SMEM3>>>(zh, w2h, pAtt, pY2, nullptr, Dc, FFc);
    ln_kernel<false><<<Mc, 128>>>(pY2, g2, b2, out_feed, nullptr);

    // Join: main stream waits for norm_attn
    cudaEventRecord(eJoin, s2);
    cudaStreamWaitEvent(0, eJoin, 0);
}

// round 12
// speedup vs baseline: 4.1273x; 1.0186x over previous
#include <cuda_runtime.h>
#include <cuda_fp16.h>
#include <math.h>
#include <stdint.h>

// Problem constants
constexpr int Bc  = 2;
constexpr int Sc  = 4096;
constexpr int Dc  = 512;
constexpr int Hc  = 8;
constexpr int HDc = 64;
constexpr int FFc = 2048;
constexpr int BHc = Bc * Hc;        // 16
constexpr int Mc  = Bc * Sc;        // 8192

// ---------------------------------------------------------------------------
// Scratch (device globals)
// ---------------------------------------------------------------------------
__device__ float g_rs [BHc * Sc];
__device__ float g_y1 [Mc * Dc];
__device__ float g_att[Mc * Dc];
__device__ float g_y2 [Mc * Dc];

__device__ __half g_p  [(size_t)BHc * Sc * Sc];   // unnormalized P, fp16

__device__ __half g_xh [Mc * Dc];
__device__ __half g_qh [BHc * Sc * HDc];
__device__ __half g_kh [BHc * Sc * HDc];
__device__ __half g_ch [Mc * Dc];
__device__ __half g_ah [Mc * Dc];
__device__ __half g_zh [Mc * FFc];
__device__ __half g_wqh[Dc * Dc];
__device__ __half g_wkh[Dc * Dc];
__device__ __half g_wfh[Dc * Dc];
__device__ __half g_w1h[FFc * Dc];
__device__ __half g_w2h[Dc * FFc];

// ---------------------------------------------------------------------------
// Helpers
// ---------------------------------------------------------------------------
__device__ __forceinline__ uint32_t smem_u32(const void* p) {
    uint32_t a;
    asm("{ .reg .u64 t; cvta.to.shared.u64 t, %1; cvt.u32.u64 %0, t; }"
        : "=r"(a) : "l"(p));
    return a;
}
__device__ __forceinline__ void cp16(uint32_t saddr, const void* g) {
    asm volatile("cp.async.cg.shared.global [%0], [%1], 16;"
                 :: "r"(saddr), "l"(g) : "memory");
}
#define CP_COMMIT()  asm volatile("cp.async.commit_group;" ::: "memory")
#define CP_WAIT(n)   asm volatile("cp.async.wait_group %0;" :: "n"(n) : "memory")

__device__ __forceinline__ void ldsm_x4(uint32_t& r0, uint32_t& r1,
                                        uint32_t& r2, uint32_t& r3, uint32_t a) {
    asm volatile("ldmatrix.sync.aligned.m8n8.x4.shared.b16 {%0,%1,%2,%3}, [%4];"
                 : "=r"(r0), "=r"(r1), "=r"(r2), "=r"(r3) : "r"(a));
}
__device__ __forceinline__ void ldsm_x4_t(uint32_t& r0, uint32_t& r1,
                                          uint32_t& r2, uint32_t& r3, uint32_t a) {
    asm volatile("ldmatrix.sync.aligned.m8n8.x4.trans.shared.b16 {%0,%1,%2,%3}, [%4];"
                 : "=r"(r0), "=r"(r1), "=r"(r2), "=r"(r3) : "r"(a));
}

__device__ __forceinline__ void mma16816(float c[4],
        uint32_t a0, uint32_t a1, uint32_t a2, uint32_t a3,
        uint32_t b0, uint32_t b1) {
    asm volatile("mma.sync.aligned.m16n8k16.row.col.f32.f16.f16.f32 "
                 "{%0,%1,%2,%3}, {%4,%5,%6,%7}, {%8,%9}, {%0,%1,%2,%3};"
                 : "+f"(c[0]), "+f"(c[1]), "+f"(c[2]), "+f"(c[3])
                 : "r"(a0), "r"(a1), "r"(a2), "r"(a3), "r"(b0), "r"(b1));
}

__device__ __forceinline__ uint32_t pack_h(__half a, __half b) {
    return ((uint32_t)__half_as_ushort(b) << 16) | (uint32_t)__half_as_ushort(a);
}
__device__ __forceinline__ uint32_t pack_hf(float x, float y) {
    return pack_h(__float2half_rn(x), __float2half_rn(y));
}

// ---------------------------------------------------------------------------
// fp32 -> fp16 conversion
// ---------------------------------------------------------------------------
__global__ __launch_bounds__(256)
void cvt_hi(const float4* __restrict__ in, uint2* __restrict__ hi)
{
    size_t i = (size_t)blockIdx.x * 256 + threadIdx.x;
    float4 v = in[i];
    hi[i] = make_uint2(pack_hf(v.x, v.y), pack_hf(v.z, v.w));
}

// ---------------------------------------------------------------------------
// HMMA GEMM (fp16 x1), 3-stage cp.async.
// ---------------------------------------------------------------------------
constexpr int GP = 80;
constexpr int SM_A = 0, SM_W = 10240;
constexpr int GSTG = 20480;
constexpr int GEMM_SMEM3 = 3 * GSTG;           // 61440

template<int EPI>
__global__ __launch_bounds__(256, 2)
void gemm_mma(const __half* __restrict__ Ah,
              const __half* __restrict__ Wh,
              const float* __restrict__ res, float* __restrict__ Cf,
              __half* __restrict__ Ch,
              int N, int K)
{
    extern __shared__ __align__(16) char smd[];
    const uint32_t sb = smem_u32(smd);
    const int tid = threadIdx.x, lane = tid & 31, wid = tid >> 5;
    const int wm = wid >> 2, wn = wid & 3;
    const int m0 = blockIdx.y * 128, n0 = blockIdx.x * 128;
    const int NK = K >> 5;

    float acc[4][4][4];
    #pragma unroll
    for (int i = 0; i < 4; ++i)
        #pragma unroll
        for (int j = 0; j < 4; ++j)
            #pragma unroll
            for (int q = 0; q < 4; ++q) acc[i][j][q] = 0.f;

    auto issue = [&](int it, int stg) {
        uint32_t base = sb + stg * GSTG;
        #pragma unroll
        for (int i = 0; i < 2; ++i) {
            int c = tid + i * 256, row = c >> 2, part = c & 3;
            int so = row * GP + part * 16;
            size_t ga = (size_t)(m0 + row) * K + it * 32 + part * 8;
            size_t gw = (size_t)(n0 + row) * K + it * 32 + part * 8;
            cp16(base + SM_A + so, Ah + ga);
            cp16(base + SM_W + so, Wh + gw);
        }
        CP_COMMIT();
    };

    issue(0, 0);
    issue(1, 1);

    for (int it = 0; it < NK; ++it) {
        const int stg = it % 3;
        if (it + 2 < NK) { CP_WAIT(1); } else { CP_WAIT(0); }
        __syncthreads();
        if (it + 2 < NK) issue(it + 2, (it + 2) % 3);
        const uint32_t base = sb + stg * GSTG;

        #pragma unroll
        for (int ks = 0; ks < 2; ++ks) {
            uint32_t wh[4][2];
            #pragma unroll
            for (int nfp = 0; nfp < 2; ++nfp) {
                int ro = (wn * 32 + nfp * 16 + (lane & 15)) * GP + ks * 32 + (lane >> 4) * 16;
                uint32_t r0, r1, r2, r3;
                ldsm_x4(r0, r1, r2, r3, base + SM_W + ro);
                wh[nfp*2][0] = r0; wh[nfp*2+1][0] = r1;
                wh[nfp*2][1] = r2; wh[nfp*2+1][1] = r3;
            }
            #pragma unroll
            for (int mf = 0; mf < 4; ++mf) {
                int ro = (wm * 64 + mf * 16 + (lane & 15)) * GP + ks * 32 + (lane >> 4) * 16;
                uint32_t a0, a1, a2, a3;
                ldsm_x4(a0, a1, a2, a3, base + SM_A + ro);
                #pragma unroll
                for (int nf = 0; nf < 4; ++nf)
                    mma16816(acc[mf][nf], a0, a1, a2, a3, wh[nf][0], wh[nf][1]);
            }
        }
    }

    // epilogue
    #pragma unroll
    for (int mf = 0; mf < 4; ++mf) {
        int r0 = m0 + wm * 64 + mf * 16 + (lane >> 2);
        #pragma unroll
        for (int nf = 0; nf < 4; ++nf) {
            int c = n0 + wn * 32 + nf * 8 + (lane & 3) * 2;
            float v0 = acc[mf][nf][0], v1 = acc[mf][nf][1];
            float v2 = acc[mf][nf][2], v3 = acc[mf][nf][3];
            if (EPI == 3) {
                int hh = c >> 6, d = c & 63;
                int b0 = r0 >> 12, s0 = r0 & 4095;
                size_t o = (((size_t)(b0 * Hc + hh)) * Sc + s0) * HDc + d;
                int r1 = r0 + 8;
                int b1 = r1 >> 12, s1 = r1 & 4095;
                size_t o2 = (((size_t)(b1 * Hc + hh)) * Sc + s1) * HDc + d;
                *(uint32_t*)(Ch + o)  = pack_hf(v0, v1);
                *(uint32_t*)(Ch + o2) = pack_hf(v2, v3);
            } else if (EPI == 1) {
                size_t o = (size_t)r0 * N + c;
                float2 rr = *(const float2*)(res + o);
                *(float2*)(Cf + o) = make_float2(v0 + rr.x, v1 + rr.y);
                o = (size_t)(r0 + 8) * N + c;
                rr = *(const float2*)(res + o);
                *(float2*)(Cf + o) = make_float2(v2 + rr.x, v3 + rr.y);
            } else {
                size_t o = (size_t)r0 * N + c;
                *(uint32_t*)(Ch + o) = pack_hf(fmaxf(v0, 0.f), fmaxf(v1, 0.f));
                o = (size_t)(r0 + 8) * N + c;
                *(uint32_t*)(Ch + o) = pack_hf(fmaxf(v2, 0.f), fmaxf(v3, 0.f));
            }
        }
    }
}

// ---------------------------------------------------------------------------
// HMMA attention (fp16 x1), register-fragment PV:
// S = qh*kh. exp'd P packs serve BOTH the gmem store and the PV A-operand
// (C-fragment layout == A-fragment layout). Each warp computes a partial
// ctx over its 32-key half for the FULL 64 HD cols; one smem reduction at
// the end combines wn pairs. One __syncthreads per iteration.
// ---------------------------------------------------------------------------
constexpr int AP    = 144;
constexpr int A_QH  = 0;                        // 128*144 = 18432
constexpr int A_K0  = 18432;                    // 3 stages x 9216 -> end 46080
constexpr int A_RS  = 46080;                    // rowsums (512B)
constexpr int RPAD  = 66;                       // red row stride (floats)
constexpr int ATT_SMEM = 46080 + 512 + 16;      // red area reuses [0, 33792)

__global__ __launch_bounds__(256, 2)
void attn_mma()
{
    extern __shared__ __align__(16) char sm[];
    float* rsum = (float*)(sm + A_RS);
    float* red  = (float*)sm;                    // valid only after post-loop sync
    const uint32_t sb = smem_u32(sm);
    const int tid = threadIdx.x, lane = tid & 31, wid = tid >> 5;
    const int wm = wid >> 1, wn = wid & 1;       // 4 M-warps x 2 key-half warps
    const int bh = blockIdx.y, q0 = blockIdx.x * 128;
    constexpr int NKT = Sc / 64;

    const __half* Qh = g_qh + (size_t)bh * Sc * HDc;
    const __half* Kh = g_kh + (size_t)bh * Sc * HDc;

    auto issueK = [&](int kt, int stg) {
        uint32_t base = sb + A_K0 + stg * 9216;
        #pragma unroll
        for (int i = 0; i < 2; ++i) {
            int c = tid + i * 256, row = c >> 3, part = c & 7;
            cp16(base + row * AP + part * 16,
                 Kh + (size_t)(kt * 64 + row) * HDc + part * 8);
        }
        CP_COMMIT();
    };

    issueK(0, 0);
    issueK(1, 1);

    // Q tile 128x64 fp16 = 1024 16B-chunks
    #pragma unroll
    for (int i = 0; i < 4; ++i) {
        int c = tid + i * 256, row = c >> 3, part = c & 7;
        size_t g = (size_t)(q0 + row) * HDc + part * 8;
        *(uint4*)(sm + A_QH + row * AP + part * 16) = *(const uint4*)(Qh + g);
    }
    if (tid < 128) rsum[tid] = 0.f;

    // partial ctx: this warp's 32-key half x full 64 HD cols
    float ctx[2][8][4];
    #pragma unroll
    for (int i = 0; i < 2; ++i)
        #pragma unroll
        for (int j = 0; j < 8; ++j)
            #pragma unroll
            for (int q = 0; q < 4; ++q) ctx[i][j][q] = 0.f;
    float rs[2][2] = {{0.f, 0.f}, {0.f, 0.f}};

    for (int kt = 0; kt < NKT; ++kt) {
        const int stg = kt % 3;
        if (kt + 2 < NKT) { CP_WAIT(1); } else { CP_WAIT(0); }
        __syncthreads();   // K[stg] ready; all warps done with stage (kt+2)%3
        if (kt + 2 < NKT) issueK(kt + 2, (kt + 2) % 3);
        const uint32_t KB = sb + A_K0 + stg * 9216;

        // ---- S = qh*kh ----
        float s[2][4][4];
        #pragma unroll
        for (int i = 0; i < 2; ++i)
            #pragma unroll
            for (int j = 0; j < 4; ++j)
                #pragma unroll
                for (int q = 0; q < 4; ++q) s[i][j][q] = 0.f;

        #pragma unroll
        for (int ks = 0; ks < 4; ++ks) {
            uint32_t bhf[4][2];
            #pragma unroll
            for (int nfp = 0; nfp < 2; ++nfp) {
                int ro = (wn * 32 + nfp * 16 + (lane & 15)) * AP + ks * 32 + (lane >> 4) * 16;
                uint32_t r0, r1, r2, r3;
                ldsm_x4(r0, r1, r2, r3, KB + ro);
                bhf[nfp*2][0] = r0; bhf[nfp*2+1][0] = r1;
                bhf[nfp*2][1] = r2; bhf[nfp*2+1][1] = r3;
            }
            #pragma unroll
            for (int mf = 0; mf < 2; ++mf) {
                int ro = (wm * 32 + mf * 16 + (lane & 15)) * AP + ks * 32 + (lane >> 4) * 16;
                uint32_t a0, a1, a2, a3;
                ldsm_x4(a0, a1, a2, a3, sb + A_QH + ro);
                #pragma unroll
                for (int nf = 0; nf < 4; ++nf)
                    mma16816(s[mf][nf], a0, a1, a2, a3, bhf[nf][0], bhf[nf][1]);
            }
        }

        // ---- exp, rowsum, P gmem store; packs double as PV A fragments ----
        uint32_t qp[2][4][2];
        #pragma unroll
        for (int mf = 0; mf < 2; ++mf) {
            int rl = wm * 32 + mf * 16 + (lane >> 2);
            #pragma unroll
            for (int nf = 0; nf < 4; ++nf) {
                int cl_ = wn * 32 + nf * 8 + (lane & 3) * 2;
                float p0 = __expf(s[mf][nf][0] * 0.125f);
                float p1 = __expf(s[mf][nf][1] * 0.125f);
                float p2 = __expf(s[mf][nf][2] * 0.125f);
                float p3 = __expf(s[mf][nf][3] * 0.125f);
                rs[mf][0] += p0 + p1;
                rs[mf][1] += p2 + p3;
                uint32_t q01 = pack_hf(p0, p1);
                uint32_t q23 = pack_hf(p2, p3);
                size_t gr = ((size_t)bh * Sc + q0 + rl) * Sc + kt * 64 + cl_;
                *(uint32_t*)(g_p + gr) = q01;
                *(uint32_t*)(g_p + gr + (size_t)8 * Sc) = q23;
                qp[mf][nf][0] = q01;
                qp[mf][nf][1] = q23;
            }
        }

        // ---- partial ctx += P V over this warp's 32 keys (register A) ----
        #pragma unroll
        for (int ks2 = 0; ks2 < 2; ++ks2) {
            uint32_t vh[8][2];
            #pragma unroll
            for (int nfp = 0; nfp < 4; ++nfp) {
                int ro = (wn * 32 + ks2 * 16 + (lane & 15)) * AP
                       + nfp * 32 + (lane >> 4) * 16;
                uint32_t r0, r1, r2, r3;
                ldsm_x4_t(r0, r1, r2, r3, KB + ro);
                vh[nfp*2][0] = r0; vh[nfp*2][1] = r1;
                vh[nfp*2+1][0] = r2; vh[nfp*2+1][1] = r3;
            }
            #pragma unroll
            for (int mf = 0; mf < 2; ++mf) {
                uint32_t a0 = qp[mf][ks2*2][0],   a1 = qp[mf][ks2*2][1];
                uint32_t a2 = qp[mf][ks2*2+1][0], a3 = qp[mf][ks2*2+1][1];
                #pragma unroll
                for (int nf = 0; nf < 8; ++nf)
                    mma16816(ctx[mf][nf], a0, a1, a2, a3, vh[nf][0], vh[nf][1]);
            }
        }
    }

    // ---- rowsum reduce (cross-warp via atomics) ----
    #pragma unroll
    for (int mf = 0; mf < 2; ++mf)
        #pragma unroll
        for (int h = 0; h < 2; ++h) {
            float v = rs[mf][h];
            v += __shfl_xor_sync(0xffffffffu, v, 1);
            v += __shfl_xor_sync(0xffffffffu, v, 2);
            if ((lane & 3) == 0)
                atomicAdd(&rsum[wm * 32 + mf * 16 + h * 8 + (lane >> 2)], v);
        }

    // RACE FIX (R11 post-mortem): red overlaps Q/K-stage smem. All warps must
    // finish their final-iteration ldsm reads of K/Q before anyone overwrites
    // that region with reduction data.
    __syncthreads();

    // ---- wn=1 warps publish their partial ctx (smem, K/Q area reused) ----
    if (wn == 1) {
        #pragma unroll
        for (int mf = 0; mf < 2; ++mf) {
            int r = wm * 32 + mf * 16 + (lane >> 2);
            #pragma unroll
            for (int nf = 0; nf < 8; ++nf) {
                int c = nf * 8 + (lane & 3) * 2;
                *(float2*)&red[r * RPAD + c] =
                    make_float2(ctx[mf][nf][0], ctx[mf][nf][1]);
                *(float2*)&red[(r + 8) * RPAD + c] =
                    make_float2(ctx[mf][nf][2], ctx[mf][nf][3]);
            }
        }
    }
    __syncthreads();

    if (tid < 128) g_rs[(size_t)bh * Sc + q0 + tid] = rsum[tid];

    // ---- wn=0 warps: combine halves, normalize, store ctx (full HD) ----
    if (wn == 0) {
        const int bb = bh >> 3, hh = bh & 7;
        #pragma unroll
        for (int mf = 0; mf < 2; ++mf) {
            int rl = wm * 32 + mf * 16 + (lane >> 2);
            float i0 = 1.f / rsum[rl];
            float i1 = 1.f / rsum[rl + 8];
            #pragma unroll
            for (int nf = 0; nf < 8; ++nf) {
                int d = nf * 8 + (lane & 3) * 2;
                float2 o1 = *(float2*)&red[rl * RPAD + d];
                float2 o2 = *(float2*)&red[(rl + 8) * RPAD + d];
                size_t o = ((size_t)bb * Sc + q0 + rl) * Dc + hh * HDc + d;
                *(uint32_t*)(g_ch + o) =
                    pack_hf((ctx[mf][nf][0] + o1.x) * i0,
                            (ctx[mf][nf][1] + o1.y) * i0);
                o += (size_t)8 * Dc;
                *(uint32_t*)(g_ch + o) =
                    pack_hf((ctx[mf][nf][2] + o2.x) * i1,
                            (ctx[mf][nf][3] + o2.y) * i1);
            }
        }
    }
}

// ---------------------------------------------------------------------------
// attn = fp16 P / rowsum
// ---------------------------------------------------------------------------
__global__ __launch_bounds__(256)
void norm_attn(float* __restrict__ attn)
{
    size_t i = (size_t)blockIdx.x * 256 + threadIdx.x;   // uint2 index (4 halves)
    size_t row = (i * 4) >> 12;
    float inv = 1.0f / g_rs[row];
    uint2 pv = ((const uint2*)g_p)[i];
    __half2 a = *(__half2*)&pv.x;
    __half2 b = *(__half2*)&pv.y;
    float2 fa = __half22float2(a);
    float2 fb = __half22float2(b);
    float4 o;
    o.x = fa.x * inv; o.y = fa.y * inv;
    o.z = fb.x * inv; o.w = fb.y * inv;
    ((float4*)attn)[i] = o;
}

// ---------------------------------------------------------------------------
// LayerNorm; optionally emits fp16 copy
// ---------------------------------------------------------------------------
template<bool SPLIT>
__global__ __launch_bounds__(128)
void ln_kernel(const float* __restrict__ X, const float* __restrict__ gw,
               const float* __restrict__ bw, float* __restrict__ Y,
               __half* __restrict__ Yh)
{
    const int row = blockIdx.x;
    const int tid = threadIdx.x;
    float4 v = ((const float4*)(X + (size_t)row * Dc))[tid];
    float s = (v.x + v.y) + (v.z + v.w);
    float q = (v.x*v.x + v.y*v.y) + (v.z*v.z + v.w*v.w);
    #pragma unroll
    for (int o = 16; o; o >>= 1) {
        s += __shfl_xor_sync(0xffffffffu, s, o);
        q += __shfl_xor_sync(0xffffffffu, q, o);
    }
    __shared__ float ss[4], sq[4];
    if ((tid & 31) == 0) { ss[tid >> 5] = s; sq[tid >> 5] = q; }
    __syncthreads();
    s = ss[0] + ss[1] + ss[2] + ss[3];
    q = sq[0] + sq[1] + sq[2] + sq[3];
    const float mu  = s * (1.0f / Dc);
    const float var = q * (1.0f / Dc) - mu * mu;
    const float inv = rsqrtf(var + 1e-5f);
    float4 g4 = ((const float4*)gw)[tid];
    float4 b4 = ((const float4*)bw)[tid];
    float4 o4;
    o4.x = (v.x - mu) * inv * g4.x + b4.x;
    o4.y = (v.y - mu) * inv * g4.y + b4.y;
    o4.z = (v.z - mu) * inv * g4.z + b4.z;
    o4.w = (v.w - mu) * inv * g4.w + b4.w;
    ((float4*)(Y + (size_t)row * Dc))[tid] = o4;
    if (SPLIT) {
        size_t o = (size_t)row * Dc + tid * 4;
        *(uint32_t*)(Yh + o)     = pack_hf(o4.x, o4.y);
        *(uint32_t*)(Yh + o + 2) = pack_hf(o4.z, o4.w);
    }
}

// ---------------------------------------------------------------------------
extern "C" void kernel_launch(void* const* d_in, const int* in_sizes, int n_in,
                              void* d_out, int out_size)
{
    const float* x    = (const float*)d_in[0];
    const float* Wq   = (const float*)d_in[2];
    const float* Wk   = (const float*)d_in[3];
    const float* Wfc  = (const float*)d_in[5];
    const float* Wff1 = (const float*)d_in[6];
    const float* Wff2 = (const float*)d_in[7];
    const float* g1   = (const float*)d_in[8];
    const float* b1   = (const float*)d_in[9];
    const float* g2   = (const float*)d_in[10];
    const float* b2   = (const float*)d_in[11];

    float* out_feed = (float*)d_out;
    float* out_attn = (float*)d_out + (size_t)Mc * Dc;

    float *pY1, *pAtt, *pY2;
    cudaGetSymbolAddress((void**)&pY1,  g_y1);
    cudaGetSymbolAddress((void**)&pAtt, g_att);
    cudaGetSymbolAddress((void**)&pY2,  g_y2);

    __half *xh,*qh,*kh,*ch,*ah,*zh;
    __half *wqh,*wkh,*wfh,*w1h,*w2h;
    cudaGetSymbolAddress((void**)&xh,  g_xh);
    cudaGetSymbolAddress((void**)&qh,  g_qh);
    cudaGetSymbolAddress((void**)&kh,  g_kh);
    cudaGetSymbolAddress((void**)&ch,  g_ch);
    cudaGetSymbolAddress((void**)&ah,  g_ah);
    cudaGetSymbolAddress((void**)&zh,  g_zh);
    cudaGetSymbolAddress((void**)&wqh, g_wqh);
    cudaGetSymbolAddress((void**)&wkh, g_wkh);
    cudaGetSymbolAddress((void**)&wfh, g_wfh);
    cudaGetSymbolAddress((void**)&w1h, g_w1h);
    cudaGetSymbolAddress((void**)&w2h, g_w2h);

    cudaFuncSetAttribute(attn_mma,
                         cudaFuncAttributeMaxDynamicSharedMemorySize, ATT_SMEM);
    cudaFuncSetAttribute(gemm_mma<1>,
                         cudaFuncAttributeMaxDynamicSharedMemorySize, GEMM_SMEM3);
    cudaFuncSetAttribute(gemm_mma<2>,
                         cudaFuncAttributeMaxDynamicSharedMemorySize, GEMM_SMEM3);
    cudaFuncSetAttribute(gemm_mma<3>,
                         cudaFuncAttributeMaxDynamicSharedMemorySize, GEMM_SMEM3);

    // One-time side-stream resources
    static cudaStream_t s2 = nullptr;
    static cudaEvent_t  eFork = nullptr, eJoin = nullptr, eW = nullptr;
    static cudaEvent_t  eX = nullptr, eK = nullptr;
    if (s2 == nullptr) {
        cudaStreamCreateWithFlags(&s2, cudaStreamNonBlocking);
        cudaEventCreateWithFlags(&eFork, cudaEventDisableTiming);
        cudaEventCreateWithFlags(&eJoin, cudaEventDisableTiming);
        cudaEventCreateWithFlags(&eW,    cudaEventDisableTiming);
        cudaEventCreateWithFlags(&eX,    cudaEventDisableTiming);
        cudaEventCreateWithFlags(&eK,    cudaEventDisableTiming);
    }

    // 0. x -> fp16 on main; weights -> fp16 on side stream
    cudaEventRecord(eFork, 0);
    cudaStreamWaitEvent(s2, eFork, 0);
    cvt_hi<<<(unsigned)((size_t)Mc * Dc / 1024), 256>>>((const float4*)x, (uint2*)xh);
    cudaEventRecord(eX, 0);
    auto cvtW = [&](const float* w, __half* hi, size_t n) {
        cvt_hi<<<(unsigned)(n / 1024), 256, 0, s2>>>((const float4*)w, (uint2*)hi);
    };
    cvtW(Wq,   wqh, (size_t)Dc * Dc);
    cvtW(Wk,   wkh, (size_t)Dc * Dc);
    cvtW(Wfc,  wfh, (size_t)Dc * Dc);
    cvtW(Wff1, w1h, (size_t)FFc * Dc);
    cvtW(Wff2, w2h, (size_t)Dc * FFc);
    cudaEventRecord(eW, s2);
    cudaStreamWaitEvent(0, eW, 0);      // main needs weights for Q proj
    cudaStreamWaitEvent(s2, eX, 0);     // s2 needs xh for K proj

    // 1. Q proj on main || K proj on s2 (both permuted fp16)
    gemm_mma<3><<<dim3(Dc/128, Mc/128), 256, GEMM_SMEM3>>>(xh, wqh, nullptr, nullptr, qh, Dc, Dc);
    gemm_mma<3><<<dim3(Dc/128, Mc/128), 256, GEMM_SMEM3, s2>>>(xh, wkh, nullptr, nullptr, kh, Dc, Dc);
    cudaEventRecord(eK, s2);
    cudaStreamWaitEvent(0, eK, 0);

    // 2. Attention (fp16 unnormalized P to scratch + ctx fp16)
    attn_mma<<<dim3(Sc/128, BHc), 256, ATT_SMEM>>>();

    // Fork: normalize attn (fp16 -> fp32) on side stream, concurrent with FFN
    cudaEventRecord(eFork, 0);
    cudaStreamWaitEvent(s2, eFork, 0);
    {
        size_t n4 = (size_t)BHc * Sc * Sc / 4;
        norm_attn<<<(unsigned)(n4 / 256), 256, 0, s2>>>(out_attn);
    }

    // 3. y1 = x + ctx@Wfc^T ; att = LN(y1) (+ fp16)
    gemm_mma<1><<<dim3(Dc/128, Mc/128), 256, GEMM_SMEM3>>>(ch, wfh, x, pY1, nullptr, Dc, Dc);
    ln_kernel<true><<<Mc, 128>>>(pY1, g1, b1, pAtt, ah);

    // 4. z = relu(att@Wff1^T) ; y2 = att + z@Wff2^T ; out = LN(y2)
    gemm_mma<2><<<dim3(FFc/128, Mc/128), 256, GEMM_SMEM3>>>(ah, w1h, nullptr, nullptr, zh, FFc, Dc);
    gemm_mma<1><<<dim3(Dc/128, Mc/128), 256, GEMM_SMEM3>>>(zh, w2h, pAtt, pY2, nullptr, Dc, FFc);
    ln_kernel<false><<<Mc, 128>>>(pY2, g2, b2, out_feed, nullptr);

    // Join: main stream waits for norm_attn
    cudaEventRecord(eJoin, s2);
    cudaStreamWaitEvent(0, eJoin, 0);
}

// round 13
// speedup vs baseline: 4.1312x; 1.0010x over previous
#include <cuda_runtime.h>
#include <cuda_fp16.h>
#include <math.h>
#include <stdint.h>

// Problem constants
constexpr int Bc  = 2;
constexpr int Sc  = 4096;
constexpr int Dc  = 512;
constexpr int Hc  = 8;
constexpr int HDc = 64;
constexpr int FFc = 2048;
constexpr int BHc = Bc * Hc;        // 16
constexpr int Mc  = Bc * Sc;        // 8192

// ---------------------------------------------------------------------------
// Scratch (device globals)
// ---------------------------------------------------------------------------
__device__ float g_rs [BHc * Sc];
__device__ float g_y1 [Mc * Dc];
__device__ float g_att[Mc * Dc];
__device__ float g_y2 [Mc * Dc];

__device__ __half g_p  [(size_t)BHc * Sc * Sc];   // unnormalized P, fp16

__device__ __half g_xh [Mc * Dc];
__device__ __half g_qh [BHc * Sc * HDc];
__device__ __half g_kh [BHc * Sc * HDc];
__device__ __half g_ch [Mc * Dc];
__device__ __half g_ah [Mc * Dc];
__device__ __half g_zh [Mc * FFc];
__device__ __half g_wqh[Dc * Dc];
__device__ __half g_wkh[Dc * Dc];
__device__ __half g_wfh[Dc * Dc];
__device__ __half g_w1h[FFc * Dc];
__device__ __half g_w2h[Dc * FFc];

// ---------------------------------------------------------------------------
// Helpers
// ---------------------------------------------------------------------------
__device__ __forceinline__ uint32_t smem_u32(const void* p) {
    uint32_t a;
    asm("{ .reg .u64 t; cvta.to.shared.u64 t, %1; cvt.u32.u64 %0, t; }"
        : "=r"(a) : "l"(p));
    return a;
}
__device__ __forceinline__ void cp16(uint32_t saddr, const void* g) {
    asm volatile("cp.async.cg.shared.global [%0], [%1], 16;"
                 :: "r"(saddr), "l"(g) : "memory");
}
#define CP_COMMIT()  asm volatile("cp.async.commit_group;" ::: "memory")
#define CP_WAIT(n)   asm volatile("cp.async.wait_group %0;" :: "n"(n) : "memory")

__device__ __forceinline__ void ldsm_x4(uint32_t& r0, uint32_t& r1,
                                        uint32_t& r2, uint32_t& r3, uint32_t a) {
    asm volatile("ldmatrix.sync.aligned.m8n8.x4.shared.b16 {%0,%1,%2,%3}, [%4];"
                 : "=r"(r0), "=r"(r1), "=r"(r2), "=r"(r3) : "r"(a));
}
__device__ __forceinline__ void ldsm_x4_t(uint32_t& r0, uint32_t& r1,
                                          uint32_t& r2, uint32_t& r3, uint32_t a) {
    asm volatile("ldmatrix.sync.aligned.m8n8.x4.trans.shared.b16 {%0,%1,%2,%3}, [%4];"
                 : "=r"(r0), "=r"(r1), "=r"(r2), "=r"(r3) : "r"(a));
}

__device__ __forceinline__ void mma16816(float c[4],
        uint32_t a0, uint32_t a1, uint32_t a2, uint32_t a3,
        uint32_t b0, uint32_t b1) {
    asm volatile("mma.sync.aligned.m16n8k16.row.col.f32.f16.f16.f32 "
                 "{%0,%1,%2,%3}, {%4,%5,%6,%7}, {%8,%9}, {%0,%1,%2,%3};"
                 : "+f"(c[0]), "+f"(c[1]), "+f"(c[2]), "+f"(c[3])
                 : "r"(a0), "r"(a1), "r"(a2), "r"(a3), "r"(b0), "r"(b1));
}

__device__ __forceinline__ uint32_t pack_h(__half a, __half b) {
    return ((uint32_t)__half_as_ushort(b) << 16) | (uint32_t)__half_as_ushort(a);
}
__device__ __forceinline__ uint32_t pack_hf(float x, float y) {
    return pack_h(__float2half_rn(x), __float2half_rn(y));
}

// ---------------------------------------------------------------------------
// fp32 -> fp16 conversion
// ---------------------------------------------------------------------------
__global__ __launch_bounds__(256)
void cvt_hi(const float4* __restrict__ in, uint2* __restrict__ hi)
{
    size_t i = (size_t)blockIdx.x * 256 + threadIdx.x;
    float4 v = in[i];
    hi[i] = make_uint2(pack_hf(v.x, v.y), pack_hf(v.z, v.w));
}

// ---------------------------------------------------------------------------
// HMMA GEMM (fp16 x1), 3-stage cp.async. (unchanged)
// ---------------------------------------------------------------------------
constexpr int GP = 80;
constexpr int SM_A = 0, SM_W = 10240;
constexpr int GSTG = 20480;
constexpr int GEMM_SMEM3 = 3 * GSTG;           // 61440

template<int EPI>
__global__ __launch_bounds__(256, 2)
void gemm_mma(const __half* __restrict__ Ah,
              const __half* __restrict__ Wh,
              const float* __restrict__ res, float* __restrict__ Cf,
              __half* __restrict__ Ch,
              int N, int K)
{
    extern __shared__ __align__(16) char smd[];
    const uint32_t sb = smem_u32(smd);
    const int tid = threadIdx.x, lane = tid & 31, wid = tid >> 5;
    const int wm = wid >> 2, wn = wid & 3;
    const int m0 = blockIdx.y * 128, n0 = blockIdx.x * 128;
    const int NK = K >> 5;

    float acc[4][4][4];
    #pragma unroll
    for (int i = 0; i < 4; ++i)
        #pragma unroll
        for (int j = 0; j < 4; ++j)
            #pragma unroll
            for (int q = 0; q < 4; ++q) acc[i][j][q] = 0.f;

    auto issue = [&](int it, int stg) {
        uint32_t base = sb + stg * GSTG;
        #pragma unroll
        for (int i = 0; i < 2; ++i) {
            int c = tid + i * 256, row = c >> 2, part = c & 3;
            int so = row * GP + part * 16;
            size_t ga = (size_t)(m0 + row) * K + it * 32 + part * 8;
            size_t gw = (size_t)(n0 + row) * K + it * 32 + part * 8;
            cp16(base + SM_A + so, Ah + ga);
            cp16(base + SM_W + so, Wh + gw);
        }
        CP_COMMIT();
    };

    issue(0, 0);
    issue(1, 1);

    for (int it = 0; it < NK; ++it) {
        const int stg = it % 3;
        if (it + 2 < NK) { CP_WAIT(1); } else { CP_WAIT(0); }
        __syncthreads();
        if (it + 2 < NK) issue(it + 2, (it + 2) % 3);
        const uint32_t base = sb + stg * GSTG;

        #pragma unroll
        for (int ks = 0; ks < 2; ++ks) {
            uint32_t wh[4][2];
            #pragma unroll
            for (int nfp = 0; nfp < 2; ++nfp) {
                int ro = (wn * 32 + nfp * 16 + (lane & 15)) * GP + ks * 32 + (lane >> 4) * 16;
                uint32_t r0, r1, r2, r3;
                ldsm_x4(r0, r1, r2, r3, base + SM_W + ro);
                wh[nfp*2][0] = r0; wh[nfp*2+1][0] = r1;
                wh[nfp*2][1] = r2; wh[nfp*2+1][1] = r3;
            }
            #pragma unroll
            for (int mf = 0; mf < 4; ++mf) {
                int ro = (wm * 64 + mf * 16 + (lane & 15)) * GP + ks * 32 + (lane >> 4) * 16;
                uint32_t a0, a1, a2, a3;
                ldsm_x4(a0, a1, a2, a3, base + SM_A + ro);
                #pragma unroll
                for (int nf = 0; nf < 4; ++nf)
                    mma16816(acc[mf][nf], a0, a1, a2, a3, wh[nf][0], wh[nf][1]);
            }
        }
    }

    // epilogue
    #pragma unroll
    for (int mf = 0; mf < 4; ++mf) {
        int r0 = m0 + wm * 64 + mf * 16 + (lane >> 2);
        #pragma unroll
        for (int nf = 0; nf < 4; ++nf) {
            int c = n0 + wn * 32 + nf * 8 + (lane & 3) * 2;
            float v0 = acc[mf][nf][0], v1 = acc[mf][nf][1];
            float v2 = acc[mf][nf][2], v3 = acc[mf][nf][3];
            if (EPI == 3) {
                int hh = c >> 6, d = c & 63;
                int b0 = r0 >> 12, s0 = r0 & 4095;
                size_t o = (((size_t)(b0 * Hc + hh)) * Sc + s0) * HDc + d;
                int r1 = r0 + 8;
                int b1 = r1 >> 12, s1 = r1 & 4095;
                size_t o2 = (((size_t)(b1 * Hc + hh)) * Sc + s1) * HDc + d;
                *(uint32_t*)(Ch + o)  = pack_hf(v0, v1);
                *(uint32_t*)(Ch + o2) = pack_hf(v2, v3);
            } else if (EPI == 1) {
                size_t o = (size_t)r0 * N + c;
                float2 rr = *(const float2*)(res + o);
                *(float2*)(Cf + o) = make_float2(v0 + rr.x, v1 + rr.y);
                o = (size_t)(r0 + 8) * N + c;
                rr = *(const float2*)(res + o);
                *(float2*)(Cf + o) = make_float2(v2 + rr.x, v3 + rr.y);
            } else {
                size_t o = (size_t)r0 * N + c;
                *(uint32_t*)(Ch + o) = pack_hf(fmaxf(v0, 0.f), fmaxf(v1, 0.f));
                o = (size_t)(r0 + 8) * N + c;
                *(uint32_t*)(Ch + o) = pack_hf(fmaxf(v2, 0.f), fmaxf(v3, 0.f));
            }
        }
    }
}

// ---------------------------------------------------------------------------
// HMMA attention (fp16 x1), 8 M-warps, register-fragment PV:
// Each warp owns 16 query rows x full 64 keys x full 64 HD cols.
// No cross-warp reduction; rowsums reduce within the quad (2 shfls).
// Live regs ~100 -> fits the 128-reg cap at occupancy 2 (no spills).
// ---------------------------------------------------------------------------
constexpr int AP    = 144;
constexpr int A_QH  = 0;                        // 128*144 = 18432
constexpr int A_K0  = 18432;                    // 3 stages x 9216 -> end 46080
constexpr int ATT_SMEM = 46080 + 16;

__global__ __launch_bounds__(256, 2)
void attn_mma()
{
    extern __shared__ __align__(16) char sm[];
    const uint32_t sb = smem_u32(sm);
    const int tid = threadIdx.x, lane = tid & 31, wid = tid >> 5;  // wid 0..7
    const int bh = blockIdx.y, q0 = blockIdx.x * 128;
    constexpr int NKT = Sc / 64;

    const __half* Qh = g_qh + (size_t)bh * Sc * HDc;
    const __half* Kh = g_kh + (size_t)bh * Sc * HDc;

    auto issueK = [&](int kt, int stg) {
        uint32_t base = sb + A_K0 + stg * 9216;
        #pragma unroll
        for (int i = 0; i < 2; ++i) {
            int c = tid + i * 256, row = c >> 3, part = c & 7;
            cp16(base + row * AP + part * 16,
                 Kh + (size_t)(kt * 64 + row) * HDc + part * 8);
        }
        CP_COMMIT();
    };

    issueK(0, 0);
    issueK(1, 1);

    // Q tile 128x64 fp16 = 1024 16B-chunks
    #pragma unroll
    for (int i = 0; i < 4; ++i) {
        int c = tid + i * 256, row = c >> 3, part = c & 7;
        size_t g = (size_t)(q0 + row) * HDc + part * 8;
        *(uint4*)(sm + A_QH + row * AP + part * 16) = *(const uint4*)(Qh + g);
    }

    float ctx[8][4];
    #pragma unroll
    for (int j = 0; j < 8; ++j)
        #pragma unroll
        for (int q = 0; q < 4; ++q) ctx[j][q] = 0.f;
    float rs0 = 0.f, rs1 = 0.f;

    const int rl = wid * 16 + (lane >> 2);       // this thread's query row (and +8)

    for (int kt = 0; kt < NKT; ++kt) {
        const int stg = kt % 3;
        if (kt + 2 < NKT) { CP_WAIT(1); } else { CP_WAIT(0); }
        __syncthreads();   // K[stg] ready; all warps done with stage (kt+2)%3
        if (kt + 2 < NKT) issueK(kt + 2, (kt + 2) % 3);
        const uint32_t KB = sb + A_K0 + stg * 9216;

        // ---- S = qh*kh : 16 queries x 64 keys ----
        float s[8][4];
        #pragma unroll
        for (int j = 0; j < 8; ++j)
            #pragma unroll
            for (int q = 0; q < 4; ++q) s[j][q] = 0.f;

        #pragma unroll
        for (int ks = 0; ks < 4; ++ks) {
            uint32_t bhf[8][2];
            #pragma unroll
            for (int nfp = 0; nfp < 4; ++nfp) {
                int ro = (nfp * 16 + (lane & 15)) * AP + ks * 32 + (lane >> 4) * 16;
                uint32_t r0, r1, r2, r3;
                ldsm_x4(r0, r1, r2, r3, KB + ro);
                bhf[nfp*2][0] = r0; bhf[nfp*2+1][0] = r1;
                bhf[nfp*2][1] = r2; bhf[nfp*2+1][1] = r3;
            }
            int ro = (wid * 16 + (lane & 15)) * AP + ks * 32 + (lane >> 4) * 16;
            uint32_t a0, a1, a2, a3;
            ldsm_x4(a0, a1, a2, a3, sb + A_QH + ro);
            #pragma unroll
            for (int nf = 0; nf < 8; ++nf)
                mma16816(s[nf], a0, a1, a2, a3, bhf[nf][0], bhf[nf][1]);
        }

        // ---- exp, rowsum, P gmem store; packs double as PV A fragments ----
        uint32_t qp[8][2];
        #pragma unroll
        for (int nf = 0; nf < 8; ++nf) {
            int cl_ = nf * 8 + (lane & 3) * 2;
            float p0 = __expf(s[nf][0] * 0.125f);
            float p1 = __expf(s[nf][1] * 0.125f);
            float p2 = __expf(s[nf][2] * 0.125f);
            float p3 = __expf(s[nf][3] * 0.125f);
            rs0 += p0 + p1;
            rs1 += p2 + p3;
            uint32_t q01 = pack_hf(p0, p1);
            uint32_t q23 = pack_hf(p2, p3);
            size_t gr = ((size_t)bh * Sc + q0 + rl) * Sc + kt * 64 + cl_;
            *(uint32_t*)(g_p + gr) = q01;
            *(uint32_t*)(g_p + gr + (size_t)8 * Sc) = q23;
            qp[nf][0] = q01;
            qp[nf][1] = q23;
        }

        // ---- ctx += P V over all 64 keys (register A fragments) ----
        #pragma unroll
        for (int ks2 = 0; ks2 < 4; ++ks2) {
            uint32_t vh[8][2];
            #pragma unroll
            for (int nfp = 0; nfp < 4; ++nfp) {
                int ro = (ks2 * 16 + (lane & 15)) * AP + nfp * 32 + (lane >> 4) * 16;
                uint32_t r0, r1, r2, r3;
                ldsm_x4_t(r0, r1, r2, r3, KB + ro);
                vh[nfp*2][0] = r0; vh[nfp*2][1] = r1;
                vh[nfp*2+1][0] = r2; vh[nfp*2+1][1] = r3;
            }
            uint32_t a0 = qp[2*ks2][0],   a1 = qp[2*ks2][1];
            uint32_t a2 = qp[2*ks2+1][0], a3 = qp[2*ks2+1][1];
            #pragma unroll
            for (int nf = 0; nf < 8; ++nf)
                mma16816(ctx[nf], a0, a1, a2, a3, vh[nf][0], vh[nf][1]);
        }
    }

    // ---- rowsum reduce within quad (rows owned by a single warp) ----
    rs0 += __shfl_xor_sync(0xffffffffu, rs0, 1);
    rs0 += __shfl_xor_sync(0xffffffffu, rs0, 2);
    rs1 += __shfl_xor_sync(0xffffffffu, rs1, 1);
    rs1 += __shfl_xor_sync(0xffffffffu, rs1, 2);

    if ((lane & 3) == 0) {
        g_rs[(size_t)bh * Sc + q0 + rl]     = rs0;
        g_rs[(size_t)bh * Sc + q0 + rl + 8] = rs1;
    }

    // ---- normalize and store ctx (fp16, head-merged layout) ----
    const int bb = bh >> 3, hh = bh & 7;
    float i0 = 1.f / rs0;
    float i1 = 1.f / rs1;
    #pragma unroll
    for (int nf = 0; nf < 8; ++nf) {
        int d = nf * 8 + (lane & 3) * 2;
        size_t o = ((size_t)bb * Sc + q0 + rl) * Dc + hh * HDc + d;
        *(uint32_t*)(g_ch + o) = pack_hf(ctx[nf][0] * i0, ctx[nf][1] * i0);
        o += (size_t)8 * Dc;
        *(uint32_t*)(g_ch + o) = pack_hf(ctx[nf][2] * i1, ctx[nf][3] * i1);
    }
}

// ---------------------------------------------------------------------------
// attn = fp16 P / rowsum
// ---------------------------------------------------------------------------
__global__ __launch_bounds__(256)
void norm_attn(float* __restrict__ attn)
{
    size_t i = (size_t)blockIdx.x * 256 + threadIdx.x;   // uint2 index (4 halves)
    size_t row = (i * 4) >> 12;
    float inv = 1.0f / g_rs[row];
    uint2 pv = ((const uint2*)g_p)[i];
    __half2 a = *(__half2*)&pv.x;
    __half2 b = *(__half2*)&pv.y;
    float2 fa = __half22float2(a);
    float2 fb = __half22float2(b);
    float4 o;
    o.x = fa.x * inv; o.y = fa.y * inv;
    o.z = fb.x * inv; o.w = fb.y * inv;
    ((float4*)attn)[i] = o;
}

// ---------------------------------------------------------------------------
// LayerNorm; optionally emits fp16 copy
// ---------------------------------------------------------------------------
template<bool SPLIT>
__global__ __launch_bounds__(128)
void ln_kernel(const float* __restrict__ X, const float* __restrict__ gw,
               const float* __restrict__ bw, float* __restrict__ Y,
               __half* __restrict__ Yh)
{
    const int row = blockIdx.x;
    const int tid = threadIdx.x;
    float4 v = ((const float4*)(X + (size_t)row * Dc))[tid];
    float s = (v.x + v.y) + (v.z + v.w);
    float q = (v.x*v.x + v.y*v.y) + (v.z*v.z + v.w*v.w);
    #pragma unroll
    for (int o = 16; o; o >>= 1) {
        s += __shfl_xor_sync(0xffffffffu, s, o);
        q += __shfl_xor_sync(0xffffffffu, q, o);
    }
    __shared__ float ss[4], sq[4];
    if ((tid & 31) == 0) { ss[tid >> 5] = s; sq[tid >> 5] = q; }
    __syncthreads();
    s = ss[0] + ss[1] + ss[2] + ss[3];
    q = sq[0] + sq[1] + sq[2] + sq[3];
    const float mu  = s * (1.0f / Dc);
    const float var = q * (1.0f / Dc) - mu * mu;
    const float inv = rsqrtf(var + 1e-5f);
    float4 g4 = ((const float4*)gw)[tid];
    float4 b4 = ((const float4*)bw)[tid];
    float4 o4;
    o4.x = (v.x - mu) * inv * g4.x + b4.x;
    o4.y = (v.y - mu) * inv * g4.y + b4.y;
    o4.z = (v.z - mu) * inv * g4.z + b4.z;
    o4.w = (v.w - mu) * inv * g4.w + b4.w;
    ((float4*)(Y + (size_t)row * Dc))[tid] = o4;
    if (SPLIT) {
        size_t o = (size_t)row * Dc + tid * 4;
        *(uint32_t*)(Yh + o)     = pack_hf(o4.x, o4.y);
        *(uint32_t*)(Yh + o + 2) = pack_hf(o4.z, o4.w);
    }
}

// ---------------------------------------------------------------------------
extern "C" void kernel_launch(void* const* d_in, const int* in_sizes, int n_in,
                              void* d_out, int out_size)
{
    const float* x    = (const float*)d_in[0];
    const float* Wq   = (const float*)d_in[2];
    const float* Wk   = (const float*)d_in[3];
    const float* Wfc  = (const float*)d_in[5];
    const float* Wff1 = (const float*)d_in[6];
    const float* Wff2 = (const float*)d_in[7];
    const float* g1   = (const float*)d_in[8];
    const float* b1   = (const float*)d_in[9];
    const float* g2   = (const float*)d_in[10];
    const float* b2   = (const float*)d_in[11];

    float* out_feed = (float*)d_out;
    float* out_attn = (float*)d_out + (size_t)Mc * Dc;

    float *pY1, *pAtt, *pY2;
    cudaGetSymbolAddress((void**)&pY1,  g_y1);
    cudaGetSymbolAddress((void**)&pAtt, g_att);
    cudaGetSymbolAddress((void**)&pY2,  g_y2);

    __half *xh,*qh,*kh,*ch,*ah,*zh;
    __half *wqh,*wkh,*wfh,*w1h,*w2h;
    cudaGetSymbolAddress((void**)&xh,  g_xh);
    cudaGetSymbolAddress((void**)&qh,  g_qh);
    cudaGetSymbolAddress((void**)&kh,  g_kh);
    cudaGetSymbolAddress((void**)&ch,  g_ch);
    cudaGetSymbolAddress((void**)&ah,  g_ah);
    cudaGetSymbolAddress((void**)&zh,  g_zh);
    cudaGetSymbolAddress((void**)&wqh, g_wqh);
    cudaGetSymbolAddress((void**)&wkh, g_wkh);
    cudaGetSymbolAddress((void**)&wfh, g_wfh);
    cudaGetSymbolAddress((void**)&w1h, g_w1h);
    cudaGetSymbolAddress((void**)&w2h, g_w2h);

    cudaFuncSetAttribute(attn_mma,
                         cudaFuncAttributeMaxDynamicSharedMemorySize, ATT_SMEM);
    cudaFuncSetAttribute(gemm_mma<1>,
                         cudaFuncAttributeMaxDynamicSharedMemorySize, GEMM_SMEM3);
    cudaFuncSetAttribute(gemm_mma<2>,
                         cudaFuncAttributeMaxDynamicSharedMemorySize, GEMM_SMEM3);
    cudaFuncSetAttribute(gemm_mma<3>,
                         cudaFuncAttributeMaxDynamicSharedMemorySize, GEMM_SMEM3);

    // One-time side-stream resources
    static cudaStream_t s2 = nullptr;
    static cudaEvent_t  eFork = nullptr, eJoin = nullptr, eW = nullptr;
    static cudaEvent_t  eX = nullptr, eK = nullptr;
    if (s2 == nullptr) {
        cudaStreamCreateWithFlags(&s2, cudaStreamNonBlocking);
        cudaEventCreateWithFlags(&eFork, cudaEventDisableTiming);
        cudaEventCreateWithFlags(&eJoin, cudaEventDisableTiming);
        cudaEventCreateWithFlags(&eW,    cudaEventDisableTiming);
        cudaEventCreateWithFlags(&eX,    cudaEventDisableTiming);
        cudaEventCreateWithFlags(&eK,    cudaEventDisableTiming);
    }

    // 0. x -> fp16 on main; weights -> fp16 on side stream
    cudaEventRecord(eFork, 0);
    cudaStreamWaitEvent(s2, eFork, 0);
    cvt_hi<<<(unsigned)((size_t)Mc * Dc / 1024), 256>>>((const float4*)x, (uint2*)xh);
    cudaEventRecord(eX, 0);
    auto cvtW = [&](const float* w, __half* hi, size_t n) {
        cvt_hi<<<(unsigned)(n / 1024), 256, 0, s2>>>((const float4*)w, (uint2*)hi);
    };
    cvtW(Wq,   wqh, (size_t)Dc * Dc);
    cvtW(Wk,   wkh, (size_t)Dc * Dc);
    cvtW(Wfc,  wfh, (size_t)Dc * Dc);
    cvtW(Wff1, w1h, (size_t)FFc * Dc);
    cvtW(Wff2, w2h, (size_t)Dc * FFc);
    cudaEventRecord(eW, s2);
    cudaStreamWaitEvent(0, eW, 0);      // main needs weights for Q proj
    cudaStreamWaitEvent(s2, eX, 0);     // s2 needs xh for K proj

    // 1. Q proj on main || K proj on s2 (both permuted fp16)
    gemm_mma<3><<<dim3(Dc/128, Mc/128), 256, GEMM_SMEM3>>>(xh, wqh, nullptr, nullptr, qh, Dc, Dc);
    gemm_mma<3><<<dim3(Dc/128, Mc/128), 256, GEMM_SMEM3, s2>>>(xh, wkh, nullptr, nullptr, kh, Dc, Dc);
    cudaEventRecord(eK, s2);
    cudaStreamWaitEvent(0, eK, 0);

    // 2. Attention (fp16 unnormalized P to scratch + ctx fp16)
    attn_mma<<<dim3(Sc/128, BHc), 256, ATT_SMEM>>>();

    // Fork: normalize attn (fp16 -> fp32) on side stream, concurrent with FFN
    cudaEventRecord(eFork, 0);
    cudaStreamWaitEvent(s2, eFork, 0);
    {
        size_t n4 = (size_t)BHc * Sc * Sc / 4;
        norm_attn<<<(unsigned)(n4 / 256), 256, 0, s2>>>(out_attn);
    }

    // 3. y1 = x + ctx@Wfc^T ; att = LN(y1) (+ fp16)
    gemm_mma<1><<<dim3(Dc/128, Mc/128), 256, GEMM_SMEM3>>>(ch, wfh, x, pY1, nullptr, Dc, Dc);
    ln_kernel<true><<<Mc, 128>>>(pY1, g1, b1, pAtt, ah);

    // 4. z = relu(att@Wff1^T) ; y2 = att + z@Wff2^T ; out = LN(y2)
    gemm_mma<2><<<dim3(FFc/128, Mc/128), 256, GEMM_SMEM3>>>(ah, w1h, nullptr, nullptr, zh, FFc, Dc);
    gemm_mma<1><<<dim3(Dc/128, Mc/128), 256, GEMM_SMEM3>>>(zh, w2h, pAtt, pY2, nullptr, Dc, FFc);
    ln_kernel<false><<<Mc, 128>>>(pY2, g2, b2, out_feed, nullptr);

    // Join: main stream waits for norm_attn
    cudaEventRecord(eJoin, s2);
    cudaStreamWaitEvent(0, eJoin, 0);
}